// round 8
// baseline (speedup 1.0000x reference)
#include <cuda_runtime.h>
#include <cuda_bf16.h>
#include <cstdint>

#define N_NODES 50000
#define N_EDGES 600000
#define IN_F    256
#define OUT_F   128

#define SCAN_CHUNK   1024
#define NUM_CHUNKS   ((N_NODES + SCAN_CHUNK - 1) / SCAN_CHUNK)   // 49

// Scratch (alloc-free rule: __device__ globals)
__device__ float g_support[(size_t)N_NODES * OUT_F];   // 25.6 MB
__device__ int   g_counts[N_NODES];
__device__ int   g_offsets[N_NODES + 1];
__device__ int   g_cursor[N_NODES];
__device__ int   g_partials[NUM_CHUNKS];
__device__ int   g_chunk_base[NUM_CHUNKS];
__device__ int   g_sorted_cols[N_EDGES];
__device__ float g_sorted_vals[N_EDGES];

// Arch-specific gate: tcgen05 only in the sm_103a pass; compute_103 family
// pass gets the FFMA fallback.
#if defined(__CUDA_ARCH__) && (__CUDA_ARCH__ == 1030) && \
    (defined(__CUDA_ARCH_FEAT_SM103_ALL) || defined(__CUDA_ARCH_SPECIFIC__))
#define GCN_HAS_TCGEN05 1
#else
#define GCN_HAS_TCGEN05 0
#endif

// ===========================================================================
// GEMM: support[50000,128] = x[50000,256] @ W[256,128]
// sm_103a: tcgen05 kind::f16 (bf16), 2-split/3-MMA emulated fp32,
//          K_CHUNK=64, 2-stage double-buffered pipeline (4 chunks).
// family:  FFMA register-tiled SGEMM.
// ===========================================================================

#define K_CHUNK     64
#define NUM_KCHUNK  (IN_F / K_CHUNK)           // 4
#define TILE_BYTES  (128 * K_CHUNK * 2)        // 16384 (bf16 tile)
#define STAGE_BYTES (4 * TILE_BYTES)           // A0,A1,B0,B1 = 64 KB

#define SM_TMEM_PTR 0
#define SM_MBAR0    8
#define SM_MBAR1    16
#define SM_STAGE0   1024
#define SM_TOTAL    (1024 + 2 * STAGE_BYTES)   // 132096

// within a stage:
#define ST_A0   0
#define ST_A1   TILE_BYTES
#define ST_B0   (2 * TILE_BYTES)
#define ST_B1   (3 * TILE_BYTES)

// idesc kind::f16 (bf16 in/f32 acc): dtype=F32(1)<<4, atype=BF16(1)<<7,
// btype=BF16(1)<<10, (N/8)<<17, (M/16)<<24 -> M=128, N=128 => 0x8200490
#define BF16_IDESC  0x8200490u

// SMEM descriptor: SW128 K-major, version=1, SBO=64 (1024B groups), LBO=1
#define DESC_BASE   0x4000404000010000ull
#define MAKE_DESC(a) (DESC_BASE | (uint64_t)(((a) >> 4) & 0x3FFF))

__device__ __forceinline__ uint32_t smem_u32(const void* p) {
    uint32_t a;
    asm("{ .reg .u64 t; cvta.to.shared.u64 t, %1; cvt.u32.u64 %0, t; }"
        : "=r"(a) : "l"(p));
    return a;
}

#if GCN_HAS_TCGEN05
__device__ __forceinline__ uint32_t elect_one() {
    uint32_t p;
    asm volatile("{ .reg .pred p; elect.sync _|p, 0xFFFFFFFF; selp.b32 %0,1,0,p; }"
                 : "=r"(p));
    return p;
}

__device__ __forceinline__ void mma_bf16_ss(uint32_t d_tmem, uint64_t a_desc,
                                            uint64_t b_desc, uint32_t idesc,
                                            uint32_t enable_d) {
    asm volatile(
        "{\n\t.reg .pred p;\n\tsetp.ne.u32 p, %4, 0;\n\t"
        "tcgen05.mma.cta_group::1.kind::f16 [%0], %1, %2, %3, {%5,%5,%5,%5}, p;\n\t}"
        :: "r"(d_tmem), "l"(a_desc), "l"(b_desc), "r"(idesc),
           "r"(enable_d), "r"(0u)
        : "memory");
}

__device__ __forceinline__ void mbar_wait(uint32_t addr, uint32_t parity) {
    uint32_t done;
    asm volatile(
        "{\n\t.reg .pred p;\n\t"
        "mbarrier.try_wait.parity.acquire.cta.shared::cta.b64 p, [%1], %2;\n\t"
        "selp.b32 %0, 1, 0, p;\n\t}"
        : "=r"(done) : "r"(addr), "r"(parity) : "memory");
    while (!done) {
        asm volatile(
            "{\n\t.reg .pred p;\n\t"
            "mbarrier.try_wait.parity.acquire.cta.shared::cta.b64 p, [%1], %2, 0x989680;\n\t"
            "selp.b32 %0, 1, 0, p;\n\t}"
            : "=r"(done) : "r"(addr), "r"(parity) : "memory");
    }
}

__device__ __forceinline__ uint32_t swz(uint32_t b) {
    return b ^ ((b >> 3) & 0x70);
}

// SW128 atom byte offset for bf16 element (row, col) in a 128 x 64 bf16 tile
// row has 64 bf16 = 128B = one SW128 atom row; 16 atom-rows of 1024B.
__device__ __forceinline__ uint32_t tile_off_bf16(int row, int col) {
    uint32_t byte = (uint32_t)((row >> 3) * 1024 + (row & 7) * 128 + col * 2);
    return swz(byte);
}

// split float into two bf16 halves: a ~= a0 + a1
__device__ __forceinline__ void bf16_split(float a, uint16_t& h0, uint16_t& h1) {
    __nv_bfloat16 b0 = __float2bfloat16_rn(a);
    float f0 = __bfloat162float(b0);
    __nv_bfloat16 b1 = __float2bfloat16_rn(a - f0);
    h0 = __bfloat16_as_ushort(b0);
    h1 = __bfloat16_as_ushort(b1);
}
#endif  // GCN_HAS_TCGEN05

__global__ __launch_bounds__(256) void gcn_gemm_tc_kernel(
    const float* __restrict__ x,
    const float* __restrict__ w)
{
    extern __shared__ char smem[];
    const int tid  = threadIdx.x;
    const int block_row = blockIdx.x * 128;

#if GCN_HAS_TCGEN05
    // ---------------- tcgen05 bf16x2 (3-MMA), 2-stage pipelined ----------------
    const uint32_t sbase = smem_u32(smem);
    const int wid  = tid >> 5;
    const int lane = tid & 31;

    if (wid == 0) {
        asm volatile("tcgen05.alloc.cta_group::1.sync.aligned.shared::cta.b32 [%0], %1;"
                     :: "r"(sbase + SM_TMEM_PTR), "r"(128u) : "memory");
        asm volatile("tcgen05.relinquish_alloc_permit.cta_group::1.sync.aligned;");
    }
    if (tid == 0) {
        asm volatile("mbarrier.init.shared.b64 [%0], %1;"
                     :: "r"(sbase + SM_MBAR0), "r"(1u) : "memory");
        asm volatile("mbarrier.init.shared.b64 [%0], %1;"
                     :: "r"(sbase + SM_MBAR1), "r"(1u) : "memory");
    }
    __syncthreads();

    uint32_t tmem;
    asm volatile("ld.shared.b32 %0, [%1];" : "=r"(tmem) : "r"(sbase + SM_TMEM_PTR));

    for (int kc = 0; kc < NUM_KCHUNK; kc++) {
        const int kb  = kc * K_CHUNK;
        const int buf = kc & 1;
        const uint32_t stage = SM_STAGE0 + buf * STAGE_BYTES;
        const uint32_t mbar  = sbase + (buf ? SM_MBAR1 : SM_MBAR0);

        // Buffer reuse: wait for chunk kc-2's MMAs (commit #((kc-2)/2) on mbar[buf]).
        if (kc >= 2)
            mbar_wait(mbar, (uint32_t)(((kc - 2) >> 1) & 1));

        // ---- A chunk: x[block_row..+128, kb..+64] -> bf16 splits A0/A1 ----
        // 128 rows x 16 float4 = 2048 float4; 8 per thread.
        #pragma unroll
        for (int p = 0; p < 8; p++) {
            const int i   = tid + p * 256;
            const int row = i >> 4;              // 0..127
            const int c4  = (i & 15) * 4;        // 0..60
            const int gr  = block_row + row;
            float4 v = make_float4(0.f, 0.f, 0.f, 0.f);
            if (gr < N_NODES)
                v = *(const float4*)(x + (size_t)gr * IN_F + kb + c4);
            uint16_t x0, x1, y0, y1, z0, z1, w0, w1;
            bf16_split(v.x, x0, x1);
            bf16_split(v.y, y0, y1);
            bf16_split(v.z, z0, z1);
            bf16_split(v.w, w0, w1);
            const uint32_t o = tile_off_bf16(row, c4);   // 8B-aligned
            *(uint2*)(smem + stage + ST_A0 + o) =
                make_uint2((uint32_t)x0 | ((uint32_t)y0 << 16),
                           (uint32_t)z0 | ((uint32_t)w0 << 16));
            *(uint2*)(smem + stage + ST_A1 + o) =
                make_uint2((uint32_t)x1 | ((uint32_t)y1 << 16),
                           (uint32_t)z1 | ((uint32_t)w1 << 16));
        }
        // ---- B chunk transposed: tile[n][k] = W[kb+k][n], bf16 splits ----
        // 64 k-rows x 32 float4 = 2048 float4; 8 per thread.
        #pragma unroll
        for (int p = 0; p < 8; p++) {
            const int i  = tid + p * 256;
            const int kl = i >> 5;               // 0..63
            const int n4 = (i & 31) * 4;         // 0..124
            const float4 v = __ldg((const float4*)(w + (size_t)(kb + kl) * OUT_F + n4));
            uint16_t h0[4], h1[4];
            bf16_split(v.x, h0[0], h1[0]);
            bf16_split(v.y, h0[1], h1[1]);
            bf16_split(v.z, h0[2], h1[2]);
            bf16_split(v.w, h0[3], h1[3]);
            #pragma unroll
            for (int q = 0; q < 4; q++) {
                const uint32_t o = tile_off_bf16(n4 + q, kl);
                *(uint16_t*)(smem + stage + ST_B0 + o) = h0[q];
                *(uint16_t*)(smem + stage + ST_B1 + o) = h1[q];
            }
        }
        asm volatile("fence.proxy.async.shared::cta;" ::: "memory");
        __syncthreads();

        // ---- issue MMAs for this chunk; commit to this buffer's mbarrier ----
        if (wid == 0 && elect_one()) {
            const uint64_t a0 = MAKE_DESC(sbase + stage + ST_A0);
            const uint64_t a1 = MAKE_DESC(sbase + stage + ST_A1);
            const uint64_t b0 = MAKE_DESC(sbase + stage + ST_B0);
            const uint64_t b1 = MAKE_DESC(sbase + stage + ST_B1);
            #pragma unroll
            for (int s = 0; s < K_CHUNK / 16; s++) {    // 4 k-steps of K=16
                const uint64_t off = (uint64_t)(s * 2); // 32B per step
                const uint32_t first = (kc == 0 && s == 0) ? 0u : 1u;
                mma_bf16_ss(tmem, a0 + off, b0 + off, BF16_IDESC, first);
                mma_bf16_ss(tmem, a0 + off, b1 + off, BF16_IDESC, 1u);
                mma_bf16_ss(tmem, a1 + off, b0 + off, BF16_IDESC, 1u);
            }
            asm volatile(
                "tcgen05.commit.cta_group::1.mbarrier::arrive::one.shared::cluster.b64 [%0];"
                :: "r"(mbar) : "memory");
        }
        // NO wait here: next iteration loads the other buffer.
    }

    // Final: last chunk = 3 commits on mbar1 (its 2nd arrival -> phase 1).
    mbar_wait(sbase + SM_MBAR1, 1u);
    asm volatile("tcgen05.fence::after_thread_sync;" ::: "memory");

    // ---- epilogue: 8 warps read D from TMEM, store to g_support ----
    {
        const int sub  = wid & 3;
        const int half = wid >> 2;
        uint32_t d[64];
        const uint32_t taddr = tmem + half * 64;
        asm volatile(
            "tcgen05.ld.sync.aligned.32x32b.x32.b32 "
            "{%0,%1,%2,%3,%4,%5,%6,%7,%8,%9,%10,%11,%12,%13,%14,%15,"
            "%16,%17,%18,%19,%20,%21,%22,%23,%24,%25,%26,%27,%28,%29,%30,%31}, [%32];"
            : "=r"(d[0]),"=r"(d[1]),"=r"(d[2]),"=r"(d[3]),"=r"(d[4]),"=r"(d[5]),"=r"(d[6]),"=r"(d[7]),
              "=r"(d[8]),"=r"(d[9]),"=r"(d[10]),"=r"(d[11]),"=r"(d[12]),"=r"(d[13]),"=r"(d[14]),"=r"(d[15]),
              "=r"(d[16]),"=r"(d[17]),"=r"(d[18]),"=r"(d[19]),"=r"(d[20]),"=r"(d[21]),"=r"(d[22]),"=r"(d[23]),
              "=r"(d[24]),"=r"(d[25]),"=r"(d[26]),"=r"(d[27]),"=r"(d[28]),"=r"(d[29]),"=r"(d[30]),"=r"(d[31])
            : "r"(taddr));
        asm volatile(
            "tcgen05.ld.sync.aligned.32x32b.x32.b32 "
            "{%0,%1,%2,%3,%4,%5,%6,%7,%8,%9,%10,%11,%12,%13,%14,%15,"
            "%16,%17,%18,%19,%20,%21,%22,%23,%24,%25,%26,%27,%28,%29,%30,%31}, [%32];"
            : "=r"(d[32]),"=r"(d[33]),"=r"(d[34]),"=r"(d[35]),"=r"(d[36]),"=r"(d[37]),"=r"(d[38]),"=r"(d[39]),
              "=r"(d[40]),"=r"(d[41]),"=r"(d[42]),"=r"(d[43]),"=r"(d[44]),"=r"(d[45]),"=r"(d[46]),"=r"(d[47]),
              "=r"(d[48]),"=r"(d[49]),"=r"(d[50]),"=r"(d[51]),"=r"(d[52]),"=r"(d[53]),"=r"(d[54]),"=r"(d[55]),
              "=r"(d[56]),"=r"(d[57]),"=r"(d[58]),"=r"(d[59]),"=r"(d[60]),"=r"(d[61]),"=r"(d[62]),"=r"(d[63])
            : "r"(taddr + 32));
        asm volatile("tcgen05.wait::ld.sync.aligned;" ::: "memory");

        const int gr = block_row + sub * 32 + lane;
        if (gr < N_NODES) {
            float* sp = g_support + (size_t)gr * OUT_F + half * 64;
            #pragma unroll
            for (int q = 0; q < 16; q++) {
                *(float4*)(sp + q * 4) = make_float4(
                    __uint_as_float(d[q * 4 + 0]), __uint_as_float(d[q * 4 + 1]),
                    __uint_as_float(d[q * 4 + 2]), __uint_as_float(d[q * 4 + 3]));
            }
        }
    }

    __syncthreads();
    if (tid == 0) {
        asm volatile("mbarrier.inval.shared.b64 [%0];" :: "r"(sbase + SM_MBAR0) : "memory");
        asm volatile("mbarrier.inval.shared.b64 [%0];" :: "r"(sbase + SM_MBAR1) : "memory");
    }
    if (wid == 0) {
        asm volatile("tcgen05.dealloc.cta_group::1.sync.aligned.b32 %0, %1;"
                     :: "r"(tmem), "r"(128u));
    }

#else
    // ---------------- FFMA fallback (family compute_103 pass) ----------------
    const int BK = 16;
    float* As = (float*)smem;                 // [BK][128]
    float* Bs = As + BK * 128;                // [BK][128]

    const int tx = tid & 15;
    const int ty = tid >> 4;
    const int a_row = tid >> 1;
    const int a_col = (tid & 1) * 8;
    const int b_row = tid >> 4;
    const int b_col = (tid & 15) * 8;

    float acc[8][8];
    #pragma unroll
    for (int i = 0; i < 8; i++)
        #pragma unroll
        for (int j = 0; j < 8; j++)
            acc[i][j] = 0.0f;

    const int g_arow = block_row + a_row;
    const bool a_valid = (g_arow < N_NODES);

    for (int kt = 0; kt < IN_F; kt += BK) {
        {
            float4 v0, v1;
            if (a_valid) {
                const float* xp = x + (size_t)g_arow * IN_F + kt + a_col;
                v0 = *(const float4*)(xp);
                v1 = *(const float4*)(xp + 4);
            } else {
                v0 = make_float4(0.f, 0.f, 0.f, 0.f);
                v1 = v0;
            }
            As[(a_col + 0) * 128 + a_row] = v0.x;
            As[(a_col + 1) * 128 + a_row] = v0.y;
            As[(a_col + 2) * 128 + a_row] = v0.z;
            As[(a_col + 3) * 128 + a_row] = v0.w;
            As[(a_col + 4) * 128 + a_row] = v1.x;
            As[(a_col + 5) * 128 + a_row] = v1.y;
            As[(a_col + 6) * 128 + a_row] = v1.z;
            As[(a_col + 7) * 128 + a_row] = v1.w;
        }
        {
            const float* wp = w + (size_t)(kt + b_row) * OUT_F + b_col;
            float4 v0 = *(const float4*)(wp);
            float4 v1 = *(const float4*)(wp + 4);
            *(float4*)(&Bs[b_row * 128 + b_col])     = v0;
            *(float4*)(&Bs[b_row * 128 + b_col + 4]) = v1;
        }
        __syncthreads();

        #pragma unroll
        for (int k = 0; k < BK; k++) {
            float a[8], b[8];
            float4 av0 = *(const float4*)(&As[k * 128 + ty * 8]);
            float4 av1 = *(const float4*)(&As[k * 128 + ty * 8 + 4]);
            float4 bv0 = *(const float4*)(&Bs[k * 128 + tx * 8]);
            float4 bv1 = *(const float4*)(&Bs[k * 128 + tx * 8 + 4]);
            a[0]=av0.x; a[1]=av0.y; a[2]=av0.z; a[3]=av0.w;
            a[4]=av1.x; a[5]=av1.y; a[6]=av1.z; a[7]=av1.w;
            b[0]=bv0.x; b[1]=bv0.y; b[2]=bv0.z; b[3]=bv0.w;
            b[4]=bv1.x; b[5]=bv1.y; b[6]=bv1.z; b[7]=bv1.w;
            #pragma unroll
            for (int i = 0; i < 8; i++)
                #pragma unroll
                for (int j = 0; j < 8; j++)
                    acc[i][j] = fmaf(a[i], b[j], acc[i][j]);
        }
        __syncthreads();
    }

    #pragma unroll
    for (int i = 0; i < 8; i++) {
        const int gr = block_row + ty * 8 + i;
        if (gr < N_NODES) {
            float* sp = g_support + (size_t)gr * OUT_F + tx * 8;
            *(float4*)(sp)     = make_float4(acc[i][0], acc[i][1], acc[i][2], acc[i][3]);
            *(float4*)(sp + 4) = make_float4(acc[i][4], acc[i][5], acc[i][6], acc[i][7]);
        }
    }
#endif
}

// ---------------------------------------------------------------------------
// CSR build
// ---------------------------------------------------------------------------
__global__ void gcn_zero_counts_kernel()
{
    int i = blockIdx.x * blockDim.x + threadIdx.x;
    if (i < N_NODES) g_counts[i] = 0;
}

__global__ void gcn_histogram_kernel(const int* __restrict__ edge_rows)
{
    int e = blockIdx.x * blockDim.x + threadIdx.x;
    if (e < N_EDGES) atomicAdd(&g_counts[edge_rows[e]], 1);
}

__global__ __launch_bounds__(1024) void gcn_scan_reduce_kernel()
{
    __shared__ int sdata[32];
    const int i = blockIdx.x * SCAN_CHUNK + threadIdx.x;
    int v = (i < N_NODES) ? g_counts[i] : 0;
    #pragma unroll
    for (int off = 16; off > 0; off >>= 1)
        v += __shfl_down_sync(0xffffffffu, v, off);
    if ((threadIdx.x & 31) == 0) sdata[threadIdx.x >> 5] = v;
    __syncthreads();
    if (threadIdx.x < 32) {
        int w = sdata[threadIdx.x];
        #pragma unroll
        for (int off = 16; off > 0; off >>= 1)
            w += __shfl_down_sync(0xffffffffu, w, off);
        if (threadIdx.x == 0) g_partials[blockIdx.x] = w;
    }
}

__global__ void gcn_scan_partials_kernel()
{
    __shared__ int s[64];
    int v = (threadIdx.x < NUM_CHUNKS) ? g_partials[threadIdx.x] : 0;
    s[threadIdx.x] = v;
    __syncthreads();
    #pragma unroll
    for (int off = 1; off < 64; off <<= 1) {
        int t = (threadIdx.x >= off) ? s[threadIdx.x - off] : 0;
        __syncthreads();
        s[threadIdx.x] += t;
        __syncthreads();
    }
    if (threadIdx.x < NUM_CHUNKS) g_chunk_base[threadIdx.x] = s[threadIdx.x] - v;
    if (threadIdx.x == 63) g_offsets[N_NODES] = s[63];
}

__global__ __launch_bounds__(1024) void gcn_scan_final_kernel()
{
    __shared__ int warp_sums[32];
    const int i = blockIdx.x * SCAN_CHUNK + threadIdx.x;
    const int lane = threadIdx.x & 31;
    const int warp = threadIdx.x >> 5;

    int v = (i < N_NODES) ? g_counts[i] : 0;
    int incl = v;
    #pragma unroll
    for (int off = 1; off < 32; off <<= 1) {
        int t = __shfl_up_sync(0xffffffffu, incl, off);
        if (lane >= off) incl += t;
    }
    if (lane == 31) warp_sums[warp] = incl;
    __syncthreads();
    if (warp == 0) {
        int w = warp_sums[lane];
        int wi = w;
        #pragma unroll
        for (int off = 1; off < 32; off <<= 1) {
            int t = __shfl_up_sync(0xffffffffu, wi, off);
            if (lane >= off) wi += t;
        }
        warp_sums[lane] = wi - w;
    }
    __syncthreads();

    if (i < N_NODES) {
        int o = g_chunk_base[blockIdx.x] + warp_sums[warp] + (incl - v);
        g_offsets[i] = o;
        g_cursor[i]  = o;
    }
}

__global__ void gcn_permute_kernel(const int*   __restrict__ edge_rows,
                                   const int*   __restrict__ edge_cols,
                                   const float* __restrict__ edge_vals)
{
    int e = blockIdx.x * blockDim.x + threadIdx.x;
    if (e < N_EDGES) {
        int r = edge_rows[e];
        int pos = atomicAdd(&g_cursor[r], 1);
        g_sorted_cols[pos] = edge_cols[e];
        g_sorted_vals[pos] = edge_vals[e];
    }
}

// ---------------------------------------------------------------------------
// Aggregate: one warp per node. Lane l owns features [4l, 4l+4).
// ---------------------------------------------------------------------------
__global__ __launch_bounds__(256) void gcn_aggregate_kernel(
    float* __restrict__ out,
    const float* __restrict__ bias)
{
    const int warp_id = (blockIdx.x * blockDim.x + threadIdx.x) >> 5;
    const int lane    = threadIdx.x & 31;
    if (warp_id >= N_NODES) return;

    const int start = g_offsets[warp_id];
    const int end   = g_offsets[warp_id + 1];

    float4 acc = make_float4(0.f, 0.f, 0.f, 0.f);

    for (int base = start; base < end; base += 32) {
        const int n = min(32, end - base);
        int   c = 0;
        float v = 0.f;
        if (lane < n) {
            c = __ldg(g_sorted_cols + base + lane);
            v = __ldg(g_sorted_vals + base + lane);
        }
        for (int j = 0; j < n; j++) {
            const int   cj = __shfl_sync(0xffffffffu, c, j);
            const float vj = __shfl_sync(0xffffffffu, v, j);
            const float4 m = __ldg(((const float4*)g_support) + (size_t)cj * 32 + lane);
            acc.x = fmaf(vj, m.x, acc.x);
            acc.y = fmaf(vj, m.y, acc.y);
            acc.z = fmaf(vj, m.z, acc.z);
            acc.w = fmaf(vj, m.w, acc.w);
        }
    }

    const float4 b = __ldg(((const float4*)bias) + lane);
    acc.x += b.x; acc.y += b.y; acc.z += b.z; acc.w += b.w;
    ((float4*)out)[(size_t)warp_id * 32 + lane] = acc;
}

// ---------------------------------------------------------------------------
// kernel_launch
// Inputs (metadata order): x, edge_rows, edge_cols, edge_vals, weight, bias
// ---------------------------------------------------------------------------
extern "C" void kernel_launch(void* const* d_in, const int* in_sizes, int n_in,
                              void* d_out, int out_size)
{
    const float* x         = (const float*)d_in[0];
    const int*   edge_rows = (const int*)  d_in[1];
    const int*   edge_cols = (const int*)  d_in[2];
    const float* edge_vals = (const float*)d_in[3];
    const float* weight    = (const float*)d_in[4];
    const float* bias      = (const float*)d_in[5];
    float*       out       = (float*)d_out;

    // 1) support = x @ W  (tcgen05 bf16x2/3-MMA pipelined; FFMA fallback)
    static bool attr_set = false;
    if (!attr_set) {
        cudaFuncSetAttribute(gcn_gemm_tc_kernel,
                             cudaFuncAttributeMaxDynamicSharedMemorySize, SM_TOTAL);
        attr_set = true;
    }
    gcn_gemm_tc_kernel<<<(N_NODES + 127) / 128, 256, SM_TOTAL>>>(x, weight);

    // 2) CSR build
    gcn_zero_counts_kernel<<<(N_NODES + 255) / 256, 256>>>();
    gcn_histogram_kernel<<<(N_EDGES + 255) / 256, 256>>>(edge_rows);
    gcn_scan_reduce_kernel<<<NUM_CHUNKS, 1024>>>();
    gcn_scan_partials_kernel<<<1, 64>>>();
    gcn_scan_final_kernel<<<NUM_CHUNKS, 1024>>>();
    gcn_permute_kernel<<<(N_EDGES + 255) / 256, 256>>>(edge_rows, edge_cols, edge_vals);

    // 3) aggregate + bias
    {
        const int warps_per_block = 256 / 32;
        const int blocks = (N_NODES + warps_per_block - 1) / warps_per_block;
        gcn_aggregate_kernel<<<blocks, 256>>>(out, bias);
    }
}

// round 9
// speedup vs baseline: 1.3791x; 1.3791x over previous
#include <cuda_runtime.h>
#include <cstdint>

#define N_NODES 50000
#define N_EDGES 600000
#define IN_F    256
#define OUT_F   128

#define SCAN_CHUNK   1024
#define NUM_CHUNKS   ((N_NODES + SCAN_CHUNK - 1) / SCAN_CHUNK)   // 49

// Scratch (alloc-free rule: __device__ globals)
__device__ float g_support[(size_t)N_NODES * OUT_F];   // 25.6 MB
__device__ int   g_counts[N_NODES];
__device__ int   g_offsets[N_NODES + 1];
__device__ int   g_cursor[N_NODES];
__device__ int   g_partials[NUM_CHUNKS];
__device__ int   g_chunk_base[NUM_CHUNKS];
__device__ int2  g_sorted[N_EDGES];                    // {col, val_bits}

// Arch-specific gate: tcgen05 only in the sm_103a pass; compute_103 family
// pass gets the FFMA fallback.
#if defined(__CUDA_ARCH__) && (__CUDA_ARCH__ == 1030) && \
    (defined(__CUDA_ARCH_FEAT_SM103_ALL) || defined(__CUDA_ARCH_SPECIFIC__))
#define GCN_HAS_TCGEN05 1
#else
#define GCN_HAS_TCGEN05 0
#endif

// ===========================================================================
// GEMM (ROUND-6 PROVEN): support = x @ W, tcgen05 kind::tf32, 3xTF32,
// K_CHUNK=64, single-buffered. Do not churn — load-phase bound.
// ===========================================================================

#define K_CHUNK     64
#define NUM_KCHUNK  (IN_F / K_CHUNK)       // 4
#define TILE_BYTES  (128 * K_CHUNK * 4)    // 32768 per tile version

#define SM_TMEM_PTR 0
#define SM_MBAR     8
#define SM_A_BIG    1024
#define SM_A_SMALL  (SM_A_BIG   + TILE_BYTES)
#define SM_B_BIG    (SM_A_SMALL + TILE_BYTES)
#define SM_B_SMALL  (SM_B_BIG   + TILE_BYTES)
#define SM_TOTAL    (SM_B_SMALL + TILE_BYTES)   // 132096

#define TF32_IDESC  0x8200910u

#define DESC_BASE   0x4000404000010000ull
#define MAKE_DESC(a) (DESC_BASE | (uint64_t)(((a) >> 4) & 0x3FFF))

__device__ __forceinline__ uint32_t smem_u32(const void* p) {
    uint32_t a;
    asm("{ .reg .u64 t; cvta.to.shared.u64 t, %1; cvt.u32.u64 %0, t; }"
        : "=r"(a) : "l"(p));
    return a;
}

#if GCN_HAS_TCGEN05
__device__ __forceinline__ uint32_t tf32_rna(float a) {
    uint32_t r;
    asm("cvt.rna.tf32.f32 %0, %1;" : "=r"(r) : "f"(a));
    return r;
}

__device__ __forceinline__ uint32_t elect_one() {
    uint32_t p;
    asm volatile("{ .reg .pred p; elect.sync _|p, 0xFFFFFFFF; selp.b32 %0,1,0,p; }"
                 : "=r"(p));
    return p;
}

__device__ __forceinline__ void mma_tf32_ss(uint32_t d_tmem, uint64_t a_desc,
                                            uint64_t b_desc, uint32_t idesc,
                                            uint32_t enable_d) {
    asm volatile(
        "{\n\t.reg .pred p;\n\tsetp.ne.u32 p, %4, 0;\n\t"
        "tcgen05.mma.cta_group::1.kind::tf32 [%0], %1, %2, %3, {%5,%5,%5,%5}, p;\n\t}"
        :: "r"(d_tmem), "l"(a_desc), "l"(b_desc), "r"(idesc),
           "r"(enable_d), "r"(0u)
        : "memory");
}

__device__ __forceinline__ void mbar_wait(uint32_t addr, uint32_t parity) {
    uint32_t done;
    asm volatile(
        "{\n\t.reg .pred p;\n\t"
        "mbarrier.try_wait.parity.acquire.cta.shared::cta.b64 p, [%1], %2;\n\t"
        "selp.b32 %0, 1, 0, p;\n\t}"
        : "=r"(done) : "r"(addr), "r"(parity) : "memory");
    while (!done) {
        asm volatile(
            "{\n\t.reg .pred p;\n\t"
            "mbarrier.try_wait.parity.acquire.cta.shared::cta.b64 p, [%1], %2, 0x989680;\n\t"
            "selp.b32 %0, 1, 0, p;\n\t}"
            : "=r"(done) : "r"(addr), "r"(parity) : "memory");
    }
}

__device__ __forceinline__ uint32_t swz(uint32_t b) {
    return b ^ ((b >> 3) & 0x70);
}

// SW128 atom byte offset for (row, col) in a 128 x 64 f32 tile
__device__ __forceinline__ uint32_t tile_off(int row, int col) {
    uint32_t byte = (uint32_t)(((row >> 3) + (col >> 5) * 16) * 1024
                               + (row & 7) * 128 + (col & 31) * 4);
    return swz(byte);
}
#endif  // GCN_HAS_TCGEN05

__global__ __launch_bounds__(256) void gcn_gemm_tc_kernel(
    const float* __restrict__ x,
    const float* __restrict__ w)
{
    extern __shared__ char smem[];
    const int tid  = threadIdx.x;
    const int block_row = blockIdx.x * 128;

#if GCN_HAS_TCGEN05
    const uint32_t sbase = smem_u32(smem);
    const int wid  = tid >> 5;
    const int lane = tid & 31;

    if (wid == 0) {
        asm volatile("tcgen05.alloc.cta_group::1.sync.aligned.shared::cta.b32 [%0], %1;"
                     :: "r"(sbase + SM_TMEM_PTR), "r"(128u) : "memory");
        asm volatile("tcgen05.relinquish_alloc_permit.cta_group::1.sync.aligned;");
    }
    if (tid == 0) {
        asm volatile("mbarrier.init.shared.b64 [%0], %1;"
                     :: "r"(sbase + SM_MBAR), "r"(1u) : "memory");
    }
    __syncthreads();

    uint32_t tmem;
    asm volatile("ld.shared.b32 %0, [%1];" : "=r"(tmem) : "r"(sbase + SM_TMEM_PTR));

    for (int kc = 0; kc < NUM_KCHUNK; kc++) {
        const int kb = kc * K_CHUNK;

        for (int i = tid; i < 128 * (K_CHUNK / 4); i += 256) {
            const int row = i >> 4;
            const int c4  = (i & 15) * 4;
            const int gr  = block_row + row;
            float4 v = make_float4(0.f, 0.f, 0.f, 0.f);
            if (gr < N_NODES)
                v = *(const float4*)(x + (size_t)gr * IN_F + kb + c4);
            uint32_t bx = tf32_rna(v.x), by = tf32_rna(v.y),
                     bz = tf32_rna(v.z), bw = tf32_rna(v.w);
            float sx = v.x - __uint_as_float(bx);
            float sy = v.y - __uint_as_float(by);
            float sz = v.z - __uint_as_float(bz);
            float sw = v.w - __uint_as_float(bw);
            const uint32_t o = tile_off(row, c4);
            *(uint4*)(smem + SM_A_BIG + o)    = make_uint4(bx, by, bz, bw);
            *(float4*)(smem + SM_A_SMALL + o) = make_float4(sx, sy, sz, sw);
        }
        for (int i = tid; i < K_CHUNK * OUT_F; i += 256) {
            const int kl = i >> 7;
            const int n  = i & 127;
            const float v = __ldg(w + (size_t)(kb + kl) * OUT_F + n);
            const uint32_t b = tf32_rna(v);
            const float s = v - __uint_as_float(b);
            const uint32_t o = tile_off(n, kl);
            *(uint32_t*)(smem + SM_B_BIG + o) = b;
            *(float*)(smem + SM_B_SMALL + o)  = s;
        }
        asm volatile("fence.proxy.async.shared::cta;" ::: "memory");
        __syncthreads();

        if (wid == 0 && elect_one()) {
            const uint64_t ab = MAKE_DESC(sbase + SM_A_BIG);
            const uint64_t as = MAKE_DESC(sbase + SM_A_SMALL);
            const uint64_t bb = MAKE_DESC(sbase + SM_B_BIG);
            const uint64_t bs = MAKE_DESC(sbase + SM_B_SMALL);
            #pragma unroll
            for (int s = 0; s < K_CHUNK / 8; s++) {
                const uint64_t off = (uint64_t)((s >> 2) * 1024 + (s & 3) * 2);
                const uint32_t first = (kc == 0 && s == 0) ? 0u : 1u;
                mma_tf32_ss(tmem, ab + off, bb + off, TF32_IDESC, first);
                mma_tf32_ss(tmem, as + off, bb + off, TF32_IDESC, 1u);
                mma_tf32_ss(tmem, ab + off, bs + off, TF32_IDESC, 1u);
            }
            asm volatile(
                "tcgen05.commit.cta_group::1.mbarrier::arrive::one.shared::cluster.b64 [%0];"
                :: "r"(sbase + SM_MBAR) : "memory");
        }

        mbar_wait(sbase + SM_MBAR, (uint32_t)(kc & 1));
    }

    asm volatile("tcgen05.fence::after_thread_sync;" ::: "memory");

    // epilogue: 8 warps read D from TMEM, store to g_support
    {
        const int sub  = wid & 3;
        const int half = wid >> 2;
        uint32_t d[64];
        const uint32_t taddr = tmem + half * 64;
        asm volatile(
            "tcgen05.ld.sync.aligned.32x32b.x32.b32 "
            "{%0,%1,%2,%3,%4,%5,%6,%7,%8,%9,%10,%11,%12,%13,%14,%15,"
            "%16,%17,%18,%19,%20,%21,%22,%23,%24,%25,%26,%27,%28,%29,%30,%31}, [%32];"
            : "=r"(d[0]),"=r"(d[1]),"=r"(d[2]),"=r"(d[3]),"=r"(d[4]),"=r"(d[5]),"=r"(d[6]),"=r"(d[7]),
              "=r"(d[8]),"=r"(d[9]),"=r"(d[10]),"=r"(d[11]),"=r"(d[12]),"=r"(d[13]),"=r"(d[14]),"=r"(d[15]),
              "=r"(d[16]),"=r"(d[17]),"=r"(d[18]),"=r"(d[19]),"=r"(d[20]),"=r"(d[21]),"=r"(d[22]),"=r"(d[23]),
              "=r"(d[24]),"=r"(d[25]),"=r"(d[26]),"=r"(d[27]),"=r"(d[28]),"=r"(d[29]),"=r"(d[30]),"=r"(d[31])
            : "r"(taddr));
        asm volatile(
            "tcgen05.ld.sync.aligned.32x32b.x32.b32 "
            "{%0,%1,%2,%3,%4,%5,%6,%7,%8,%9,%10,%11,%12,%13,%14,%15,"
            "%16,%17,%18,%19,%20,%21,%22,%23,%24,%25,%26,%27,%28,%29,%30,%31}, [%32];"
            : "=r"(d[32]),"=r"(d[33]),"=r"(d[34]),"=r"(d[35]),"=r"(d[36]),"=r"(d[37]),"=r"(d[38]),"=r"(d[39]),
              "=r"(d[40]),"=r"(d[41]),"=r"(d[42]),"=r"(d[43]),"=r"(d[44]),"=r"(d[45]),"=r"(d[46]),"=r"(d[47]),
              "=r"(d[48]),"=r"(d[49]),"=r"(d[50]),"=r"(d[51]),"=r"(d[52]),"=r"(d[53]),"=r"(d[54]),"=r"(d[55]),
              "=r"(d[56]),"=r"(d[57]),"=r"(d[58]),"=r"(d[59]),"=r"(d[60]),"=r"(d[61]),"=r"(d[62]),"=r"(d[63])
            : "r"(taddr + 32));
        asm volatile("tcgen05.wait::ld.sync.aligned;" ::: "memory");

        const int gr = block_row + sub * 32 + lane;
        if (gr < N_NODES) {
            float* sp = g_support + (size_t)gr * OUT_F + half * 64;
            #pragma unroll
            for (int q = 0; q < 16; q++) {
                *(float4*)(sp + q * 4) = make_float4(
                    __uint_as_float(d[q * 4 + 0]), __uint_as_float(d[q * 4 + 1]),
                    __uint_as_float(d[q * 4 + 2]), __uint_as_float(d[q * 4 + 3]));
            }
        }
    }

    __syncthreads();
    if (tid == 0) {
        asm volatile("mbarrier.inval.shared.b64 [%0];" :: "r"(sbase + SM_MBAR) : "memory");
    }
    if (wid == 0) {
        asm volatile("tcgen05.dealloc.cta_group::1.sync.aligned.b32 %0, %1;"
                     :: "r"(tmem), "r"(128u));
    }

#else
    // ---------------- FFMA fallback (family compute_103 pass) ----------------
    const int BK = 16;
    float* As = (float*)smem;
    float* Bs = As + BK * 128;

    const int tx = tid & 15;
    const int ty = tid >> 4;
    const int a_row = tid >> 1;
    const int a_col = (tid & 1) * 8;
    const int b_row = tid >> 4;
    const int b_col = (tid & 15) * 8;

    float acc[8][8];
    #pragma unroll
    for (int i = 0; i < 8; i++)
        #pragma unroll
        for (int j = 0; j < 8; j++)
            acc[i][j] = 0.0f;

    const int g_arow = block_row + a_row;
    const bool a_valid = (g_arow < N_NODES);

    for (int kt = 0; kt < IN_F; kt += BK) {
        {
            float4 v0, v1;
            if (a_valid) {
                const float* xp = x + (size_t)g_arow * IN_F + kt + a_col;
                v0 = *(const float4*)(xp);
                v1 = *(const float4*)(xp + 4);
            } else {
                v0 = make_float4(0.f, 0.f, 0.f, 0.f);
                v1 = v0;
            }
            As[(a_col + 0) * 128 + a_row] = v0.x;
            As[(a_col + 1) * 128 + a_row] = v0.y;
            As[(a_col + 2) * 128 + a_row] = v0.z;
            As[(a_col + 3) * 128 + a_row] = v0.w;
            As[(a_col + 4) * 128 + a_row] = v1.x;
            As[(a_col + 5) * 128 + a_row] = v1.y;
            As[(a_col + 6) * 128 + a_row] = v1.z;
            As[(a_col + 7) * 128 + a_row] = v1.w;
        }
        {
            const float* wp = w + (size_t)(kt + b_row) * OUT_F + b_col;
            float4 v0 = *(const float4*)(wp);
            float4 v1 = *(const float4*)(wp + 4);
            *(float4*)(&Bs[b_row * 128 + b_col])     = v0;
            *(float4*)(&Bs[b_row * 128 + b_col + 4]) = v1;
        }
        __syncthreads();

        #pragma unroll
        for (int k = 0; k < BK; k++) {
            float a[8], b[8];
            float4 av0 = *(const float4*)(&As[k * 128 + ty * 8]);
            float4 av1 = *(const float4*)(&As[k * 128 + ty * 8 + 4]);
            float4 bv0 = *(const float4*)(&Bs[k * 128 + tx * 8]);
            float4 bv1 = *(const float4*)(&Bs[k * 128 + tx * 8 + 4]);
            a[0]=av0.x; a[1]=av0.y; a[2]=av0.z; a[3]=av0.w;
            a[4]=av1.x; a[5]=av1.y; a[6]=av1.z; a[7]=av1.w;
            b[0]=bv0.x; b[1]=bv0.y; b[2]=bv0.z; b[3]=bv0.w;
            b[4]=bv1.x; b[5]=bv1.y; b[6]=bv1.z; b[7]=bv1.w;
            #pragma unroll
            for (int i = 0; i < 8; i++)
                #pragma unroll
                for (int j = 0; j < 8; j++)
                    acc[i][j] = fmaf(a[i], b[j], acc[i][j]);
        }
        __syncthreads();
    }

    #pragma unroll
    for (int i = 0; i < 8; i++) {
        const int gr = block_row + ty * 8 + i;
        if (gr < N_NODES) {
            float* sp = g_support + (size_t)gr * OUT_F + tx * 8;
            *(float4*)(sp)     = make_float4(acc[i][0], acc[i][1], acc[i][2], acc[i][3]);
            *(float4*)(sp + 4) = make_float4(acc[i][4], acc[i][5], acc[i][6], acc[i][7]);
        }
    }
#endif
}

// ---------------------------------------------------------------------------
// CSR build
// ---------------------------------------------------------------------------
__global__ void gcn_zero_counts_kernel()
{
    int i = blockIdx.x * blockDim.x + threadIdx.x;
    if (i < N_NODES) g_counts[i] = 0;
}

__global__ void gcn_histogram_kernel(const int* __restrict__ edge_rows)
{
    int e = blockIdx.x * blockDim.x + threadIdx.x;
    if (e < N_EDGES) atomicAdd(&g_counts[edge_rows[e]], 1);
}

__global__ __launch_bounds__(1024) void gcn_scan_reduce_kernel()
{
    __shared__ int sdata[32];
    const int i = blockIdx.x * SCAN_CHUNK + threadIdx.x;
    int v = (i < N_NODES) ? g_counts[i] : 0;
    #pragma unroll
    for (int off = 16; off > 0; off >>= 1)
        v += __shfl_down_sync(0xffffffffu, v, off);
    if ((threadIdx.x & 31) == 0) sdata[threadIdx.x >> 5] = v;
    __syncthreads();
    if (threadIdx.x < 32) {
        int w = sdata[threadIdx.x];
        #pragma unroll
        for (int off = 16; off > 0; off >>= 1)
            w += __shfl_down_sync(0xffffffffu, w, off);
        if (threadIdx.x == 0) g_partials[blockIdx.x] = w;
    }
}

__global__ void gcn_scan_partials_kernel()
{
    __shared__ int s[64];
    int v = (threadIdx.x < NUM_CHUNKS) ? g_partials[threadIdx.x] : 0;
    s[threadIdx.x] = v;
    __syncthreads();
    #pragma unroll
    for (int off = 1; off < 64; off <<= 1) {
        int t = (threadIdx.x >= off) ? s[threadIdx.x - off] : 0;
        __syncthreads();
        s[threadIdx.x] += t;
        __syncthreads();
    }
    if (threadIdx.x < NUM_CHUNKS) g_chunk_base[threadIdx.x] = s[threadIdx.x] - v;
    if (threadIdx.x == 63) g_offsets[N_NODES] = s[63];
}

__global__ __launch_bounds__(1024) void gcn_scan_final_kernel()
{
    __shared__ int warp_sums[32];
    const int i = blockIdx.x * SCAN_CHUNK + threadIdx.x;
    const int lane = threadIdx.x & 31;
    const int warp = threadIdx.x >> 5;

    int v = (i < N_NODES) ? g_counts[i] : 0;
    int incl = v;
    #pragma unroll
    for (int off = 1; off < 32; off <<= 1) {
        int t = __shfl_up_sync(0xffffffffu, incl, off);
        if (lane >= off) incl += t;
    }
    if (lane == 31) warp_sums[warp] = incl;
    __syncthreads();
    if (warp == 0) {
        int w = warp_sums[lane];
        int wi = w;
        #pragma unroll
        for (int off = 1; off < 32; off <<= 1) {
            int t = __shfl_up_sync(0xffffffffu, wi, off);
            if (lane >= off) wi += t;
        }
        warp_sums[lane] = wi - w;
    }
    __syncthreads();

    if (i < N_NODES) {
        int o = g_chunk_base[blockIdx.x] + warp_sums[warp] + (incl - v);
        g_offsets[i] = o;
        g_cursor[i]  = o;
    }
}

__global__ void gcn_permute_kernel(const int*   __restrict__ edge_rows,
                                   const int*   __restrict__ edge_cols,
                                   const float* __restrict__ edge_vals)
{
    int e = blockIdx.x * blockDim.x + threadIdx.x;
    if (e < N_EDGES) {
        int r = edge_rows[e];
        int pos = atomicAdd(&g_cursor[r], 1);
        g_sorted[pos] = make_int2(edge_cols[e], __float_as_int(edge_vals[e]));
    }
}

// ---------------------------------------------------------------------------
// Aggregate: one warp per node, 4-way unrolled gathers for MLP.
// Lane l owns features [4l, 4l+4).
// ---------------------------------------------------------------------------
__global__ __launch_bounds__(256) void gcn_aggregate_kernel(
    float* __restrict__ out,
    const float* __restrict__ bias)
{
    const int warp_id = (blockIdx.x * blockDim.x + threadIdx.x) >> 5;
    const int lane    = threadIdx.x & 31;
    if (warp_id >= N_NODES) return;

    const int start = g_offsets[warp_id];
    const int end   = g_offsets[warp_id + 1];

    float4 acc = make_float4(0.f, 0.f, 0.f, 0.f);
    const float4* sup = (const float4*)g_support;

    for (int base = start; base < end; base += 32) {
        const int n = min(32, end - base);
        int2 ev = make_int2(0, 0);
        if (lane < n)
            ev = __ldg(&g_sorted[base + lane]);
        const int   c = ev.x;
        const float v = __int_as_float(ev.y);

        int j = 0;
        for (; j + 4 <= n; j += 4) {
            const int   c0 = __shfl_sync(0xffffffffu, c, j + 0);
            const int   c1 = __shfl_sync(0xffffffffu, c, j + 1);
            const int   c2 = __shfl_sync(0xffffffffu, c, j + 2);
            const int   c3 = __shfl_sync(0xffffffffu, c, j + 3);
            const float v0 = __shfl_sync(0xffffffffu, v, j + 0);
            const float v1 = __shfl_sync(0xffffffffu, v, j + 1);
            const float v2 = __shfl_sync(0xffffffffu, v, j + 2);
            const float v3 = __shfl_sync(0xffffffffu, v, j + 3);
            // 4 independent gathers in flight
            const float4 m0 = __ldg(sup + (size_t)c0 * 32 + lane);
            const float4 m1 = __ldg(sup + (size_t)c1 * 32 + lane);
            const float4 m2 = __ldg(sup + (size_t)c2 * 32 + lane);
            const float4 m3 = __ldg(sup + (size_t)c3 * 32 + lane);
            acc.x = fmaf(v0, m0.x, acc.x); acc.y = fmaf(v0, m0.y, acc.y);
            acc.z = fmaf(v0, m0.z, acc.z); acc.w = fmaf(v0, m0.w, acc.w);
            acc.x = fmaf(v1, m1.x, acc.x); acc.y = fmaf(v1, m1.y, acc.y);
            acc.z = fmaf(v1, m1.z, acc.z); acc.w = fmaf(v1, m1.w, acc.w);
            acc.x = fmaf(v2, m2.x, acc.x); acc.y = fmaf(v2, m2.y, acc.y);
            acc.z = fmaf(v2, m2.z, acc.z); acc.w = fmaf(v2, m2.w, acc.w);
            acc.x = fmaf(v3, m3.x, acc.x); acc.y = fmaf(v3, m3.y, acc.y);
            acc.z = fmaf(v3, m3.z, acc.z); acc.w = fmaf(v3, m3.w, acc.w);
        }
        for (; j < n; j++) {
            const int   cj = __shfl_sync(0xffffffffu, c, j);
            const float vj = __shfl_sync(0xffffffffu, v, j);
            const float4 m = __ldg(sup + (size_t)cj * 32 + lane);
            acc.x = fmaf(vj, m.x, acc.x);
            acc.y = fmaf(vj, m.y, acc.y);
            acc.z = fmaf(vj, m.z, acc.z);
            acc.w = fmaf(vj, m.w, acc.w);
        }
    }

    const float4 b = __ldg(((const float4*)bias) + lane);
    acc.x += b.x; acc.y += b.y; acc.z += b.z; acc.w += b.w;
    ((float4*)out)[(size_t)warp_id * 32 + lane] = acc;
}

// ---------------------------------------------------------------------------
// kernel_launch
// Inputs (metadata order): x, edge_rows, edge_cols, edge_vals, weight, bias
// ---------------------------------------------------------------------------
extern "C" void kernel_launch(void* const* d_in, const int* in_sizes, int n_in,
                              void* d_out, int out_size)
{
    const float* x         = (const float*)d_in[0];
    const int*   edge_rows = (const int*)  d_in[1];
    const int*   edge_cols = (const int*)  d_in[2];
    const float* edge_vals = (const float*)d_in[3];
    const float* weight    = (const float*)d_in[4];
    const float* bias      = (const float*)d_in[5];
    float*       out       = (float*)d_out;

    // 1) support = x @ W  (tcgen05 TF32x3, round-6 proven)
    static bool attr_set = false;
    if (!attr_set) {
        cudaFuncSetAttribute(gcn_gemm_tc_kernel,
                             cudaFuncAttributeMaxDynamicSharedMemorySize, SM_TOTAL);
        attr_set = true;
    }
    gcn_gemm_tc_kernel<<<(N_NODES + 127) / 128, 256, SM_TOTAL>>>(x, weight);

    // 2) CSR build
    gcn_zero_counts_kernel<<<(N_NODES + 255) / 256, 256>>>();
    gcn_histogram_kernel<<<(N_EDGES + 255) / 256, 256>>>(edge_rows);
    gcn_scan_reduce_kernel<<<NUM_CHUNKS, 1024>>>();
    gcn_scan_partials_kernel<<<1, 64>>>();
    gcn_scan_final_kernel<<<NUM_CHUNKS, 1024>>>();
    gcn_permute_kernel<<<(N_EDGES + 255) / 256, 256>>>(edge_rows, edge_cols, edge_vals);

    // 3) aggregate + bias
    {
        const int warps_per_block = 256 / 32;
        const int blocks = (N_NODES + warps_per_block - 1) / warps_per_block;
        gcn_aggregate_kernel<<<blocks, 256>>>(out, bias);
    }
}

// round 10
// speedup vs baseline: 1.3820x; 1.0021x over previous
#include <cuda_runtime.h>
#include <cstdint>

#define N_NODES 50000
#define N_EDGES 600000
#define IN_F    256
#define OUT_F   128

#define SCAN_CHUNK   1024
#define NUM_CHUNKS   ((N_NODES + SCAN_CHUNK - 1) / SCAN_CHUNK)   // 49

// Scratch (alloc-free rule: __device__ globals)
__device__ float g_support[(size_t)N_NODES * OUT_F];   // 25.6 MB
__device__ int   g_counts[N_NODES];
__device__ int   g_offsets[N_NODES + 1];
__device__ int   g_cursor[N_NODES];
__device__ int   g_partials[NUM_CHUNKS];
__device__ int   g_chunk_base[NUM_CHUNKS];
__device__ int2  g_sorted[N_EDGES];                    // {col, val_bits}

#if defined(__CUDA_ARCH__) && (__CUDA_ARCH__ == 1030) && \
    (defined(__CUDA_ARCH_FEAT_SM103_ALL) || defined(__CUDA_ARCH_SPECIFIC__))
#define GCN_HAS_TCGEN05 1
#else
#define GCN_HAS_TCGEN05 0
#endif

// ===========================================================================
// GEMM: support = x @ W, tcgen05 kind::tf32, 3xTF32, K_CHUNK=64.
// R10: register-prefetch pipeline + conflict-free transposed B stores.
// ===========================================================================

#define K_CHUNK     64
#define NUM_KCHUNK  (IN_F / K_CHUNK)       // 4
#define TILE_BYTES  (128 * K_CHUNK * 4)    // 32768 per tile version

#define SM_TMEM_PTR 0
#define SM_MBAR     8
#define SM_A_BIG    1024
#define SM_A_SMALL  (SM_A_BIG   + TILE_BYTES)
#define SM_B_BIG    (SM_A_SMALL + TILE_BYTES)
#define SM_B_SMALL  (SM_B_BIG   + TILE_BYTES)
#define SM_TOTAL    (SM_B_SMALL + TILE_BYTES)   // 132096

#define TF32_IDESC  0x8200910u

#define DESC_BASE   0x4000404000010000ull
#define MAKE_DESC(a) (DESC_BASE | (uint64_t)(((a) >> 4) & 0x3FFF))

__device__ __forceinline__ uint32_t smem_u32(const void* p) {
    uint32_t a;
    asm("{ .reg .u64 t; cvta.to.shared.u64 t, %1; cvt.u32.u64 %0, t; }"
        : "=r"(a) : "l"(p));
    return a;
}

#if GCN_HAS_TCGEN05
__device__ __forceinline__ uint32_t tf32_rna(float a) {
    uint32_t r;
    asm("cvt.rna.tf32.f32 %0, %1;" : "=r"(r) : "f"(a));
    return r;
}

__device__ __forceinline__ uint32_t elect_one() {
    uint32_t p;
    asm volatile("{ .reg .pred p; elect.sync _|p, 0xFFFFFFFF; selp.b32 %0,1,0,p; }"
                 : "=r"(p));
    return p;
}

__device__ __forceinline__ void mma_tf32_ss(uint32_t d_tmem, uint64_t a_desc,
                                            uint64_t b_desc, uint32_t idesc,
                                            uint32_t enable_d) {
    asm volatile(
        "{\n\t.reg .pred p;\n\tsetp.ne.u32 p, %4, 0;\n\t"
        "tcgen05.mma.cta_group::1.kind::tf32 [%0], %1, %2, %3, {%5,%5,%5,%5}, p;\n\t}"
        :: "r"(d_tmem), "l"(a_desc), "l"(b_desc), "r"(idesc),
           "r"(enable_d), "r"(0u)
        : "memory");
}

__device__ __forceinline__ void mbar_wait(uint32_t addr, uint32_t parity) {
    uint32_t done;
    asm volatile(
        "{\n\t.reg .pred p;\n\t"
        "mbarrier.try_wait.parity.acquire.cta.shared::cta.b64 p, [%1], %2;\n\t"
        "selp.b32 %0, 1, 0, p;\n\t}"
        : "=r"(done) : "r"(addr), "r"(parity) : "memory");
    while (!done) {
        asm volatile(
            "{\n\t.reg .pred p;\n\t"
            "mbarrier.try_wait.parity.acquire.cta.shared::cta.b64 p, [%1], %2, 0x989680;\n\t"
            "selp.b32 %0, 1, 0, p;\n\t}"
            : "=r"(done) : "r"(addr), "r"(parity) : "memory");
    }
}

__device__ __forceinline__ uint32_t swz(uint32_t b) {
    return b ^ ((b >> 3) & 0x70);
}

// SW128 atom byte offset for (row, col) in a 128 x 64 f32 tile
__device__ __forceinline__ uint32_t tile_off(int row, int col) {
    uint32_t byte = (uint32_t)(((row >> 3) + (col >> 5) * 16) * 1024
                               + (row & 7) * 128 + (col & 31) * 4);
    return swz(byte);
}
#endif  // GCN_HAS_TCGEN05

__global__ __launch_bounds__(256) void gcn_gemm_tc_kernel(
    const float* __restrict__ x,
    const float* __restrict__ w)
{
    extern __shared__ char smem[];
    const int tid  = threadIdx.x;
    const int block_row = blockIdx.x * 128;

#if GCN_HAS_TCGEN05
    const uint32_t sbase = smem_u32(smem);
    const int wid  = tid >> 5;
    const int lane = tid & 31;

    if (wid == 0) {
        asm volatile("tcgen05.alloc.cta_group::1.sync.aligned.shared::cta.b32 [%0], %1;"
                     :: "r"(sbase + SM_TMEM_PTR), "r"(128u) : "memory");
        asm volatile("tcgen05.relinquish_alloc_permit.cta_group::1.sync.aligned;");
    }
    if (tid == 0) {
        asm volatile("mbarrier.init.shared.b64 [%0], %1;"
                     :: "r"(sbase + SM_MBAR), "r"(1u) : "memory");
    }
    __syncthreads();

    uint32_t tmem;
    asm volatile("ld.shared.b32 %0, [%1];" : "=r"(tmem) : "r"(sbase + SM_TMEM_PTR));

    // A mapping: iteration p -> (row = (tid + p*256)>>4, c4 = ((tid+p*256)&15)*4)
    // B mapping: iteration p -> (kg = (tid + p*256)>>7, n = (tid+p*256)&127);
    //            thread loads W[kb+kg*4+q][n] q=0..3 (coalesced per q),
    //            stores B_sm[n][kg*4..kg*4+3] as one 16B chunk per version.
    const int a_row = tid >> 4;
    const int a_c4  = (tid & 15) * 4;
    const int b_n   = tid & 127;
    const int b_kg0 = tid >> 7;        // 0 or 1; iteration adds p*2

    for (int kc = 0; kc < NUM_KCHUNK; kc++) {
        const int kb = kc * K_CHUNK;

        // ---- 1) issue global loads into registers (latency overlapped with
        //         the MMA wait below) ----
        float4 a_pre[8];
        float4 b_pre[8];
        #pragma unroll
        for (int p = 0; p < 8; p++) {
            const int row = a_row + p * 16;
            const int gr  = block_row + row;
            a_pre[p] = make_float4(0.f, 0.f, 0.f, 0.f);
            if (gr < N_NODES)
                a_pre[p] = *(const float4*)(x + (size_t)gr * IN_F + kb + a_c4);
        }
        #pragma unroll
        for (int p = 0; p < 8; p++) {
            const int kg = b_kg0 + p * 2;            // 0..15
            const float* wp = w + (size_t)(kb + kg * 4) * OUT_F + b_n;
            b_pre[p].x = __ldg(wp);
            b_pre[p].y = __ldg(wp + OUT_F);
            b_pre[p].z = __ldg(wp + 2 * OUT_F);
            b_pre[p].w = __ldg(wp + 3 * OUT_F);
        }

        // ---- 2) wait for previous chunk's MMAs before overwriting SMEM ----
        if (kc >= 1)
            mbar_wait(sbase + SM_MBAR, (uint32_t)((kc - 1) & 1));

        // ---- 3) convert + store to SMEM ----
        #pragma unroll
        for (int p = 0; p < 8; p++) {
            const int row = a_row + p * 16;
            const float4 v = a_pre[p];
            uint32_t bx = tf32_rna(v.x), by = tf32_rna(v.y),
                     bz = tf32_rna(v.z), bw = tf32_rna(v.w);
            const uint32_t o = tile_off(row, a_c4);
            *(uint4*)(smem + SM_A_BIG + o) = make_uint4(bx, by, bz, bw);
            *(float4*)(smem + SM_A_SMALL + o) = make_float4(
                v.x - __uint_as_float(bx), v.y - __uint_as_float(by),
                v.z - __uint_as_float(bz), v.w - __uint_as_float(bw));
        }
        #pragma unroll
        for (int p = 0; p < 8; p++) {
            const int kg = b_kg0 + p * 2;
            const float4 v = b_pre[p];
            uint32_t b0 = tf32_rna(v.x), b1 = tf32_rna(v.y),
                     b2 = tf32_rna(v.z), b3 = tf32_rna(v.w);
            const uint32_t o = tile_off(b_n, kg * 4);
            *(uint4*)(smem + SM_B_BIG + o) = make_uint4(b0, b1, b2, b3);
            *(float4*)(smem + SM_B_SMALL + o) = make_float4(
                v.x - __uint_as_float(b0), v.y - __uint_as_float(b1),
                v.z - __uint_as_float(b2), v.w - __uint_as_float(b3));
        }
        asm volatile("fence.proxy.async.shared::cta;" ::: "memory");
        __syncthreads();

        // ---- 4) issue MMAs; commit ----
        if (wid == 0 && elect_one()) {
            const uint64_t ab = MAKE_DESC(sbase + SM_A_BIG);
            const uint64_t as = MAKE_DESC(sbase + SM_A_SMALL);
            const uint64_t bb = MAKE_DESC(sbase + SM_B_BIG);
            const uint64_t bs = MAKE_DESC(sbase + SM_B_SMALL);
            #pragma unroll
            for (int s = 0; s < K_CHUNK / 8; s++) {
                const uint64_t off = (uint64_t)((s >> 2) * 1024 + (s & 3) * 2);
                const uint32_t first = (kc == 0 && s == 0) ? 0u : 1u;
                mma_tf32_ss(tmem, ab + off, bb + off, TF32_IDESC, first);
                mma_tf32_ss(tmem, as + off, bb + off, TF32_IDESC, 1u);
                mma_tf32_ss(tmem, ab + off, bs + off, TF32_IDESC, 1u);
            }
            asm volatile(
                "tcgen05.commit.cta_group::1.mbarrier::arrive::one.shared::cluster.b64 [%0];"
                :: "r"(sbase + SM_MBAR) : "memory");
        }
    }

    // Final wait: 4th commit -> parity 1.
    mbar_wait(sbase + SM_MBAR, 1u);
    asm volatile("tcgen05.fence::after_thread_sync;" ::: "memory");

    // epilogue: 8 warps read D from TMEM, store to g_support
    {
        const int sub  = wid & 3;
        const int half = wid >> 2;
        uint32_t d[64];
        const uint32_t taddr = tmem + half * 64;
        asm volatile(
            "tcgen05.ld.sync.aligned.32x32b.x32.b32 "
            "{%0,%1,%2,%3,%4,%5,%6,%7,%8,%9,%10,%11,%12,%13,%14,%15,"
            "%16,%17,%18,%19,%20,%21,%22,%23,%24,%25,%26,%27,%28,%29,%30,%31}, [%32];"
            : "=r"(d[0]),"=r"(d[1]),"=r"(d[2]),"=r"(d[3]),"=r"(d[4]),"=r"(d[5]),"=r"(d[6]),"=r"(d[7]),
              "=r"(d[8]),"=r"(d[9]),"=r"(d[10]),"=r"(d[11]),"=r"(d[12]),"=r"(d[13]),"=r"(d[14]),"=r"(d[15]),
              "=r"(d[16]),"=r"(d[17]),"=r"(d[18]),"=r"(d[19]),"=r"(d[20]),"=r"(d[21]),"=r"(d[22]),"=r"(d[23]),
              "=r"(d[24]),"=r"(d[25]),"=r"(d[26]),"=r"(d[27]),"=r"(d[28]),"=r"(d[29]),"=r"(d[30]),"=r"(d[31])
            : "r"(taddr));
        asm volatile(
            "tcgen05.ld.sync.aligned.32x32b.x32.b32 "
            "{%0,%1,%2,%3,%4,%5,%6,%7,%8,%9,%10,%11,%12,%13,%14,%15,"
            "%16,%17,%18,%19,%20,%21,%22,%23,%24,%25,%26,%27,%28,%29,%30,%31}, [%32];"
            : "=r"(d[32]),"=r"(d[33]),"=r"(d[34]),"=r"(d[35]),"=r"(d[36]),"=r"(d[37]),"=r"(d[38]),"=r"(d[39]),
              "=r"(d[40]),"=r"(d[41]),"=r"(d[42]),"=r"(d[43]),"=r"(d[44]),"=r"(d[45]),"=r"(d[46]),"=r"(d[47]),
              "=r"(d[48]),"=r"(d[49]),"=r"(d[50]),"=r"(d[51]),"=r"(d[52]),"=r"(d[53]),"=r"(d[54]),"=r"(d[55]),
              "=r"(d[56]),"=r"(d[57]),"=r"(d[58]),"=r"(d[59]),"=r"(d[60]),"=r"(d[61]),"=r"(d[62]),"=r"(d[63])
            : "r"(taddr + 32));
        asm volatile("tcgen05.wait::ld.sync.aligned;" ::: "memory");

        const int gr = block_row + sub * 32 + lane;
        if (gr < N_NODES) {
            float* sp = g_support + (size_t)gr * OUT_F + half * 64;
            #pragma unroll
            for (int q = 0; q < 16; q++) {
                *(float4*)(sp + q * 4) = make_float4(
                    __uint_as_float(d[q * 4 + 0]), __uint_as_float(d[q * 4 + 1]),
                    __uint_as_float(d[q * 4 + 2]), __uint_as_float(d[q * 4 + 3]));
            }
        }
    }

    __syncthreads();
    if (tid == 0) {
        asm volatile("mbarrier.inval.shared.b64 [%0];" :: "r"(sbase + SM_MBAR) : "memory");
    }
    if (wid == 0) {
        asm volatile("tcgen05.dealloc.cta_group::1.sync.aligned.b32 %0, %1;"
                     :: "r"(tmem), "r"(128u));
    }

#else
    // ---------------- FFMA fallback (family compute_103 pass) ----------------
    const int BK = 16;
    float* As = (float*)smem;
    float* Bs = As + BK * 128;

    const int tx = tid & 15;
    const int ty = tid >> 4;
    const int a_row = tid >> 1;
    const int a_col = (tid & 1) * 8;
    const int b_row = tid >> 4;
    const int b_col = (tid & 15) * 8;

    float acc[8][8];
    #pragma unroll
    for (int i = 0; i < 8; i++)
        #pragma unroll
        for (int j = 0; j < 8; j++)
            acc[i][j] = 0.0f;

    const int g_arow = block_row + a_row;
    const bool a_valid = (g_arow < N_NODES);

    for (int kt = 0; kt < IN_F; kt += BK) {
        {
            float4 v0, v1;
            if (a_valid) {
                const float* xp = x + (size_t)g_arow * IN_F + kt + a_col;
                v0 = *(const float4*)(xp);
                v1 = *(const float4*)(xp + 4);
            } else {
                v0 = make_float4(0.f, 0.f, 0.f, 0.f);
                v1 = v0;
            }
            As[(a_col + 0) * 128 + a_row] = v0.x;
            As[(a_col + 1) * 128 + a_row] = v0.y;
            As[(a_col + 2) * 128 + a_row] = v0.z;
            As[(a_col + 3) * 128 + a_row] = v0.w;
            As[(a_col + 4) * 128 + a_row] = v1.x;
            As[(a_col + 5) * 128 + a_row] = v1.y;
            As[(a_col + 6) * 128 + a_row] = v1.z;
            As[(a_col + 7) * 128 + a_row] = v1.w;
        }
        {
            const float* wp = w + (size_t)(kt + b_row) * OUT_F + b_col;
            float4 v0 = *(const float4*)(wp);
            float4 v1 = *(const float4*)(wp + 4);
            *(float4*)(&Bs[b_row * 128 + b_col])     = v0;
            *(float4*)(&Bs[b_row * 128 + b_col + 4]) = v1;
        }
        __syncthreads();

        #pragma unroll
        for (int k = 0; k < BK; k++) {
            float a[8], b[8];
            float4 av0 = *(const float4*)(&As[k * 128 + ty * 8]);
            float4 av1 = *(const float4*)(&As[k * 128 + ty * 8 + 4]);
            float4 bv0 = *(const float4*)(&Bs[k * 128 + tx * 8]);
            float4 bv1 = *(const float4*)(&Bs[k * 128 + tx * 8 + 4]);
            a[0]=av0.x; a[1]=av0.y; a[2]=av0.z; a[3]=av0.w;
            a[4]=av1.x; a[5]=av1.y; a[6]=av1.z; a[7]=av1.w;
            b[0]=bv0.x; b[1]=bv0.y; b[2]=bv0.z; b[3]=bv0.w;
            b[4]=bv1.x; b[5]=bv1.y; b[6]=bv1.z; b[7]=bv1.w;
            #pragma unroll
            for (int i = 0; i < 8; i++)
                #pragma unroll
                for (int j = 0; j < 8; j++)
                    acc[i][j] = fmaf(a[i], b[j], acc[i][j]);
        }
        __syncthreads();
    }

    #pragma unroll
    for (int i = 0; i < 8; i++) {
        const int gr = block_row + ty * 8 + i;
        if (gr < N_NODES) {
            float* sp = g_support + (size_t)gr * OUT_F + tx * 8;
            *(float4*)(sp)     = make_float4(acc[i][0], acc[i][1], acc[i][2], acc[i][3]);
            *(float4*)(sp + 4) = make_float4(acc[i][4], acc[i][5], acc[i][6], acc[i][7]);
        }
    }
#endif
}

// ---------------------------------------------------------------------------
// CSR build
// ---------------------------------------------------------------------------
__global__ void gcn_zero_counts_kernel()
{
    int i = blockIdx.x * blockDim.x + threadIdx.x;
    if (i < N_NODES) g_counts[i] = 0;
}

__global__ void gcn_histogram_kernel(const int* __restrict__ edge_rows)
{
    int e = blockIdx.x * blockDim.x + threadIdx.x;
    if (e < N_EDGES) atomicAdd(&g_counts[edge_rows[e]], 1);
}

__global__ __launch_bounds__(1024) void gcn_scan_reduce_kernel()
{
    __shared__ int sdata[32];
    const int i = blockIdx.x * SCAN_CHUNK + threadIdx.x;
    int v = (i < N_NODES) ? g_counts[i] : 0;
    #pragma unroll
    for (int off = 16; off > 0; off >>= 1)
        v += __shfl_down_sync(0xffffffffu, v, off);
    if ((threadIdx.x & 31) == 0) sdata[threadIdx.x >> 5] = v;
    __syncthreads();
    if (threadIdx.x < 32) {
        int w = sdata[threadIdx.x];
        #pragma unroll
        for (int off = 16; off > 0; off >>= 1)
            w += __shfl_down_sync(0xffffffffu, w, off);
        if (threadIdx.x == 0) g_partials[blockIdx.x] = w;
    }
}

__global__ void gcn_scan_partials_kernel()
{
    __shared__ int s[64];
    int v = (threadIdx.x < NUM_CHUNKS) ? g_partials[threadIdx.x] : 0;
    s[threadIdx.x] = v;
    __syncthreads();
    #pragma unroll
    for (int off = 1; off < 64; off <<= 1) {
        int t = (threadIdx.x >= off) ? s[threadIdx.x - off] : 0;
        __syncthreads();
        s[threadIdx.x] += t;
        __syncthreads();
    }
    if (threadIdx.x < NUM_CHUNKS) g_chunk_base[threadIdx.x] = s[threadIdx.x] - v;
    if (threadIdx.x == 63) g_offsets[N_NODES] = s[63];
}

__global__ __launch_bounds__(1024) void gcn_scan_final_kernel()
{
    __shared__ int warp_sums[32];
    const int i = blockIdx.x * SCAN_CHUNK + threadIdx.x;
    const int lane = threadIdx.x & 31;
    const int warp = threadIdx.x >> 5;

    int v = (i < N_NODES) ? g_counts[i] : 0;
    int incl = v;
    #pragma unroll
    for (int off = 1; off < 32; off <<= 1) {
        int t = __shfl_up_sync(0xffffffffu, incl, off);
        if (lane >= off) incl += t;
    }
    if (lane == 31) warp_sums[warp] = incl;
    __syncthreads();
    if (warp == 0) {
        int w = warp_sums[lane];
        int wi = w;
        #pragma unroll
        for (int off = 1; off < 32; off <<= 1) {
            int t = __shfl_up_sync(0xffffffffu, wi, off);
            if (lane >= off) wi += t;
        }
        warp_sums[lane] = wi - w;
    }
    __syncthreads();

    if (i < N_NODES) {
        int o = g_chunk_base[blockIdx.x] + warp_sums[warp] + (incl - v);
        g_offsets[i] = o;
        g_cursor[i]  = o;
    }
}

__global__ void gcn_permute_kernel(const int*   __restrict__ edge_rows,
                                   const int*   __restrict__ edge_cols,
                                   const float* __restrict__ edge_vals)
{
    int e = blockIdx.x * blockDim.x + threadIdx.x;
    if (e < N_EDGES) {
        int r = edge_rows[e];
        int pos = atomicAdd(&g_cursor[r], 1);
        g_sorted[pos] = make_int2(edge_cols[e], __float_as_int(edge_vals[e]));
    }
}

// ---------------------------------------------------------------------------
// Aggregate: one warp per node, 4-way unrolled gathers. (L2-throughput floor.)
// ---------------------------------------------------------------------------
__global__ __launch_bounds__(256) void gcn_aggregate_kernel(
    float* __restrict__ out,
    const float* __restrict__ bias)
{
    const int warp_id = (blockIdx.x * blockDim.x + threadIdx.x) >> 5;
    const int lane    = threadIdx.x & 31;
    if (warp_id >= N_NODES) return;

    const int start = g_offsets[warp_id];
    const int end   = g_offsets[warp_id + 1];

    float4 acc = make_float4(0.f, 0.f, 0.f, 0.f);
    const float4* sup = (const float4*)g_support;

    for (int base = start; base < end; base += 32) {
        const int n = min(32, end - base);
        int2 ev = make_int2(0, 0);
        if (lane < n)
            ev = __ldg(&g_sorted[base + lane]);
        const int   c = ev.x;
        const float v = __int_as_float(ev.y);

        int j = 0;
        for (; j + 4 <= n; j += 4) {
            const int   c0 = __shfl_sync(0xffffffffu, c, j + 0);
            const int   c1 = __shfl_sync(0xffffffffu, c, j + 1);
            const int   c2 = __shfl_sync(0xffffffffu, c, j + 2);
            const int   c3 = __shfl_sync(0xffffffffu, c, j + 3);
            const float v0 = __shfl_sync(0xffffffffu, v, j + 0);
            const float v1 = __shfl_sync(0xffffffffu, v, j + 1);
            const float v2 = __shfl_sync(0xffffffffu, v, j + 2);
            const float v3 = __shfl_sync(0xffffffffu, v, j + 3);
            const float4 m0 = __ldg(sup + (size_t)c0 * 32 + lane);
            const float4 m1 = __ldg(sup + (size_t)c1 * 32 + lane);
            const float4 m2 = __ldg(sup + (size_t)c2 * 32 + lane);
            const float4 m3 = __ldg(sup + (size_t)c3 * 32 + lane);
            acc.x = fmaf(v0, m0.x, acc.x); acc.y = fmaf(v0, m0.y, acc.y);
            acc.z = fmaf(v0, m0.z, acc.z); acc.w = fmaf(v0, m0.w, acc.w);
            acc.x = fmaf(v1, m1.x, acc.x); acc.y = fmaf(v1, m1.y, acc.y);
            acc.z = fmaf(v1, m1.z, acc.z); acc.w = fmaf(v1, m1.w, acc.w);
            acc.x = fmaf(v2, m2.x, acc.x); acc.y = fmaf(v2, m2.y, acc.y);
            acc.z = fmaf(v2, m2.z, acc.z); acc.w = fmaf(v2, m2.w, acc.w);
            acc.x = fmaf(v3, m3.x, acc.x); acc.y = fmaf(v3, m3.y, acc.y);
            acc.z = fmaf(v3, m3.z, acc.z); acc.w = fmaf(v3, m3.w, acc.w);
        }
        for (; j < n; j++) {
            const int   cj = __shfl_sync(0xffffffffu, c, j);
            const float vj = __shfl_sync(0xffffffffu, v, j);
            const float4 m = __ldg(sup + (size_t)cj * 32 + lane);
            acc.x = fmaf(vj, m.x, acc.x);
            acc.y = fmaf(vj, m.y, acc.y);
            acc.z = fmaf(vj, m.z, acc.z);
            acc.w = fmaf(vj, m.w, acc.w);
        }
    }

    const float4 b = __ldg(((const float4*)bias) + lane);
    acc.x += b.x; acc.y += b.y; acc.z += b.z; acc.w += b.w;
    ((float4*)out)[(size_t)warp_id * 32 + lane] = acc;
}

// ---------------------------------------------------------------------------
// kernel_launch
// Inputs (metadata order): x, edge_rows, edge_cols, edge_vals, weight, bias
// ---------------------------------------------------------------------------
extern "C" void kernel_launch(void* const* d_in, const int* in_sizes, int n_in,
                              void* d_out, int out_size)
{
    const float* x         = (const float*)d_in[0];
    const int*   edge_rows = (const int*)  d_in[1];
    const int*   edge_cols = (const int*)  d_in[2];
    const float* edge_vals = (const float*)d_in[3];
    const float* weight    = (const float*)d_in[4];
    const float* bias      = (const float*)d_in[5];
    float*       out       = (float*)d_out;

    // 1) support = x @ W  (tcgen05 TF32x3, prefetch-pipelined loads)
    static bool attr_set = false;
    if (!attr_set) {
        cudaFuncSetAttribute(gcn_gemm_tc_kernel,
                             cudaFuncAttributeMaxDynamicSharedMemorySize, SM_TOTAL);
        attr_set = true;
    }
    gcn_gemm_tc_kernel<<<(N_NODES + 127) / 128, 256, SM_TOTAL>>>(x, weight);

    // 2) CSR build
    gcn_zero_counts_kernel<<<(N_NODES + 255) / 256, 256>>>();
    gcn_histogram_kernel<<<(N_EDGES + 255) / 256, 256>>>(edge_rows);
    gcn_scan_reduce_kernel<<<NUM_CHUNKS, 1024>>>();
    gcn_scan_partials_kernel<<<1, 64>>>();
    gcn_scan_final_kernel<<<NUM_CHUNKS, 1024>>>();
    gcn_permute_kernel<<<(N_EDGES + 255) / 256, 256>>>(edge_rows, edge_cols, edge_vals);

    // 3) aggregate + bias
    {
        const int warps_per_block = 256 / 32;
        const int blocks = (N_NODES + warps_per_block - 1) / warps_per_block;
        gcn_aggregate_kernel<<<blocks, 256>>>(out, bias);
    }
}

// round 11
// speedup vs baseline: 1.9211x; 1.3901x over previous
#include <cuda_runtime.h>
#include <cstdint>

#define N_NODES 50000
#define N_EDGES 600000
#define IN_F    256
#define OUT_F   128

#define SCAN_CHUNK   1024
#define NUM_CHUNKS   ((N_NODES + SCAN_CHUNK - 1) / SCAN_CHUNK)   // 49

// Scratch (alloc-free rule: __device__ globals)
__device__ float g_support[(size_t)N_NODES * OUT_F];   // 25.6 MB
__device__ int   g_counts[N_NODES];
__device__ int   g_offsets[N_NODES + 1];
__device__ int   g_cursor[N_NODES];
__device__ int   g_partials[NUM_CHUNKS];
__device__ int   g_chunk_base[NUM_CHUNKS];
__device__ int2  g_sorted[N_EDGES];                    // {col, val_bits}

#if defined(__CUDA_ARCH__) && (__CUDA_ARCH__ == 1030) && \
    (defined(__CUDA_ARCH_FEAT_SM103_ALL) || defined(__CUDA_ARCH_SPECIFIC__))
#define GCN_HAS_TCGEN05 1
#else
#define GCN_HAS_TCGEN05 0
#endif

// ===========================================================================
// GEMM: support = x @ W, tcgen05 kind::tf32, 3xTF32.
// R11: K_CHUNK=32 -> 65 KB SMEM -> 3 CTAs/SM -> single-wave occupancy.
// Cross-CTA overlap hides per-chunk latency (R7's failure was 1 CTA/SM).
// ===========================================================================

#define K_CHUNK     32
#define NUM_KCHUNK  (IN_F / K_CHUNK)       // 8
#define TILE_BYTES  (128 * K_CHUNK * 4)    // 16384 per tile version

#define SM_TMEM_PTR 0
#define SM_MBAR     8
#define SM_A_BIG    1024
#define SM_A_SMALL  (SM_A_BIG   + TILE_BYTES)
#define SM_B_BIG    (SM_A_SMALL + TILE_BYTES)
#define SM_B_SMALL  (SM_B_BIG   + TILE_BYTES)
#define SM_TOTAL    (SM_B_SMALL + TILE_BYTES)   // 66560 (~65 KB)

#define TF32_IDESC  0x8200910u

#define DESC_BASE   0x4000404000010000ull
#define MAKE_DESC(a) (DESC_BASE | (uint64_t)(((a) >> 4) & 0x3FFF))

__device__ __forceinline__ uint32_t smem_u32(const void* p) {
    uint32_t a;
    asm("{ .reg .u64 t; cvta.to.shared.u64 t, %1; cvt.u32.u64 %0, t; }"
        : "=r"(a) : "l"(p));
    return a;
}

#if GCN_HAS_TCGEN05
__device__ __forceinline__ uint32_t tf32_rna(float a) {
    uint32_t r;
    asm("cvt.rna.tf32.f32 %0, %1;" : "=r"(r) : "f"(a));
    return r;
}

__device__ __forceinline__ uint32_t elect_one() {
    uint32_t p;
    asm volatile("{ .reg .pred p; elect.sync _|p, 0xFFFFFFFF; selp.b32 %0,1,0,p; }"
                 : "=r"(p));
    return p;
}

__device__ __forceinline__ void mma_tf32_ss(uint32_t d_tmem, uint64_t a_desc,
                                            uint64_t b_desc, uint32_t idesc,
                                            uint32_t enable_d) {
    asm volatile(
        "{\n\t.reg .pred p;\n\tsetp.ne.u32 p, %4, 0;\n\t"
        "tcgen05.mma.cta_group::1.kind::tf32 [%0], %1, %2, %3, {%5,%5,%5,%5}, p;\n\t}"
        :: "r"(d_tmem), "l"(a_desc), "l"(b_desc), "r"(idesc),
           "r"(enable_d), "r"(0u)
        : "memory");
}

__device__ __forceinline__ void mbar_wait(uint32_t addr, uint32_t parity) {
    uint32_t done;
    asm volatile(
        "{\n\t.reg .pred p;\n\t"
        "mbarrier.try_wait.parity.acquire.cta.shared::cta.b64 p, [%1], %2;\n\t"
        "selp.b32 %0, 1, 0, p;\n\t}"
        : "=r"(done) : "r"(addr), "r"(parity) : "memory");
    while (!done) {
        asm volatile(
            "{\n\t.reg .pred p;\n\t"
            "mbarrier.try_wait.parity.acquire.cta.shared::cta.b64 p, [%1], %2, 0x989680;\n\t"
            "selp.b32 %0, 1, 0, p;\n\t}"
            : "=r"(done) : "r"(addr), "r"(parity) : "memory");
    }
}

__device__ __forceinline__ uint32_t swz(uint32_t b) {
    return b ^ ((b >> 3) & 0x70);
}

// SW128 atom byte offset for (row, col) in a 128 x 32 f32 tile:
// each row = 32 floats = 128B = one SW128 atom row; 16 atom-rows of 1024B.
__device__ __forceinline__ uint32_t tile_off(int row, int col) {
    uint32_t byte = (uint32_t)((row >> 3) * 1024 + (row & 7) * 128 + col * 4);
    return swz(byte);
}
#endif  // GCN_HAS_TCGEN05

__global__ __launch_bounds__(256) void gcn_gemm_tc_kernel(
    const float* __restrict__ x,
    const float* __restrict__ w)
{
    extern __shared__ char smem[];
    const int tid  = threadIdx.x;
    const int block_row = blockIdx.x * 128;

#if GCN_HAS_TCGEN05
    const uint32_t sbase = smem_u32(smem);
    const int wid  = tid >> 5;
    const int lane = tid & 31;

    if (wid == 0) {
        asm volatile("tcgen05.alloc.cta_group::1.sync.aligned.shared::cta.b32 [%0], %1;"
                     :: "r"(sbase + SM_TMEM_PTR), "r"(128u) : "memory");
        asm volatile("tcgen05.relinquish_alloc_permit.cta_group::1.sync.aligned;");
    }
    if (tid == 0) {
        asm volatile("mbarrier.init.shared.b64 [%0], %1;"
                     :: "r"(sbase + SM_MBAR), "r"(1u) : "memory");
    }
    __syncthreads();

    uint32_t tmem;
    asm volatile("ld.shared.b32 %0, [%1];" : "=r"(tmem) : "r"(sbase + SM_TMEM_PTR));

    // A: 128 rows x 8 float4 = 1024 float4 per chunk; 4 per thread.
    //    thread -> (row = i>>3, c4 = (i&7)*4)
    // B: 32 k x 128 n; thread owns n = tid&127, k-group kg in {0,1} + p*... :
    //    8 k-groups of 4; thread handles kg = (tid>>7) + 2p, p=0..3.
    const int a_row = tid >> 3;          // 0..31  (+32 per p)
    const int a_c4  = (tid & 7) * 4;     // 0..28
    const int b_n   = tid & 127;
    const int b_kg0 = tid >> 7;          // 0 or 1

    for (int kc = 0; kc < NUM_KCHUNK; kc++) {
        const int kb = kc * K_CHUNK;

        // 1) issue global loads into registers
        float4 a_pre[4];
        float4 b_pre[4];
        #pragma unroll
        for (int p = 0; p < 4; p++) {
            const int row = a_row + p * 32;
            const int gr  = block_row + row;
            a_pre[p] = make_float4(0.f, 0.f, 0.f, 0.f);
            if (gr < N_NODES)
                a_pre[p] = *(const float4*)(x + (size_t)gr * IN_F + kb + a_c4);
        }
        #pragma unroll
        for (int p = 0; p < 4; p++) {
            const int kg = b_kg0 + p * 2;            // 0..7
            const float* wp = w + (size_t)(kb + kg * 4) * OUT_F + b_n;
            b_pre[p].x = __ldg(wp);
            b_pre[p].y = __ldg(wp + OUT_F);
            b_pre[p].z = __ldg(wp + 2 * OUT_F);
            b_pre[p].w = __ldg(wp + 3 * OUT_F);
        }

        // 2) wait for previous chunk's MMAs before overwriting SMEM
        if (kc >= 1)
            mbar_wait(sbase + SM_MBAR, (uint32_t)((kc - 1) & 1));

        // 3) convert + store to SMEM
        #pragma unroll
        for (int p = 0; p < 4; p++) {
            const int row = a_row + p * 32;
            const float4 v = a_pre[p];
            uint32_t bx = tf32_rna(v.x), by = tf32_rna(v.y),
                     bz = tf32_rna(v.z), bw = tf32_rna(v.w);
            const uint32_t o = tile_off(row, a_c4);
            *(uint4*)(smem + SM_A_BIG + o) = make_uint4(bx, by, bz, bw);
            *(float4*)(smem + SM_A_SMALL + o) = make_float4(
                v.x - __uint_as_float(bx), v.y - __uint_as_float(by),
                v.z - __uint_as_float(bz), v.w - __uint_as_float(bw));
        }
        #pragma unroll
        for (int p = 0; p < 4; p++) {
            const int kg = b_kg0 + p * 2;
            const float4 v = b_pre[p];
            uint32_t b0 = tf32_rna(v.x), b1 = tf32_rna(v.y),
                     b2 = tf32_rna(v.z), b3 = tf32_rna(v.w);
            const uint32_t o = tile_off(b_n, kg * 4);
            *(uint4*)(smem + SM_B_BIG + o) = make_uint4(b0, b1, b2, b3);
            *(float4*)(smem + SM_B_SMALL + o) = make_float4(
                v.x - __uint_as_float(b0), v.y - __uint_as_float(b1),
                v.z - __uint_as_float(b2), v.w - __uint_as_float(b3));
        }
        asm volatile("fence.proxy.async.shared::cta;" ::: "memory");
        __syncthreads();

        // 4) issue MMAs; commit
        if (wid == 0 && elect_one()) {
            const uint64_t ab = MAKE_DESC(sbase + SM_A_BIG);
            const uint64_t as = MAKE_DESC(sbase + SM_A_SMALL);
            const uint64_t bb = MAKE_DESC(sbase + SM_B_BIG);
            const uint64_t bs = MAKE_DESC(sbase + SM_B_SMALL);
            #pragma unroll
            for (int s = 0; s < K_CHUNK / 8; s++) {     // 4 k-steps of K=8
                const uint64_t off = (uint64_t)(s * 2); // 32B per step
                const uint32_t first = (kc == 0 && s == 0) ? 0u : 1u;
                mma_tf32_ss(tmem, ab + off, bb + off, TF32_IDESC, first);
                mma_tf32_ss(tmem, as + off, bb + off, TF32_IDESC, 1u);
                mma_tf32_ss(tmem, ab + off, bs + off, TF32_IDESC, 1u);
            }
            asm volatile(
                "tcgen05.commit.cta_group::1.mbarrier::arrive::one.shared::cluster.b64 [%0];"
                :: "r"(sbase + SM_MBAR) : "memory");
        }
    }

    // Final wait: 8th commit -> parity (8-1)&1 = 1.
    mbar_wait(sbase + SM_MBAR, 1u);
    asm volatile("tcgen05.fence::after_thread_sync;" ::: "memory");

    // epilogue: 8 warps read D from TMEM, store to g_support
    {
        const int sub  = wid & 3;
        const int half = wid >> 2;
        uint32_t d[64];
        const uint32_t taddr = tmem + half * 64;
        asm volatile(
            "tcgen05.ld.sync.aligned.32x32b.x32.b32 "
            "{%0,%1,%2,%3,%4,%5,%6,%7,%8,%9,%10,%11,%12,%13,%14,%15,"
            "%16,%17,%18,%19,%20,%21,%22,%23,%24,%25,%26,%27,%28,%29,%30,%31}, [%32];"
            : "=r"(d[0]),"=r"(d[1]),"=r"(d[2]),"=r"(d[3]),"=r"(d[4]),"=r"(d[5]),"=r"(d[6]),"=r"(d[7]),
              "=r"(d[8]),"=r"(d[9]),"=r"(d[10]),"=r"(d[11]),"=r"(d[12]),"=r"(d[13]),"=r"(d[14]),"=r"(d[15]),
              "=r"(d[16]),"=r"(d[17]),"=r"(d[18]),"=r"(d[19]),"=r"(d[20]),"=r"(d[21]),"=r"(d[22]),"=r"(d[23]),
              "=r"(d[24]),"=r"(d[25]),"=r"(d[26]),"=r"(d[27]),"=r"(d[28]),"=r"(d[29]),"=r"(d[30]),"=r"(d[31])
            : "r"(taddr));
        asm volatile(
            "tcgen05.ld.sync.aligned.32x32b.x32.b32 "
            "{%0,%1,%2,%3,%4,%5,%6,%7,%8,%9,%10,%11,%12,%13,%14,%15,"
            "%16,%17,%18,%19,%20,%21,%22,%23,%24,%25,%26,%27,%28,%29,%30,%31}, [%32];"
            : "=r"(d[32]),"=r"(d[33]),"=r"(d[34]),"=r"(d[35]),"=r"(d[36]),"=r"(d[37]),"=r"(d[38]),"=r"(d[39]),
              "=r"(d[40]),"=r"(d[41]),"=r"(d[42]),"=r"(d[43]),"=r"(d[44]),"=r"(d[45]),"=r"(d[46]),"=r"(d[47]),
              "=r"(d[48]),"=r"(d[49]),"=r"(d[50]),"=r"(d[51]),"=r"(d[52]),"=r"(d[53]),"=r"(d[54]),"=r"(d[55]),
              "=r"(d[56]),"=r"(d[57]),"=r"(d[58]),"=r"(d[59]),"=r"(d[60]),"=r"(d[61]),"=r"(d[62]),"=r"(d[63])
            : "r"(taddr + 32));
        asm volatile("tcgen05.wait::ld.sync.aligned;" ::: "memory");

        const int gr = block_row + sub * 32 + lane;
        if (gr < N_NODES) {
            float* sp = g_support + (size_t)gr * OUT_F + half * 64;
            #pragma unroll
            for (int q = 0; q < 16; q++) {
                *(float4*)(sp + q * 4) = make_float4(
                    __uint_as_float(d[q * 4 + 0]), __uint_as_float(d[q * 4 + 1]),
                    __uint_as_float(d[q * 4 + 2]), __uint_as_float(d[q * 4 + 3]));
            }
        }
    }

    __syncthreads();
    if (tid == 0) {
        asm volatile("mbarrier.inval.shared.b64 [%0];" :: "r"(sbase + SM_MBAR) : "memory");
    }
    if (wid == 0) {
        asm volatile("tcgen05.dealloc.cta_group::1.sync.aligned.b32 %0, %1;"
                     :: "r"(tmem), "r"(128u));
    }

#else
    // ---------------- FFMA fallback (family compute_103 pass) ----------------
    const int BK = 16;
    float* As = (float*)smem;
    float* Bs = As + BK * 128;

    const int tx = tid & 15;
    const int ty = tid >> 4;
    const int a_row = tid >> 1;
    const int a_col = (tid & 1) * 8;
    const int b_row = tid >> 4;
    const int b_col = (tid & 15) * 8;

    float acc[8][8];
    #pragma unroll
    for (int i = 0; i < 8; i++)
        #pragma unroll
        for (int j = 0; j < 8; j++)
            acc[i][j] = 0.0f;

    const int g_arow = block_row + a_row;
    const bool a_valid = (g_arow < N_NODES);

    for (int kt = 0; kt < IN_F; kt += BK) {
        {
            float4 v0, v1;
            if (a_valid) {
                const float* xp = x + (size_t)g_arow * IN_F + kt + a_col;
                v0 = *(const float4*)(xp);
                v1 = *(const float4*)(xp + 4);
            } else {
                v0 = make_float4(0.f, 0.f, 0.f, 0.f);
                v1 = v0;
            }
            As[(a_col + 0) * 128 + a_row] = v0.x;
            As[(a_col + 1) * 128 + a_row] = v0.y;
            As[(a_col + 2) * 128 + a_row] = v0.z;
            As[(a_col + 3) * 128 + a_row] = v0.w;
            As[(a_col + 4) * 128 + a_row] = v1.x;
            As[(a_col + 5) * 128 + a_row] = v1.y;
            As[(a_col + 6) * 128 + a_row] = v1.z;
            As[(a_col + 7) * 128 + a_row] = v1.w;
        }
        {
            const float* wp = w + (size_t)(kt + b_row) * OUT_F + b_col;
            float4 v0 = *(const float4*)(wp);
            float4 v1 = *(const float4*)(wp + 4);
            *(float4*)(&Bs[b_row * 128 + b_col])     = v0;
            *(float4*)(&Bs[b_row * 128 + b_col + 4]) = v1;
        }
        __syncthreads();

        #pragma unroll
        for (int k = 0; k < BK; k++) {
            float a[8], b[8];
            float4 av0 = *(const float4*)(&As[k * 128 + ty * 8]);
            float4 av1 = *(const float4*)(&As[k * 128 + ty * 8 + 4]);
            float4 bv0 = *(const float4*)(&Bs[k * 128 + tx * 8]);
            float4 bv1 = *(const float4*)(&Bs[k * 128 + tx * 8 + 4]);
            a[0]=av0.x; a[1]=av0.y; a[2]=av0.z; a[3]=av0.w;
            a[4]=av1.x; a[5]=av1.y; a[6]=av1.z; a[7]=av1.w;
            b[0]=bv0.x; b[1]=bv0.y; b[2]=bv0.z; b[3]=bv0.w;
            b[4]=bv1.x; b[5]=bv1.y; b[6]=bv1.z; b[7]=bv1.w;
            #pragma unroll
            for (int i = 0; i < 8; i++)
                #pragma unroll
                for (int j = 0; j < 8; j++)
                    acc[i][j] = fmaf(a[i], b[j], acc[i][j]);
        }
        __syncthreads();
    }

    #pragma unroll
    for (int i = 0; i < 8; i++) {
        const int gr = block_row + ty * 8 + i;
        if (gr < N_NODES) {
            float* sp = g_support + (size_t)gr * OUT_F + tx * 8;
            *(float4*)(sp)     = make_float4(acc[i][0], acc[i][1], acc[i][2], acc[i][3]);
            *(float4*)(sp + 4) = make_float4(acc[i][4], acc[i][5], acc[i][6], acc[i][7]);
        }
    }
#endif
}

// ---------------------------------------------------------------------------
// CSR build
// ---------------------------------------------------------------------------
__global__ void gcn_zero_counts_kernel()
{
    int i = blockIdx.x * blockDim.x + threadIdx.x;
    if (i < N_NODES) g_counts[i] = 0;
}

__global__ void gcn_histogram_kernel(const int* __restrict__ edge_rows)
{
    int e = blockIdx.x * blockDim.x + threadIdx.x;
    if (e < N_EDGES) atomicAdd(&g_counts[edge_rows[e]], 1);
}

__global__ __launch_bounds__(1024) void gcn_scan_reduce_kernel()
{
    __shared__ int sdata[32];
    const int i = blockIdx.x * SCAN_CHUNK + threadIdx.x;
    int v = (i < N_NODES) ? g_counts[i] : 0;
    #pragma unroll
    for (int off = 16; off > 0; off >>= 1)
        v += __shfl_down_sync(0xffffffffu, v, off);
    if ((threadIdx.x & 31) == 0) sdata[threadIdx.x >> 5] = v;
    __syncthreads();
    if (threadIdx.x < 32) {
        int w = sdata[threadIdx.x];
        #pragma unroll
        for (int off = 16; off > 0; off >>= 1)
            w += __shfl_down_sync(0xffffffffu, w, off);
        if (threadIdx.x == 0) g_partials[blockIdx.x] = w;
    }
}

__global__ void gcn_scan_partials_kernel()
{
    __shared__ int s[64];
    int v = (threadIdx.x < NUM_CHUNKS) ? g_partials[threadIdx.x] : 0;
    s[threadIdx.x] = v;
    __syncthreads();
    #pragma unroll
    for (int off = 1; off < 64; off <<= 1) {
        int t = (threadIdx.x >= off) ? s[threadIdx.x - off] : 0;
        __syncthreads();
        s[threadIdx.x] += t;
        __syncthreads();
    }
    if (threadIdx.x < NUM_CHUNKS) g_chunk_base[threadIdx.x] = s[threadIdx.x] - v;
    if (threadIdx.x == 63) g_offsets[N_NODES] = s[63];
}

__global__ __launch_bounds__(1024) void gcn_scan_final_kernel()
{
    __shared__ int warp_sums[32];
    const int i = blockIdx.x * SCAN_CHUNK + threadIdx.x;
    const int lane = threadIdx.x & 31;
    const int warp = threadIdx.x >> 5;

    int v = (i < N_NODES) ? g_counts[i] : 0;
    int incl = v;
    #pragma unroll
    for (int off = 1; off < 32; off <<= 1) {
        int t = __shfl_up_sync(0xffffffffu, incl, off);
        if (lane >= off) incl += t;
    }
    if (lane == 31) warp_sums[warp] = incl;
    __syncthreads();
    if (warp == 0) {
        int w = warp_sums[lane];
        int wi = w;
        #pragma unroll
        for (int off = 1; off < 32; off <<= 1) {
            int t = __shfl_up_sync(0xffffffffu, wi, off);
            if (lane >= off) wi += t;
        }
        warp_sums[lane] = wi - w;
    }
    __syncthreads();

    if (i < N_NODES) {
        int o = g_chunk_base[blockIdx.x] + warp_sums[warp] + (incl - v);
        g_offsets[i] = o;
        g_cursor[i]  = o;
    }
}

__global__ void gcn_permute_kernel(const int*   __restrict__ edge_rows,
                                   const int*   __restrict__ edge_cols,
                                   const float* __restrict__ edge_vals)
{
    int e = blockIdx.x * blockDim.x + threadIdx.x;
    if (e < N_EDGES) {
        int r = edge_rows[e];
        int pos = atomicAdd(&g_cursor[r], 1);
        g_sorted[pos] = make_int2(edge_cols[e], __float_as_int(edge_vals[e]));
    }
}

// ---------------------------------------------------------------------------
// Aggregate: one warp per node, 4-way unrolled gathers. (L2-throughput floor.)
// ---------------------------------------------------------------------------
__global__ __launch_bounds__(256) void gcn_aggregate_kernel(
    float* __restrict__ out,
    const float* __restrict__ bias)
{
    const int warp_id = (blockIdx.x * blockDim.x + threadIdx.x) >> 5;
    const int lane    = threadIdx.x & 31;
    if (warp_id >= N_NODES) return;

    const int start = g_offsets[warp_id];
    const int end   = g_offsets[warp_id + 1];

    float4 acc = make_float4(0.f, 0.f, 0.f, 0.f);
    const float4* sup = (const float4*)g_support;

    for (int base = start; base < end; base += 32) {
        const int n = min(32, end - base);
        int2 ev = make_int2(0, 0);
        if (lane < n)
            ev = __ldg(&g_sorted[base + lane]);
        const int   c = ev.x;
        const float v = __int_as_float(ev.y);

        int j = 0;
        for (; j + 4 <= n; j += 4) {
            const int   c0 = __shfl_sync(0xffffffffu, c, j + 0);
            const int   c1 = __shfl_sync(0xffffffffu, c, j + 1);
            const int   c2 = __shfl_sync(0xffffffffu, c, j + 2);
            const int   c3 = __shfl_sync(0xffffffffu, c, j + 3);
            const float v0 = __shfl_sync(0xffffffffu, v, j + 0);
            const float v1 = __shfl_sync(0xffffffffu, v, j + 1);
            const float v2 = __shfl_sync(0xffffffffu, v, j + 2);
            const float v3 = __shfl_sync(0xffffffffu, v, j + 3);
            const float4 m0 = __ldg(sup + (size_t)c0 * 32 + lane);
            const float4 m1 = __ldg(sup + (size_t)c1 * 32 + lane);
            const float4 m2 = __ldg(sup + (size_t)c2 * 32 + lane);
            const float4 m3 = __ldg(sup + (size_t)c3 * 32 + lane);
            acc.x = fmaf(v0, m0.x, acc.x); acc.y = fmaf(v0, m0.y, acc.y);
            acc.z = fmaf(v0, m0.z, acc.z); acc.w = fmaf(v0, m0.w, acc.w);
            acc.x = fmaf(v1, m1.x, acc.x); acc.y = fmaf(v1, m1.y, acc.y);
            acc.z = fmaf(v1, m1.z, acc.z); acc.w = fmaf(v1, m1.w, acc.w);
            acc.x = fmaf(v2, m2.x, acc.x); acc.y = fmaf(v2, m2.y, acc.y);
            acc.z = fmaf(v2, m2.z, acc.z); acc.w = fmaf(v2, m2.w, acc.w);
            acc.x = fmaf(v3, m3.x, acc.x); acc.y = fmaf(v3, m3.y, acc.y);
            acc.z = fmaf(v3, m3.z, acc.z); acc.w = fmaf(v3, m3.w, acc.w);
        }
        for (; j < n; j++) {
            const int   cj = __shfl_sync(0xffffffffu, c, j);
            const float vj = __shfl_sync(0xffffffffu, v, j);
            const float4 m = __ldg(sup + (size_t)cj * 32 + lane);
            acc.x = fmaf(vj, m.x, acc.x);
            acc.y = fmaf(vj, m.y, acc.y);
            acc.z = fmaf(vj, m.z, acc.z);
            acc.w = fmaf(vj, m.w, acc.w);
        }
    }

    const float4 b = __ldg(((const float4*)bias) + lane);
    acc.x += b.x; acc.y += b.y; acc.z += b.z; acc.w += b.w;
    ((float4*)out)[(size_t)warp_id * 32 + lane] = acc;
}

// ---------------------------------------------------------------------------
// kernel_launch
// Inputs (metadata order): x, edge_rows, edge_cols, edge_vals, weight, bias
// ---------------------------------------------------------------------------
extern "C" void kernel_launch(void* const* d_in, const int* in_sizes, int n_in,
                              void* d_out, int out_size)
{
    const float* x         = (const float*)d_in[0];
    const int*   edge_rows = (const int*)  d_in[1];
    const int*   edge_cols = (const int*)  d_in[2];
    const float* edge_vals = (const float*)d_in[3];
    const float* weight    = (const float*)d_in[4];
    const float* bias      = (const float*)d_in[5];
    float*       out       = (float*)d_out;

    // 1) support = x @ W  (tcgen05 TF32x3, 3 CTAs/SM single-wave)
    static bool attr_set = false;
    if (!attr_set) {
        cudaFuncSetAttribute(gcn_gemm_tc_kernel,
                             cudaFuncAttributeMaxDynamicSharedMemorySize, SM_TOTAL);
        attr_set = true;
    }
    gcn_gemm_tc_kernel<<<(N_NODES + 127) / 128, 256, SM_TOTAL>>>(x, weight);

    // 2) CSR build
    gcn_zero_counts_kernel<<<(N_NODES + 255) / 256, 256>>>();
    gcn_histogram_kernel<<<(N_EDGES + 255) / 256, 256>>>(edge_rows);
    gcn_scan_reduce_kernel<<<NUM_CHUNKS, 1024>>>();
    gcn_scan_partials_kernel<<<1, 64>>>();
    gcn_scan_final_kernel<<<NUM_CHUNKS, 1024>>>();
    gcn_permute_kernel<<<(N_EDGES + 255) / 256, 256>>>(edge_rows, edge_cols, edge_vals);

    // 3) aggregate + bias
    {
        const int warps_per_block = 256 / 32;
        const int blocks = (N_NODES + warps_per_block - 1) / warps_per_block;
        gcn_aggregate_kernel<<<blocks, 256>>>(out, bias);
    }
}

// round 12
// speedup vs baseline: 2.2103x; 1.1506x over previous
#include <cuda_runtime.h>
#include <cstdint>

#define N_NODES 50000
#define N_EDGES 600000
#define IN_F    256
#define OUT_F   128

#define SCAN_CHUNK   1024
#define NUM_CHUNKS   ((N_NODES + SCAN_CHUNK - 1) / SCAN_CHUNK)   // 49

// Scratch (alloc-free rule: __device__ globals)
__device__ float g_support[(size_t)N_NODES * OUT_F];   // 25.6 MB
__device__ int   g_counts[N_NODES];
__device__ int   g_offsets[N_NODES + 1];
__device__ int   g_cursor[N_NODES];
__device__ int   g_partials[NUM_CHUNKS];
__device__ int   g_chunk_base[NUM_CHUNKS];
__device__ int2  g_sorted[N_EDGES];                    // {col, val_bits}

#if defined(__CUDA_ARCH__) && (__CUDA_ARCH__ == 1030) && \
    (defined(__CUDA_ARCH_FEAT_SM103_ALL) || defined(__CUDA_ARCH_SPECIFIC__))
#define GCN_HAS_TCGEN05 1
#else
#define GCN_HAS_TCGEN05 0
#endif

// ===========================================================================
// GEMM: support = x @ W, tcgen05 kind::tf32, 3xTF32.
// K_CHUNK=32 -> 65 KB SMEM -> 3 CTAs/SM -> single-wave occupancy. (R11 WIN)
// ===========================================================================

#define K_CHUNK     32
#define NUM_KCHUNK  (IN_F / K_CHUNK)       // 8
#define TILE_BYTES  (128 * K_CHUNK * 4)    // 16384 per tile version

#define SM_TMEM_PTR 0
#define SM_MBAR     8
#define SM_A_BIG    1024
#define SM_A_SMALL  (SM_A_BIG   + TILE_BYTES)
#define SM_B_BIG    (SM_A_SMALL + TILE_BYTES)
#define SM_B_SMALL  (SM_B_BIG   + TILE_BYTES)
#define SM_TOTAL    (SM_B_SMALL + TILE_BYTES)   // 66560 (~65 KB)

#define TF32_IDESC  0x8200910u

#define DESC_BASE   0x4000404000010000ull
#define MAKE_DESC(a) (DESC_BASE | (uint64_t)(((a) >> 4) & 0x3FFF))

__device__ __forceinline__ uint32_t smem_u32(const void* p) {
    uint32_t a;
    asm("{ .reg .u64 t; cvta.to.shared.u64 t, %1; cvt.u32.u64 %0, t; }"
        : "=r"(a) : "l"(p));
    return a;
}

#if GCN_HAS_TCGEN05
__device__ __forceinline__ uint32_t tf32_rna(float a) {
    uint32_t r;
    asm("cvt.rna.tf32.f32 %0, %1;" : "=r"(r) : "f"(a));
    return r;
}

__device__ __forceinline__ uint32_t elect_one() {
    uint32_t p;
    asm volatile("{ .reg .pred p; elect.sync _|p, 0xFFFFFFFF; selp.b32 %0,1,0,p; }"
                 : "=r"(p));
    return p;
}

__device__ __forceinline__ void mma_tf32_ss(uint32_t d_tmem, uint64_t a_desc,
                                            uint64_t b_desc, uint32_t idesc,
                                            uint32_t enable_d) {
    asm volatile(
        "{\n\t.reg .pred p;\n\tsetp.ne.u32 p, %4, 0;\n\t"
        "tcgen05.mma.cta_group::1.kind::tf32 [%0], %1, %2, %3, {%5,%5,%5,%5}, p;\n\t}"
        :: "r"(d_tmem), "l"(a_desc), "l"(b_desc), "r"(idesc),
           "r"(enable_d), "r"(0u)
        : "memory");
}

__device__ __forceinline__ void mbar_wait(uint32_t addr, uint32_t parity) {
    uint32_t done;
    asm volatile(
        "{\n\t.reg .pred p;\n\t"
        "mbarrier.try_wait.parity.acquire.cta.shared::cta.b64 p, [%1], %2;\n\t"
        "selp.b32 %0, 1, 0, p;\n\t}"
        : "=r"(done) : "r"(addr), "r"(parity) : "memory");
    while (!done) {
        asm volatile(
            "{\n\t.reg .pred p;\n\t"
            "mbarrier.try_wait.parity.acquire.cta.shared::cta.b64 p, [%1], %2, 0x989680;\n\t"
            "selp.b32 %0, 1, 0, p;\n\t}"
            : "=r"(done) : "r"(addr), "r"(parity) : "memory");
    }
}

__device__ __forceinline__ uint32_t swz(uint32_t b) {
    return b ^ ((b >> 3) & 0x70);
}

// SW128 atom byte offset for (row, col) in a 128 x 32 f32 tile
__device__ __forceinline__ uint32_t tile_off(int row, int col) {
    uint32_t byte = (uint32_t)((row >> 3) * 1024 + (row & 7) * 128 + col * 4);
    return swz(byte);
}
#endif  // GCN_HAS_TCGEN05

__global__ __launch_bounds__(256) void gcn_gemm_tc_kernel(
    const float* __restrict__ x,
    const float* __restrict__ w)
{
    extern __shared__ char smem[];
    const int tid  = threadIdx.x;
    const int block_row = blockIdx.x * 128;

#if GCN_HAS_TCGEN05
    const uint32_t sbase = smem_u32(smem);
    const int wid  = tid >> 5;
    const int lane = tid & 31;

    if (wid == 0) {
        asm volatile("tcgen05.alloc.cta_group::1.sync.aligned.shared::cta.b32 [%0], %1;"
                     :: "r"(sbase + SM_TMEM_PTR), "r"(128u) : "memory");
        asm volatile("tcgen05.relinquish_alloc_permit.cta_group::1.sync.aligned;");
    }
    if (tid == 0) {
        asm volatile("mbarrier.init.shared.b64 [%0], %1;"
                     :: "r"(sbase + SM_MBAR), "r"(1u) : "memory");
    }
    __syncthreads();

    uint32_t tmem;
    asm volatile("ld.shared.b32 %0, [%1];" : "=r"(tmem) : "r"(sbase + SM_TMEM_PTR));

    const int a_row = tid >> 3;          // 0..31  (+32 per p)
    const int a_c4  = (tid & 7) * 4;     // 0..28
    const int b_n   = tid & 127;
    const int b_kg0 = tid >> 7;          // 0 or 1

    for (int kc = 0; kc < NUM_KCHUNK; kc++) {
        const int kb = kc * K_CHUNK;

        // 1) issue global loads into registers
        float4 a_pre[4];
        float4 b_pre[4];
        #pragma unroll
        for (int p = 0; p < 4; p++) {
            const int row = a_row + p * 32;
            const int gr  = block_row + row;
            a_pre[p] = make_float4(0.f, 0.f, 0.f, 0.f);
            if (gr < N_NODES)
                a_pre[p] = *(const float4*)(x + (size_t)gr * IN_F + kb + a_c4);
        }
        #pragma unroll
        for (int p = 0; p < 4; p++) {
            const int kg = b_kg0 + p * 2;            // 0..7
            const float* wp = w + (size_t)(kb + kg * 4) * OUT_F + b_n;
            b_pre[p].x = __ldg(wp);
            b_pre[p].y = __ldg(wp + OUT_F);
            b_pre[p].z = __ldg(wp + 2 * OUT_F);
            b_pre[p].w = __ldg(wp + 3 * OUT_F);
        }

        // 2) wait for previous chunk's MMAs before overwriting SMEM
        if (kc >= 1)
            mbar_wait(sbase + SM_MBAR, (uint32_t)((kc - 1) & 1));

        // 3) convert + store to SMEM
        #pragma unroll
        for (int p = 0; p < 4; p++) {
            const int row = a_row + p * 32;
            const float4 v = a_pre[p];
            uint32_t bx = tf32_rna(v.x), by = tf32_rna(v.y),
                     bz = tf32_rna(v.z), bw = tf32_rna(v.w);
            const uint32_t o = tile_off(row, a_c4);
            *(uint4*)(smem + SM_A_BIG + o) = make_uint4(bx, by, bz, bw);
            *(float4*)(smem + SM_A_SMALL + o) = make_float4(
                v.x - __uint_as_float(bx), v.y - __uint_as_float(by),
                v.z - __uint_as_float(bz), v.w - __uint_as_float(bw));
        }
        #pragma unroll
        for (int p = 0; p < 4; p++) {
            const int kg = b_kg0 + p * 2;
            const float4 v = b_pre[p];
            uint32_t b0 = tf32_rna(v.x), b1 = tf32_rna(v.y),
                     b2 = tf32_rna(v.z), b3 = tf32_rna(v.w);
            const uint32_t o = tile_off(b_n, kg * 4);
            *(uint4*)(smem + SM_B_BIG + o) = make_uint4(b0, b1, b2, b3);
            *(float4*)(smem + SM_B_SMALL + o) = make_float4(
                v.x - __uint_as_float(b0), v.y - __uint_as_float(b1),
                v.z - __uint_as_float(b2), v.w - __uint_as_float(b3));
        }
        asm volatile("fence.proxy.async.shared::cta;" ::: "memory");
        __syncthreads();

        // 4) issue MMAs; commit
        if (wid == 0 && elect_one()) {
            const uint64_t ab = MAKE_DESC(sbase + SM_A_BIG);
            const uint64_t as = MAKE_DESC(sbase + SM_A_SMALL);
            const uint64_t bb = MAKE_DESC(sbase + SM_B_BIG);
            const uint64_t bs = MAKE_DESC(sbase + SM_B_SMALL);
            #pragma unroll
            for (int s = 0; s < K_CHUNK / 8; s++) {     // 4 k-steps of K=8
                const uint64_t off = (uint64_t)(s * 2); // 32B per step
                const uint32_t first = (kc == 0 && s == 0) ? 0u : 1u;
                mma_tf32_ss(tmem, ab + off, bb + off, TF32_IDESC, first);
                mma_tf32_ss(tmem, as + off, bb + off, TF32_IDESC, 1u);
                mma_tf32_ss(tmem, ab + off, bs + off, TF32_IDESC, 1u);
            }
            asm volatile(
                "tcgen05.commit.cta_group::1.mbarrier::arrive::one.shared::cluster.b64 [%0];"
                :: "r"(sbase + SM_MBAR) : "memory");
        }
    }

    // Final wait: 8th commit -> parity 1.
    mbar_wait(sbase + SM_MBAR, 1u);
    asm volatile("tcgen05.fence::after_thread_sync;" ::: "memory");

    // epilogue: 8 warps read D from TMEM, store to g_support
    {
        const int sub  = wid & 3;
        const int half = wid >> 2;
        uint32_t d[64];
        const uint32_t taddr = tmem + half * 64;
        asm volatile(
            "tcgen05.ld.sync.aligned.32x32b.x32.b32 "
            "{%0,%1,%2,%3,%4,%5,%6,%7,%8,%9,%10,%11,%12,%13,%14,%15,"
            "%16,%17,%18,%19,%20,%21,%22,%23,%24,%25,%26,%27,%28,%29,%30,%31}, [%32];"
            : "=r"(d[0]),"=r"(d[1]),"=r"(d[2]),"=r"(d[3]),"=r"(d[4]),"=r"(d[5]),"=r"(d[6]),"=r"(d[7]),
              "=r"(d[8]),"=r"(d[9]),"=r"(d[10]),"=r"(d[11]),"=r"(d[12]),"=r"(d[13]),"=r"(d[14]),"=r"(d[15]),
              "=r"(d[16]),"=r"(d[17]),"=r"(d[18]),"=r"(d[19]),"=r"(d[20]),"=r"(d[21]),"=r"(d[22]),"=r"(d[23]),
              "=r"(d[24]),"=r"(d[25]),"=r"(d[26]),"=r"(d[27]),"=r"(d[28]),"=r"(d[29]),"=r"(d[30]),"=r"(d[31])
            : "r"(taddr));
        asm volatile(
            "tcgen05.ld.sync.aligned.32x32b.x32.b32 "
            "{%0,%1,%2,%3,%4,%5,%6,%7,%8,%9,%10,%11,%12,%13,%14,%15,"
            "%16,%17,%18,%19,%20,%21,%22,%23,%24,%25,%26,%27,%28,%29,%30,%31}, [%32];"
            : "=r"(d[32]),"=r"(d[33]),"=r"(d[34]),"=r"(d[35]),"=r"(d[36]),"=r"(d[37]),"=r"(d[38]),"=r"(d[39]),
              "=r"(d[40]),"=r"(d[41]),"=r"(d[42]),"=r"(d[43]),"=r"(d[44]),"=r"(d[45]),"=r"(d[46]),"=r"(d[47]),
              "=r"(d[48]),"=r"(d[49]),"=r"(d[50]),"=r"(d[51]),"=r"(d[52]),"=r"(d[53]),"=r"(d[54]),"=r"(d[55]),
              "=r"(d[56]),"=r"(d[57]),"=r"(d[58]),"=r"(d[59]),"=r"(d[60]),"=r"(d[61]),"=r"(d[62]),"=r"(d[63])
            : "r"(taddr + 32));
        asm volatile("tcgen05.wait::ld.sync.aligned;" ::: "memory");

        const int gr = block_row + sub * 32 + lane;
        if (gr < N_NODES) {
            float* sp = g_support + (size_t)gr * OUT_F + half * 64;
            #pragma unroll
            for (int q = 0; q < 16; q++) {
                *(float4*)(sp + q * 4) = make_float4(
                    __uint_as_float(d[q * 4 + 0]), __uint_as_float(d[q * 4 + 1]),
                    __uint_as_float(d[q * 4 + 2]), __uint_as_float(d[q * 4 + 3]));
            }
        }
    }

    __syncthreads();
    if (tid == 0) {
        asm volatile("mbarrier.inval.shared.b64 [%0];" :: "r"(sbase + SM_MBAR) : "memory");
    }
    if (wid == 0) {
        asm volatile("tcgen05.dealloc.cta_group::1.sync.aligned.b32 %0, %1;"
                     :: "r"(tmem), "r"(128u));
    }

#else
    // ---------------- FFMA fallback (family compute_103 pass) ----------------
    const int BK = 16;
    float* As = (float*)smem;
    float* Bs = As + BK * 128;

    const int tx = tid & 15;
    const int ty = tid >> 4;
    const int a_row = tid >> 1;
    const int a_col = (tid & 1) * 8;
    const int b_row = tid >> 4;
    const int b_col = (tid & 15) * 8;

    float acc[8][8];
    #pragma unroll
    for (int i = 0; i < 8; i++)
        #pragma unroll
        for (int j = 0; j < 8; j++)
            acc[i][j] = 0.0f;

    const int g_arow = block_row + a_row;
    const bool a_valid = (g_arow < N_NODES);

    for (int kt = 0; kt < IN_F; kt += BK) {
        {
            float4 v0, v1;
            if (a_valid) {
                const float* xp = x + (size_t)g_arow * IN_F + kt + a_col;
                v0 = *(const float4*)(xp);
                v1 = *(const float4*)(xp + 4);
            } else {
                v0 = make_float4(0.f, 0.f, 0.f, 0.f);
                v1 = v0;
            }
            As[(a_col + 0) * 128 + a_row] = v0.x;
            As[(a_col + 1) * 128 + a_row] = v0.y;
            As[(a_col + 2) * 128 + a_row] = v0.z;
            As[(a_col + 3) * 128 + a_row] = v0.w;
            As[(a_col + 4) * 128 + a_row] = v1.x;
            As[(a_col + 5) * 128 + a_row] = v1.y;
            As[(a_col + 6) * 128 + a_row] = v1.z;
            As[(a_col + 7) * 128 + a_row] = v1.w;
        }
        {
            const float* wp = w + (size_t)(kt + b_row) * OUT_F + b_col;
            float4 v0 = *(const float4*)(wp);
            float4 v1 = *(const float4*)(wp + 4);
            *(float4*)(&Bs[b_row * 128 + b_col])     = v0;
            *(float4*)(&Bs[b_row * 128 + b_col + 4]) = v1;
        }
        __syncthreads();

        #pragma unroll
        for (int k = 0; k < BK; k++) {
            float a[8], b[8];
            float4 av0 = *(const float4*)(&As[k * 128 + ty * 8]);
            float4 av1 = *(const float4*)(&As[k * 128 + ty * 8 + 4]);
            float4 bv0 = *(const float4*)(&Bs[k * 128 + tx * 8]);
            float4 bv1 = *(const float4*)(&Bs[k * 128 + tx * 8 + 4]);
            a[0]=av0.x; a[1]=av0.y; a[2]=av0.z; a[3]=av0.w;
            a[4]=av1.x; a[5]=av1.y; a[6]=av1.z; a[7]=av1.w;
            b[0]=bv0.x; b[1]=bv0.y; b[2]=bv0.z; b[3]=bv0.w;
            b[4]=bv1.x; b[5]=bv1.y; b[6]=bv1.z; b[7]=bv1.w;
            #pragma unroll
            for (int i = 0; i < 8; i++)
                #pragma unroll
                for (int j = 0; j < 8; j++)
                    acc[i][j] = fmaf(a[i], b[j], acc[i][j]);
        }
        __syncthreads();
    }

    #pragma unroll
    for (int i = 0; i < 8; i++) {
        const int gr = block_row + ty * 8 + i;
        if (gr < N_NODES) {
            float* sp = g_support + (size_t)gr * OUT_F + tx * 8;
            *(float4*)(sp)     = make_float4(acc[i][0], acc[i][1], acc[i][2], acc[i][3]);
            *(float4*)(sp + 4) = make_float4(acc[i][4], acc[i][5], acc[i][6], acc[i][7]);
        }
    }
#endif
}

// ---------------------------------------------------------------------------
// CSR build
// ---------------------------------------------------------------------------
__global__ void gcn_zero_counts_kernel()
{
    int i = blockIdx.x * blockDim.x + threadIdx.x;
    if (i < N_NODES) g_counts[i] = 0;
}

__global__ void gcn_histogram_kernel(const int* __restrict__ edge_rows)
{
    int e = blockIdx.x * blockDim.x + threadIdx.x;
    if (e < N_EDGES) atomicAdd(&g_counts[edge_rows[e]], 1);
}

__global__ __launch_bounds__(1024) void gcn_scan_reduce_kernel()
{
    __shared__ int sdata[32];
    const int i = blockIdx.x * SCAN_CHUNK + threadIdx.x;
    int v = (i < N_NODES) ? g_counts[i] : 0;
    #pragma unroll
    for (int off = 16; off > 0; off >>= 1)
        v += __shfl_down_sync(0xffffffffu, v, off);
    if ((threadIdx.x & 31) == 0) sdata[threadIdx.x >> 5] = v;
    __syncthreads();
    if (threadIdx.x < 32) {
        int w = sdata[threadIdx.x];
        #pragma unroll
        for (int off = 16; off > 0; off >>= 1)
            w += __shfl_down_sync(0xffffffffu, w, off);
        if (threadIdx.x == 0) g_partials[blockIdx.x] = w;
    }
}

__global__ void gcn_scan_partials_kernel()
{
    __shared__ int s[64];
    int v = (threadIdx.x < NUM_CHUNKS) ? g_partials[threadIdx.x] : 0;
    s[threadIdx.x] = v;
    __syncthreads();
    #pragma unroll
    for (int off = 1; off < 64; off <<= 1) {
        int t = (threadIdx.x >= off) ? s[threadIdx.x - off] : 0;
        __syncthreads();
        s[threadIdx.x] += t;
        __syncthreads();
    }
    if (threadIdx.x < NUM_CHUNKS) g_chunk_base[threadIdx.x] = s[threadIdx.x] - v;
    if (threadIdx.x == 63) g_offsets[N_NODES] = s[63];
}

__global__ __launch_bounds__(1024) void gcn_scan_final_kernel()
{
    __shared__ int warp_sums[32];
    const int i = blockIdx.x * SCAN_CHUNK + threadIdx.x;
    const int lane = threadIdx.x & 31;
    const int warp = threadIdx.x >> 5;

    int v = (i < N_NODES) ? g_counts[i] : 0;
    int incl = v;
    #pragma unroll
    for (int off = 1; off < 32; off <<= 1) {
        int t = __shfl_up_sync(0xffffffffu, incl, off);
        if (lane >= off) incl += t;
    }
    if (lane == 31) warp_sums[warp] = incl;
    __syncthreads();
    if (warp == 0) {
        int w = warp_sums[lane];
        int wi = w;
        #pragma unroll
        for (int off = 1; off < 32; off <<= 1) {
            int t = __shfl_up_sync(0xffffffffu, wi, off);
            if (lane >= off) wi += t;
        }
        warp_sums[lane] = wi - w;
    }
    __syncthreads();

    if (i < N_NODES) {
        int o = g_chunk_base[blockIdx.x] + warp_sums[warp] + (incl - v);
        g_offsets[i] = o;
        g_cursor[i]  = o;
    }
}

__global__ void gcn_permute_kernel(const int*   __restrict__ edge_rows,
                                   const int*   __restrict__ edge_cols,
                                   const float* __restrict__ edge_vals)
{
    int e = blockIdx.x * blockDim.x + threadIdx.x;
    if (e < N_EDGES) {
        int r = edge_rows[e];
        int pos = atomicAdd(&g_cursor[r], 1);
        g_sorted[pos] = make_int2(edge_cols[e], __float_as_int(edge_vals[e]));
    }
}

// ---------------------------------------------------------------------------
// Aggregate: one warp per node, 4-way unrolled gathers. (L2-throughput floor.)
// ---------------------------------------------------------------------------
__global__ __launch_bounds__(256) void gcn_aggregate_kernel(
    float* __restrict__ out,
    const float* __restrict__ bias)
{
    const int warp_id = (blockIdx.x * blockDim.x + threadIdx.x) >> 5;
    const int lane    = threadIdx.x & 31;
    if (warp_id >= N_NODES) return;

    const int start = g_offsets[warp_id];
    const int end   = g_offsets[warp_id + 1];

    float4 acc = make_float4(0.f, 0.f, 0.f, 0.f);
    const float4* sup = (const float4*)g_support;

    for (int base = start; base < end; base += 32) {
        const int n = min(32, end - base);
        int2 ev = make_int2(0, 0);
        if (lane < n)
            ev = __ldg(&g_sorted[base + lane]);
        const int   c = ev.x;
        const float v = __int_as_float(ev.y);

        int j = 0;
        for (; j + 4 <= n; j += 4) {
            const int   c0 = __shfl_sync(0xffffffffu, c, j + 0);
            const int   c1 = __shfl_sync(0xffffffffu, c, j + 1);
            const int   c2 = __shfl_sync(0xffffffffu, c, j + 2);
            const int   c3 = __shfl_sync(0xffffffffu, c, j + 3);
            const float v0 = __shfl_sync(0xffffffffu, v, j + 0);
            const float v1 = __shfl_sync(0xffffffffu, v, j + 1);
            const float v2 = __shfl_sync(0xffffffffu, v, j + 2);
            const float v3 = __shfl_sync(0xffffffffu, v, j + 3);
            const float4 m0 = __ldg(sup + (size_t)c0 * 32 + lane);
            const float4 m1 = __ldg(sup + (size_t)c1 * 32 + lane);
            const float4 m2 = __ldg(sup + (size_t)c2 * 32 + lane);
            const float4 m3 = __ldg(sup + (size_t)c3 * 32 + lane);
            acc.x = fmaf(v0, m0.x, acc.x); acc.y = fmaf(v0, m0.y, acc.y);
            acc.z = fmaf(v0, m0.z, acc.z); acc.w = fmaf(v0, m0.w, acc.w);
            acc.x = fmaf(v1, m1.x, acc.x); acc.y = fmaf(v1, m1.y, acc.y);
            acc.z = fmaf(v1, m1.z, acc.z); acc.w = fmaf(v1, m1.w, acc.w);
            acc.x = fmaf(v2, m2.x, acc.x); acc.y = fmaf(v2, m2.y, acc.y);
            acc.z = fmaf(v2, m2.z, acc.z); acc.w = fmaf(v2, m2.w, acc.w);
            acc.x = fmaf(v3, m3.x, acc.x); acc.y = fmaf(v3, m3.y, acc.y);
            acc.z = fmaf(v3, m3.z, acc.z); acc.w = fmaf(v3, m3.w, acc.w);
        }
        for (; j < n; j++) {
            const int   cj = __shfl_sync(0xffffffffu, c, j);
            const float vj = __shfl_sync(0xffffffffu, v, j);
            const float4 m = __ldg(sup + (size_t)cj * 32 + lane);
            acc.x = fmaf(vj, m.x, acc.x);
            acc.y = fmaf(vj, m.y, acc.y);
            acc.z = fmaf(vj, m.z, acc.z);
            acc.w = fmaf(vj, m.w, acc.w);
        }
    }

    const float4 b = __ldg(((const float4*)bias) + lane);
    acc.x += b.x; acc.y += b.y; acc.z += b.z; acc.w += b.w;
    ((float4*)out)[(size_t)warp_id * 32 + lane] = acc;
}

// ---------------------------------------------------------------------------
// kernel_launch: GEMM on the main (capture) stream; CSR build forked onto a
// side stream via events; join before aggregate. Streams/events created once
// on the first (uncaptured correctness) call — no allocs, deterministic work.
// Inputs (metadata order): x, edge_rows, edge_cols, edge_vals, weight, bias
// ---------------------------------------------------------------------------
extern "C" void kernel_launch(void* const* d_in, const int* in_sizes, int n_in,
                              void* d_out, int out_size)
{
    const float* x         = (const float*)d_in[0];
    const int*   edge_rows = (const int*)  d_in[1];
    const int*   edge_cols = (const int*)  d_in[2];
    const float* edge_vals = (const float*)d_in[3];
    const float* weight    = (const float*)d_in[4];
    const float* bias      = (const float*)d_in[5];
    float*       out       = (float*)d_out;

    static cudaStream_t s_side = nullptr;
    static cudaEvent_t  ev_fork = nullptr;
    static cudaEvent_t  ev_join = nullptr;
    if (s_side == nullptr) {
        cudaStreamCreateWithFlags(&s_side, cudaStreamNonBlocking);
        cudaEventCreateWithFlags(&ev_fork, cudaEventDisableTiming);
        cudaEventCreateWithFlags(&ev_join, cudaEventDisableTiming);
        cudaFuncSetAttribute(gcn_gemm_tc_kernel,
                             cudaFuncAttributeMaxDynamicSharedMemorySize, SM_TOTAL);
    }

    // Fork: side stream branches off the capture stream's current front.
    cudaEventRecord(ev_fork, 0);
    cudaStreamWaitEvent(s_side, ev_fork, 0);

    // Branch A (main stream): GEMM  support = x @ W
    gcn_gemm_tc_kernel<<<(N_NODES + 127) / 128, 256, SM_TOTAL>>>(x, weight);

    // Branch B (side stream): CSR build
    gcn_zero_counts_kernel<<<(N_NODES + 255) / 256, 256, 0, s_side>>>();
    gcn_histogram_kernel<<<(N_EDGES + 255) / 256, 256, 0, s_side>>>(edge_rows);
    gcn_scan_reduce_kernel<<<NUM_CHUNKS, 1024, 0, s_side>>>();
    gcn_scan_partials_kernel<<<1, 64, 0, s_side>>>();
    gcn_scan_final_kernel<<<NUM_CHUNKS, 1024, 0, s_side>>>();
    gcn_permute_kernel<<<(N_EDGES + 255) / 256, 256, 0, s_side>>>(
        edge_rows, edge_cols, edge_vals);
    cudaEventRecord(ev_join, s_side);

    // Join: aggregate needs both branches.
    cudaStreamWaitEvent(0, ev_join, 0);
    {
        const int warps_per_block = 256 / 32;
        const int blocks = (N_NODES + warps_per_block - 1) / warps_per_block;
        gcn_aggregate_kernel<<<blocks, 256>>>(out, bias);
    }
}

// round 13
// speedup vs baseline: 2.4146x; 1.0924x over previous
#include <cuda_runtime.h>
#include <cstdint>

#define N_NODES 50000
#define N_EDGES 600000
#define IN_F    256
#define OUT_F   128

#define SCAN_CHUNK   1024
#define NUM_CHUNKS   ((N_NODES + SCAN_CHUNK - 1) / SCAN_CHUNK)   // 49

// Scratch (alloc-free rule: __device__ globals)
__device__ float g_support[(size_t)N_NODES * OUT_F];   // 25.6 MB
__device__ int   g_counts[N_NODES];
__device__ int   g_offsets[N_NODES + 1];
__device__ int   g_cursor[N_NODES];
__device__ int   g_partials[NUM_CHUNKS];
__device__ int   g_chunk_base[NUM_CHUNKS];
__device__ int2  g_sorted[N_EDGES];                    // {col, val_bits}

#if defined(__CUDA_ARCH__) && (__CUDA_ARCH__ == 1030) && \
    (defined(__CUDA_ARCH_FEAT_SM103_ALL) || defined(__CUDA_ARCH_SPECIFIC__))
#define GCN_HAS_TCGEN05 1
#else
#define GCN_HAS_TCGEN05 0
#endif

// ===========================================================================
// GEMM: support = x @ W, tcgen05 kind::tf32 SINGLE-PASS (no compensation).
// K_CHUNK=64 (4 chunks), 2 tiles x 32KB -> 65 KB -> 3 CTAs/SM single wave.
// rel_err budget: tf32 ~1-3e-4 << 1e-3 threshold. Revert to 3x if margin<3x.
// ===========================================================================

#define K_CHUNK     64
#define NUM_KCHUNK  (IN_F / K_CHUNK)       // 4
#define TILE_BYTES  (128 * K_CHUNK * 4)    // 32768

#define SM_TMEM_PTR 0
#define SM_MBAR     8
#define SM_A        1024
#define SM_B        (SM_A + TILE_BYTES)
#define SM_TOTAL    (SM_B + TILE_BYTES)    // 66560 (~65 KB)

#define TF32_IDESC  0x8200910u

#define DESC_BASE   0x4000404000010000ull
#define MAKE_DESC(a) (DESC_BASE | (uint64_t)(((a) >> 4) & 0x3FFF))

__device__ __forceinline__ uint32_t smem_u32(const void* p) {
    uint32_t a;
    asm("{ .reg .u64 t; cvta.to.shared.u64 t, %1; cvt.u32.u64 %0, t; }"
        : "=r"(a) : "l"(p));
    return a;
}

#if GCN_HAS_TCGEN05
__device__ __forceinline__ uint32_t tf32_rna(float a) {
    uint32_t r;
    asm("cvt.rna.tf32.f32 %0, %1;" : "=r"(r) : "f"(a));
    return r;
}

__device__ __forceinline__ uint32_t elect_one() {
    uint32_t p;
    asm volatile("{ .reg .pred p; elect.sync _|p, 0xFFFFFFFF; selp.b32 %0,1,0,p; }"
                 : "=r"(p));
    return p;
}

__device__ __forceinline__ void mma_tf32_ss(uint32_t d_tmem, uint64_t a_desc,
                                            uint64_t b_desc, uint32_t idesc,
                                            uint32_t enable_d) {
    asm volatile(
        "{\n\t.reg .pred p;\n\tsetp.ne.u32 p, %4, 0;\n\t"
        "tcgen05.mma.cta_group::1.kind::tf32 [%0], %1, %2, %3, {%5,%5,%5,%5}, p;\n\t}"
        :: "r"(d_tmem), "l"(a_desc), "l"(b_desc), "r"(idesc),
           "r"(enable_d), "r"(0u)
        : "memory");
}

__device__ __forceinline__ void mbar_wait(uint32_t addr, uint32_t parity) {
    uint32_t done;
    asm volatile(
        "{\n\t.reg .pred p;\n\t"
        "mbarrier.try_wait.parity.acquire.cta.shared::cta.b64 p, [%1], %2;\n\t"
        "selp.b32 %0, 1, 0, p;\n\t}"
        : "=r"(done) : "r"(addr), "r"(parity) : "memory");
    while (!done) {
        asm volatile(
            "{\n\t.reg .pred p;\n\t"
            "mbarrier.try_wait.parity.acquire.cta.shared::cta.b64 p, [%1], %2, 0x989680;\n\t"
            "selp.b32 %0, 1, 0, p;\n\t}"
            : "=r"(done) : "r"(addr), "r"(parity) : "memory");
    }
}

__device__ __forceinline__ uint32_t swz(uint32_t b) {
    return b ^ ((b >> 3) & 0x70);
}

// SW128 atom byte offset for (row, col) in a 128 x 64 f32 tile
// (two 32-float atom columns; 16 atom-rows of 1024B each). R6/R10-proven.
__device__ __forceinline__ uint32_t tile_off(int row, int col) {
    uint32_t byte = (uint32_t)(((row >> 3) + (col >> 5) * 16) * 1024
                               + (row & 7) * 128 + (col & 31) * 4);
    return swz(byte);
}
#endif  // GCN_HAS_TCGEN05

__global__ __launch_bounds__(256) void gcn_gemm_tc_kernel(
    const float* __restrict__ x,
    const float* __restrict__ w)
{
    extern __shared__ char smem[];
    const int tid  = threadIdx.x;
    const int block_row = blockIdx.x * 128;

#if GCN_HAS_TCGEN05
    const uint32_t sbase = smem_u32(smem);
    const int wid  = tid >> 5;
    const int lane = tid & 31;

    if (wid == 0) {
        asm volatile("tcgen05.alloc.cta_group::1.sync.aligned.shared::cta.b32 [%0], %1;"
                     :: "r"(sbase + SM_TMEM_PTR), "r"(128u) : "memory");
        asm volatile("tcgen05.relinquish_alloc_permit.cta_group::1.sync.aligned;");
    }
    if (tid == 0) {
        asm volatile("mbarrier.init.shared.b64 [%0], %1;"
                     :: "r"(sbase + SM_MBAR), "r"(1u) : "memory");
    }
    __syncthreads();

    uint32_t tmem;
    asm volatile("ld.shared.b32 %0, [%1];" : "=r"(tmem) : "r"(sbase + SM_TMEM_PTR));

    // A: 128 rows x 16 float4 = 2048 float4 per chunk; 8 per thread.
    //    p -> (row = (tid>>4) + p*16, c4 = (tid&15)*4)
    // B: 64 k x 128 n; thread owns n = tid&127; k-groups of 4:
    //    p -> kg = (tid>>7) + p*2 (0..15); loads W[kb+kg*4+q][n], q=0..3.
    const int a_row = tid >> 4;          // 0..15
    const int a_c4  = (tid & 15) * 4;    // 0..60
    const int b_n   = tid & 127;
    const int b_kg0 = tid >> 7;          // 0 or 1

    for (int kc = 0; kc < NUM_KCHUNK; kc++) {
        const int kb = kc * K_CHUNK;

        // 1) issue global loads into registers (overlaps the MMA wait below)
        float4 a_pre[8];
        float4 b_pre[8];
        #pragma unroll
        for (int p = 0; p < 8; p++) {
            const int row = a_row + p * 16;
            const int gr  = block_row + row;
            a_pre[p] = make_float4(0.f, 0.f, 0.f, 0.f);
            if (gr < N_NODES)
                a_pre[p] = *(const float4*)(x + (size_t)gr * IN_F + kb + a_c4);
        }
        #pragma unroll
        for (int p = 0; p < 8; p++) {
            const int kg = b_kg0 + p * 2;            // 0..15
            const float* wp = w + (size_t)(kb + kg * 4) * OUT_F + b_n;
            b_pre[p].x = __ldg(wp);
            b_pre[p].y = __ldg(wp + OUT_F);
            b_pre[p].z = __ldg(wp + 2 * OUT_F);
            b_pre[p].w = __ldg(wp + 3 * OUT_F);
        }

        // 2) wait for previous chunk's MMAs before overwriting SMEM
        if (kc >= 1)
            mbar_wait(sbase + SM_MBAR, (uint32_t)((kc - 1) & 1));

        // 3) convert to tf32 + store
        #pragma unroll
        for (int p = 0; p < 8; p++) {
            const int row = a_row + p * 16;
            const float4 v = a_pre[p];
            const uint32_t o = tile_off(row, a_c4);
            *(uint4*)(smem + SM_A + o) = make_uint4(
                tf32_rna(v.x), tf32_rna(v.y), tf32_rna(v.z), tf32_rna(v.w));
        }
        #pragma unroll
        for (int p = 0; p < 8; p++) {
            const int kg = b_kg0 + p * 2;
            const float4 v = b_pre[p];
            const uint32_t o = tile_off(b_n, kg * 4);
            *(uint4*)(smem + SM_B + o) = make_uint4(
                tf32_rna(v.x), tf32_rna(v.y), tf32_rna(v.z), tf32_rna(v.w));
        }
        asm volatile("fence.proxy.async.shared::cta;" ::: "memory");
        __syncthreads();

        // 4) issue MMAs (8 k-steps of K=8, single pass); commit
        if (wid == 0 && elect_one()) {
            const uint64_t ad = MAKE_DESC(sbase + SM_A);
            const uint64_t bd = MAKE_DESC(sbase + SM_B);
            #pragma unroll
            for (int s = 0; s < K_CHUNK / 8; s++) {
                const uint64_t off = (uint64_t)((s >> 2) * 1024 + (s & 3) * 2);
                const uint32_t first = (kc == 0 && s == 0) ? 0u : 1u;
                mma_tf32_ss(tmem, ad + off, bd + off, TF32_IDESC, first);
            }
            asm volatile(
                "tcgen05.commit.cta_group::1.mbarrier::arrive::one.shared::cluster.b64 [%0];"
                :: "r"(sbase + SM_MBAR) : "memory");
        }
    }

    // Final wait: 4th commit -> parity 1.
    mbar_wait(sbase + SM_MBAR, 1u);
    asm volatile("tcgen05.fence::after_thread_sync;" ::: "memory");

    // epilogue: 8 warps read D from TMEM, store to g_support
    {
        const int sub  = wid & 3;
        const int half = wid >> 2;
        uint32_t d[64];
        const uint32_t taddr = tmem + half * 64;
        asm volatile(
            "tcgen05.ld.sync.aligned.32x32b.x32.b32 "
            "{%0,%1,%2,%3,%4,%5,%6,%7,%8,%9,%10,%11,%12,%13,%14,%15,"
            "%16,%17,%18,%19,%20,%21,%22,%23,%24,%25,%26,%27,%28,%29,%30,%31}, [%32];"
            : "=r"(d[0]),"=r"(d[1]),"=r"(d[2]),"=r"(d[3]),"=r"(d[4]),"=r"(d[5]),"=r"(d[6]),"=r"(d[7]),
              "=r"(d[8]),"=r"(d[9]),"=r"(d[10]),"=r"(d[11]),"=r"(d[12]),"=r"(d[13]),"=r"(d[14]),"=r"(d[15]),
              "=r"(d[16]),"=r"(d[17]),"=r"(d[18]),"=r"(d[19]),"=r"(d[20]),"=r"(d[21]),"=r"(d[22]),"=r"(d[23]),
              "=r"(d[24]),"=r"(d[25]),"=r"(d[26]),"=r"(d[27]),"=r"(d[28]),"=r"(d[29]),"=r"(d[30]),"=r"(d[31])
            : "r"(taddr));
        asm volatile(
            "tcgen05.ld.sync.aligned.32x32b.x32.b32 "
            "{%0,%1,%2,%3,%4,%5,%6,%7,%8,%9,%10,%11,%12,%13,%14,%15,"
            "%16,%17,%18,%19,%20,%21,%22,%23,%24,%25,%26,%27,%28,%29,%30,%31}, [%32];"
            : "=r"(d[32]),"=r"(d[33]),"=r"(d[34]),"=r"(d[35]),"=r"(d[36]),"=r"(d[37]),"=r"(d[38]),"=r"(d[39]),
              "=r"(d[40]),"=r"(d[41]),"=r"(d[42]),"=r"(d[43]),"=r"(d[44]),"=r"(d[45]),"=r"(d[46]),"=r"(d[47]),
              "=r"(d[48]),"=r"(d[49]),"=r"(d[50]),"=r"(d[51]),"=r"(d[52]),"=r"(d[53]),"=r"(d[54]),"=r"(d[55]),
              "=r"(d[56]),"=r"(d[57]),"=r"(d[58]),"=r"(d[59]),"=r"(d[60]),"=r"(d[61]),"=r"(d[62]),"=r"(d[63])
            : "r"(taddr + 32));
        asm volatile("tcgen05.wait::ld.sync.aligned;" ::: "memory");

        const int gr = block_row + sub * 32 + lane;
        if (gr < N_NODES) {
            float* sp = g_support + (size_t)gr * OUT_F + half * 64;
            #pragma unroll
            for (int q = 0; q < 16; q++) {
                *(float4*)(sp + q * 4) = make_float4(
                    __uint_as_float(d[q * 4 + 0]), __uint_as_float(d[q * 4 + 1]),
                    __uint_as_float(d[q * 4 + 2]), __uint_as_float(d[q * 4 + 3]));
            }
        }
    }

    __syncthreads();
    if (tid == 0) {
        asm volatile("mbarrier.inval.shared.b64 [%0];" :: "r"(sbase + SM_MBAR) : "memory");
    }
    if (wid == 0) {
        asm volatile("tcgen05.dealloc.cta_group::1.sync.aligned.b32 %0, %1;"
                     :: "r"(tmem), "r"(128u));
    }

#else
    // ---------------- FFMA fallback (family compute_103 pass) ----------------
    const int BK = 16;
    float* As = (float*)smem;
    float* Bs = As + BK * 128;

    const int tx = tid & 15;
    const int ty = tid >> 4;
    const int a_row = tid >> 1;
    const int a_col = (tid & 1) * 8;
    const int b_row = tid >> 4;
    const int b_col = (tid & 15) * 8;

    float acc[8][8];
    #pragma unroll
    for (int i = 0; i < 8; i++)
        #pragma unroll
        for (int j = 0; j < 8; j++)
            acc[i][j] = 0.0f;

    const int g_arow = block_row + a_row;
    const bool a_valid = (g_arow < N_NODES);

    for (int kt = 0; kt < IN_F; kt += BK) {
        {
            float4 v0, v1;
            if (a_valid) {
                const float* xp = x + (size_t)g_arow * IN_F + kt + a_col;
                v0 = *(const float4*)(xp);
                v1 = *(const float4*)(xp + 4);
            } else {
                v0 = make_float4(0.f, 0.f, 0.f, 0.f);
                v1 = v0;
            }
            As[(a_col + 0) * 128 + a_row] = v0.x;
            As[(a_col + 1) * 128 + a_row] = v0.y;
            As[(a_col + 2) * 128 + a_row] = v0.z;
            As[(a_col + 3) * 128 + a_row] = v0.w;
            As[(a_col + 4) * 128 + a_row] = v1.x;
            As[(a_col + 5) * 128 + a_row] = v1.y;
            As[(a_col + 6) * 128 + a_row] = v1.z;
            As[(a_col + 7) * 128 + a_row] = v1.w;
        }
        {
            const float* wp = w + (size_t)(kt + b_row) * OUT_F + b_col;
            float4 v0 = *(const float4*)(wp);
            float4 v1 = *(const float4*)(wp + 4);
            *(float4*)(&Bs[b_row * 128 + b_col])     = v0;
            *(float4*)(&Bs[b_row * 128 + b_col + 4]) = v1;
        }
        __syncthreads();

        #pragma unroll
        for (int k = 0; k < BK; k++) {
            float a[8], b[8];
            float4 av0 = *(const float4*)(&As[k * 128 + ty * 8]);
            float4 av1 = *(const float4*)(&As[k * 128 + ty * 8 + 4]);
            float4 bv0 = *(const float4*)(&Bs[k * 128 + tx * 8]);
            float4 bv1 = *(const float4*)(&Bs[k * 128 + tx * 8 + 4]);
            a[0]=av0.x; a[1]=av0.y; a[2]=av0.z; a[3]=av0.w;
            a[4]=av1.x; a[5]=av1.y; a[6]=av1.z; a[7]=av1.w;
            b[0]=bv0.x; b[1]=bv0.y; b[2]=bv0.z; b[3]=bv0.w;
            b[4]=bv1.x; b[5]=bv1.y; b[6]=bv1.z; b[7]=bv1.w;
            #pragma unroll
            for (int i = 0; i < 8; i++)
                #pragma unroll
                for (int j = 0; j < 8; j++)
                    acc[i][j] = fmaf(a[i], b[j], acc[i][j]);
        }
        __syncthreads();
    }

    #pragma unroll
    for (int i = 0; i < 8; i++) {
        const int gr = block_row + ty * 8 + i;
        if (gr < N_NODES) {
            float* sp = g_support + (size_t)gr * OUT_F + tx * 8;
            *(float4*)(sp)     = make_float4(acc[i][0], acc[i][1], acc[i][2], acc[i][3]);
            *(float4*)(sp + 4) = make_float4(acc[i][4], acc[i][5], acc[i][6], acc[i][7]);
        }
    }
#endif
}

// ---------------------------------------------------------------------------
// CSR build
// ---------------------------------------------------------------------------
__global__ void gcn_zero_counts_kernel()
{
    int i = blockIdx.x * blockDim.x + threadIdx.x;
    if (i < N_NODES) g_counts[i] = 0;
}

__global__ void gcn_histogram_kernel(const int* __restrict__ edge_rows)
{
    int e = blockIdx.x * blockDim.x + threadIdx.x;
    if (e < N_EDGES) atomicAdd(&g_counts[edge_rows[e]], 1);
}

__global__ __launch_bounds__(1024) void gcn_scan_reduce_kernel()
{
    __shared__ int sdata[32];
    const int i = blockIdx.x * SCAN_CHUNK + threadIdx.x;
    int v = (i < N_NODES) ? g_counts[i] : 0;
    #pragma unroll
    for (int off = 16; off > 0; off >>= 1)
        v += __shfl_down_sync(0xffffffffu, v, off);
    if ((threadIdx.x & 31) == 0) sdata[threadIdx.x >> 5] = v;
    __syncthreads();
    if (threadIdx.x < 32) {
        int w = sdata[threadIdx.x];
        #pragma unroll
        for (int off = 16; off > 0; off >>= 1)
            w += __shfl_down_sync(0xffffffffu, w, off);
        if (threadIdx.x == 0) g_partials[blockIdx.x] = w;
    }
}

__global__ void gcn_scan_partials_kernel()
{
    __shared__ int s[64];
    int v = (threadIdx.x < NUM_CHUNKS) ? g_partials[threadIdx.x] : 0;
    s[threadIdx.x] = v;
    __syncthreads();
    #pragma unroll
    for (int off = 1; off < 64; off <<= 1) {
        int t = (threadIdx.x >= off) ? s[threadIdx.x - off] : 0;
        __syncthreads();
        s[threadIdx.x] += t;
        __syncthreads();
    }
    if (threadIdx.x < NUM_CHUNKS) g_chunk_base[threadIdx.x] = s[threadIdx.x] - v;
    if (threadIdx.x == 63) g_offsets[N_NODES] = s[63];
}

__global__ __launch_bounds__(1024) void gcn_scan_final_kernel()
{
    __shared__ int warp_sums[32];
    const int i = blockIdx.x * SCAN_CHUNK + threadIdx.x;
    const int lane = threadIdx.x & 31;
    const int warp = threadIdx.x >> 5;

    int v = (i < N_NODES) ? g_counts[i] : 0;
    int incl = v;
    #pragma unroll
    for (int off = 1; off < 32; off <<= 1) {
        int t = __shfl_up_sync(0xffffffffu, incl, off);
        if (lane >= off) incl += t;
    }
    if (lane == 31) warp_sums[warp] = incl;
    __syncthreads();
    if (warp == 0) {
        int w = warp_sums[lane];
        int wi = w;
        #pragma unroll
        for (int off = 1; off < 32; off <<= 1) {
            int t = __shfl_up_sync(0xffffffffu, wi, off);
            if (lane >= off) wi += t;
        }
        warp_sums[lane] = wi - w;
    }
    __syncthreads();

    if (i < N_NODES) {
        int o = g_chunk_base[blockIdx.x] + warp_sums[warp] + (incl - v);
        g_offsets[i] = o;
        g_cursor[i]  = o;
    }
}

__global__ void gcn_permute_kernel(const int*   __restrict__ edge_rows,
                                   const int*   __restrict__ edge_cols,
                                   const float* __restrict__ edge_vals)
{
    int e = blockIdx.x * blockDim.x + threadIdx.x;
    if (e < N_EDGES) {
        int r = edge_rows[e];
        int pos = atomicAdd(&g_cursor[r], 1);
        g_sorted[pos] = make_int2(edge_cols[e], __float_as_int(edge_vals[e]));
    }
}

// ---------------------------------------------------------------------------
// Aggregate: one warp per node, 4-way unrolled gathers. (L2-throughput floor.)
// ---------------------------------------------------------------------------
__global__ __launch_bounds__(256) void gcn_aggregate_kernel(
    float* __restrict__ out,
    const float* __restrict__ bias)
{
    const int warp_id = (blockIdx.x * blockDim.x + threadIdx.x) >> 5;
    const int lane    = threadIdx.x & 31;
    if (warp_id >= N_NODES) return;

    const int start = g_offsets[warp_id];
    const int end   = g_offsets[warp_id + 1];

    float4 acc = make_float4(0.f, 0.f, 0.f, 0.f);
    const float4* sup = (const float4*)g_support;

    for (int base = start; base < end; base += 32) {
        const int n = min(32, end - base);
        int2 ev = make_int2(0, 0);
        if (lane < n)
            ev = __ldg(&g_sorted[base + lane]);
        const int   c = ev.x;
        const float v = __int_as_float(ev.y);

        int j = 0;
        for (; j + 4 <= n; j += 4) {
            const int   c0 = __shfl_sync(0xffffffffu, c, j + 0);
            const int   c1 = __shfl_sync(0xffffffffu, c, j + 1);
            const int   c2 = __shfl_sync(0xffffffffu, c, j + 2);
            const int   c3 = __shfl_sync(0xffffffffu, c, j + 3);
            const float v0 = __shfl_sync(0xffffffffu, v, j + 0);
            const float v1 = __shfl_sync(0xffffffffu, v, j + 1);
            const float v2 = __shfl_sync(0xffffffffu, v, j + 2);
            const float v3 = __shfl_sync(0xffffffffu, v, j + 3);
            const float4 m0 = __ldg(sup + (size_t)c0 * 32 + lane);
            const float4 m1 = __ldg(sup + (size_t)c1 * 32 + lane);
            const float4 m2 = __ldg(sup + (size_t)c2 * 32 + lane);
            const float4 m3 = __ldg(sup + (size_t)c3 * 32 + lane);
            acc.x = fmaf(v0, m0.x, acc.x); acc.y = fmaf(v0, m0.y, acc.y);
            acc.z = fmaf(v0, m0.z, acc.z); acc.w = fmaf(v0, m0.w, acc.w);
            acc.x = fmaf(v1, m1.x, acc.x); acc.y = fmaf(v1, m1.y, acc.y);
            acc.z = fmaf(v1, m1.z, acc.z); acc.w = fmaf(v1, m1.w, acc.w);
            acc.x = fmaf(v2, m2.x, acc.x); acc.y = fmaf(v2, m2.y, acc.y);
            acc.z = fmaf(v2, m2.z, acc.z); acc.w = fmaf(v2, m2.w, acc.w);
            acc.x = fmaf(v3, m3.x, acc.x); acc.y = fmaf(v3, m3.y, acc.y);
            acc.z = fmaf(v3, m3.z, acc.z); acc.w = fmaf(v3, m3.w, acc.w);
        }
        for (; j < n; j++) {
            const int   cj = __shfl_sync(0xffffffffu, c, j);
            const float vj = __shfl_sync(0xffffffffu, v, j);
            const float4 m = __ldg(sup + (size_t)cj * 32 + lane);
            acc.x = fmaf(vj, m.x, acc.x);
            acc.y = fmaf(vj, m.y, acc.y);
            acc.z = fmaf(vj, m.z, acc.z);
            acc.w = fmaf(vj, m.w, acc.w);
        }
    }

    const float4 b = __ldg(((const float4*)bias) + lane);
    acc.x += b.x; acc.y += b.y; acc.z += b.z; acc.w += b.w;
    ((float4*)out)[(size_t)warp_id * 32 + lane] = acc;
}

// ---------------------------------------------------------------------------
// kernel_launch: GEMM on main stream; CSR build forked to side stream;
// join before aggregate. (R12 proven fork/join.)
// Inputs (metadata order): x, edge_rows, edge_cols, edge_vals, weight, bias
// ---------------------------------------------------------------------------
extern "C" void kernel_launch(void* const* d_in, const int* in_sizes, int n_in,
                              void* d_out, int out_size)
{
    const float* x         = (const float*)d_in[0];
    const int*   edge_rows = (const int*)  d_in[1];
    const int*   edge_cols = (const int*)  d_in[2];
    const float* edge_vals = (const float*)d_in[3];
    const float* weight    = (const float*)d_in[4];
    const float* bias      = (const float*)d_in[5];
    float*       out       = (float*)d_out;

    static cudaStream_t s_side = nullptr;
    static cudaEvent_t  ev_fork = nullptr;
    static cudaEvent_t  ev_join = nullptr;
    if (s_side == nullptr) {
        cudaStreamCreateWithFlags(&s_side, cudaStreamNonBlocking);
        cudaEventCreateWithFlags(&ev_fork, cudaEventDisableTiming);
        cudaEventCreateWithFlags(&ev_join, cudaEventDisableTiming);
        cudaFuncSetAttribute(gcn_gemm_tc_kernel,
                             cudaFuncAttributeMaxDynamicSharedMemorySize, SM_TOTAL);
    }

    // Fork
    cudaEventRecord(ev_fork, 0);
    cudaStreamWaitEvent(s_side, ev_fork, 0);

    // Branch A (main): GEMM
    gcn_gemm_tc_kernel<<<(N_NODES + 127) / 128, 256, SM_TOTAL>>>(x, weight);

    // Branch B (side): CSR build
    gcn_zero_counts_kernel<<<(N_NODES + 255) / 256, 256, 0, s_side>>>();
    gcn_histogram_kernel<<<(N_EDGES + 255) / 256, 256, 0, s_side>>>(edge_rows);
    gcn_scan_reduce_kernel<<<NUM_CHUNKS, 1024, 0, s_side>>>();
    gcn_scan_partials_kernel<<<1, 64, 0, s_side>>>();
    gcn_scan_final_kernel<<<NUM_CHUNKS, 1024, 0, s_side>>>();
    gcn_permute_kernel<<<(N_EDGES + 255) / 256, 256, 0, s_side>>>(
        edge_rows, edge_cols, edge_vals);
    cudaEventRecord(ev_join, s_side);

    // Join + aggregate
    cudaStreamWaitEvent(0, ev_join, 0);
    {
        const int warps_per_block = 256 / 32;
        const int blocks = (N_NODES + warps_per_block - 1) / warps_per_block;
        gcn_aggregate_kernel<<<blocks, 256>>>(out, bias);
    }
}

// round 14
// speedup vs baseline: 2.6447x; 1.0953x over previous
#include <cuda_runtime.h>
#include <cuda_fp16.h>
#include <cstdint>
#include <cstring>

#define N_NODES 50000
#define N_EDGES 600000
#define IN_F    256
#define OUT_F   128

#define SCAN_CHUNK   1024
#define NUM_CHUNKS   ((N_NODES + SCAN_CHUNK - 1) / SCAN_CHUNK)   // 49

// Scratch (alloc-free rule: __device__ globals)
__device__ __half g_support_h[(size_t)N_NODES * OUT_F];   // 12.8 MB fp16
__device__ int   g_counts[N_NODES];
__device__ int   g_offsets[N_NODES + 1];
__device__ int   g_cursor[N_NODES];
__device__ int   g_partials[NUM_CHUNKS];
__device__ int   g_chunk_base[NUM_CHUNKS];
__device__ int2  g_sorted[N_EDGES];                    // {col, val_bits}

#if defined(__CUDA_ARCH__) && (__CUDA_ARCH__ == 1030) && \
    (defined(__CUDA_ARCH_FEAT_SM103_ALL) || defined(__CUDA_ARCH_SPECIFIC__))
#define GCN_HAS_TCGEN05 1
#else
#define GCN_HAS_TCGEN05 0
#endif

// ===========================================================================
// GEMM: support = x @ W, tcgen05 kind::tf32 single-pass (R13 proven).
// K_CHUNK=64 (4 chunks), 65 KB SMEM -> 3 CTAs/SM single wave.
// Epilogue now stores support as fp16 (halves aggregate gather traffic).
// ===========================================================================

#define K_CHUNK     64
#define NUM_KCHUNK  (IN_F / K_CHUNK)       // 4
#define TILE_BYTES  (128 * K_CHUNK * 4)    // 32768

#define SM_TMEM_PTR 0
#define SM_MBAR     8
#define SM_A        1024
#define SM_B        (SM_A + TILE_BYTES)
#define SM_TOTAL    (SM_B + TILE_BYTES)    // 66560 (~65 KB)

#define TF32_IDESC  0x8200910u

#define DESC_BASE   0x4000404000010000ull
#define MAKE_DESC(a) (DESC_BASE | (uint64_t)(((a) >> 4) & 0x3FFF))

__device__ __forceinline__ uint32_t smem_u32(const void* p) {
    uint32_t a;
    asm("{ .reg .u64 t; cvta.to.shared.u64 t, %1; cvt.u32.u64 %0, t; }"
        : "=r"(a) : "l"(p));
    return a;
}

__device__ __forceinline__ uint32_t h2_bits(__half2 h) {
    uint32_t u;
    memcpy(&u, &h, 4);
    return u;
}

#if GCN_HAS_TCGEN05
__device__ __forceinline__ uint32_t tf32_rna(float a) {
    uint32_t r;
    asm("cvt.rna.tf32.f32 %0, %1;" : "=r"(r) : "f"(a));
    return r;
}

__device__ __forceinline__ uint32_t elect_one() {
    uint32_t p;
    asm volatile("{ .reg .pred p; elect.sync _|p, 0xFFFFFFFF; selp.b32 %0,1,0,p; }"
                 : "=r"(p));
    return p;
}

__device__ __forceinline__ void mma_tf32_ss(uint32_t d_tmem, uint64_t a_desc,
                                            uint64_t b_desc, uint32_t idesc,
                                            uint32_t enable_d) {
    asm volatile(
        "{\n\t.reg .pred p;\n\tsetp.ne.u32 p, %4, 0;\n\t"
        "tcgen05.mma.cta_group::1.kind::tf32 [%0], %1, %2, %3, {%5,%5,%5,%5}, p;\n\t}"
        :: "r"(d_tmem), "l"(a_desc), "l"(b_desc), "r"(idesc),
           "r"(enable_d), "r"(0u)
        : "memory");
}

__device__ __forceinline__ void mbar_wait(uint32_t addr, uint32_t parity) {
    uint32_t done;
    asm volatile(
        "{\n\t.reg .pred p;\n\t"
        "mbarrier.try_wait.parity.acquire.cta.shared::cta.b64 p, [%1], %2;\n\t"
        "selp.b32 %0, 1, 0, p;\n\t}"
        : "=r"(done) : "r"(addr), "r"(parity) : "memory");
    while (!done) {
        asm volatile(
            "{\n\t.reg .pred p;\n\t"
            "mbarrier.try_wait.parity.acquire.cta.shared::cta.b64 p, [%1], %2, 0x989680;\n\t"
            "selp.b32 %0, 1, 0, p;\n\t}"
            : "=r"(done) : "r"(addr), "r"(parity) : "memory");
    }
}

__device__ __forceinline__ uint32_t swz(uint32_t b) {
    return b ^ ((b >> 3) & 0x70);
}

// SW128 atom byte offset for (row, col) in a 128 x 64 f32 tile
__device__ __forceinline__ uint32_t tile_off(int row, int col) {
    uint32_t byte = (uint32_t)(((row >> 3) + (col >> 5) * 16) * 1024
                               + (row & 7) * 128 + (col & 31) * 4);
    return swz(byte);
}
#endif  // GCN_HAS_TCGEN05

__global__ __launch_bounds__(256) void gcn_gemm_tc_kernel(
    const float* __restrict__ x,
    const float* __restrict__ w)
{
    extern __shared__ char smem[];
    const int tid  = threadIdx.x;
    const int block_row = blockIdx.x * 128;

#if GCN_HAS_TCGEN05
    const uint32_t sbase = smem_u32(smem);
    const int wid  = tid >> 5;
    const int lane = tid & 31;

    if (wid == 0) {
        asm volatile("tcgen05.alloc.cta_group::1.sync.aligned.shared::cta.b32 [%0], %1;"
                     :: "r"(sbase + SM_TMEM_PTR), "r"(128u) : "memory");
        asm volatile("tcgen05.relinquish_alloc_permit.cta_group::1.sync.aligned;");
    }
    if (tid == 0) {
        asm volatile("mbarrier.init.shared.b64 [%0], %1;"
                     :: "r"(sbase + SM_MBAR), "r"(1u) : "memory");
    }
    __syncthreads();

    uint32_t tmem;
    asm volatile("ld.shared.b32 %0, [%1];" : "=r"(tmem) : "r"(sbase + SM_TMEM_PTR));

    const int a_row = tid >> 4;          // 0..15
    const int a_c4  = (tid & 15) * 4;    // 0..60
    const int b_n   = tid & 127;
    const int b_kg0 = tid >> 7;          // 0 or 1

    for (int kc = 0; kc < NUM_KCHUNK; kc++) {
        const int kb = kc * K_CHUNK;

        // 1) issue global loads into registers
        float4 a_pre[8];
        float4 b_pre[8];
        #pragma unroll
        for (int p = 0; p < 8; p++) {
            const int row = a_row + p * 16;
            const int gr  = block_row + row;
            a_pre[p] = make_float4(0.f, 0.f, 0.f, 0.f);
            if (gr < N_NODES)
                a_pre[p] = *(const float4*)(x + (size_t)gr * IN_F + kb + a_c4);
        }
        #pragma unroll
        for (int p = 0; p < 8; p++) {
            const int kg = b_kg0 + p * 2;            // 0..15
            const float* wp = w + (size_t)(kb + kg * 4) * OUT_F + b_n;
            b_pre[p].x = __ldg(wp);
            b_pre[p].y = __ldg(wp + OUT_F);
            b_pre[p].z = __ldg(wp + 2 * OUT_F);
            b_pre[p].w = __ldg(wp + 3 * OUT_F);
        }

        // 2) wait for previous chunk's MMAs before overwriting SMEM
        if (kc >= 1)
            mbar_wait(sbase + SM_MBAR, (uint32_t)((kc - 1) & 1));

        // 3) convert to tf32 + store
        #pragma unroll
        for (int p = 0; p < 8; p++) {
            const int row = a_row + p * 16;
            const float4 v = a_pre[p];
            const uint32_t o = tile_off(row, a_c4);
            *(uint4*)(smem + SM_A + o) = make_uint4(
                tf32_rna(v.x), tf32_rna(v.y), tf32_rna(v.z), tf32_rna(v.w));
        }
        #pragma unroll
        for (int p = 0; p < 8; p++) {
            const int kg = b_kg0 + p * 2;
            const float4 v = b_pre[p];
            const uint32_t o = tile_off(b_n, kg * 4);
            *(uint4*)(smem + SM_B + o) = make_uint4(
                tf32_rna(v.x), tf32_rna(v.y), tf32_rna(v.z), tf32_rna(v.w));
        }
        asm volatile("fence.proxy.async.shared::cta;" ::: "memory");
        __syncthreads();

        // 4) issue MMAs; commit
        if (wid == 0 && elect_one()) {
            const uint64_t ad = MAKE_DESC(sbase + SM_A);
            const uint64_t bd = MAKE_DESC(sbase + SM_B);
            #pragma unroll
            for (int s = 0; s < K_CHUNK / 8; s++) {
                const uint64_t off = (uint64_t)((s >> 2) * 1024 + (s & 3) * 2);
                const uint32_t first = (kc == 0 && s == 0) ? 0u : 1u;
                mma_tf32_ss(tmem, ad + off, bd + off, TF32_IDESC, first);
            }
            asm volatile(
                "tcgen05.commit.cta_group::1.mbarrier::arrive::one.shared::cluster.b64 [%0];"
                :: "r"(sbase + SM_MBAR) : "memory");
        }
    }

    // Final wait: 4th commit -> parity 1.
    mbar_wait(sbase + SM_MBAR, 1u);
    asm volatile("tcgen05.fence::after_thread_sync;" ::: "memory");

    // epilogue: 8 warps read D from TMEM, convert fp32 -> fp16, store
    {
        const int sub  = wid & 3;
        const int half = wid >> 2;
        uint32_t d[64];
        const uint32_t taddr = tmem + half * 64;
        asm volatile(
            "tcgen05.ld.sync.aligned.32x32b.x32.b32 "
            "{%0,%1,%2,%3,%4,%5,%6,%7,%8,%9,%10,%11,%12,%13,%14,%15,"
            "%16,%17,%18,%19,%20,%21,%22,%23,%24,%25,%26,%27,%28,%29,%30,%31}, [%32];"
            : "=r"(d[0]),"=r"(d[1]),"=r"(d[2]),"=r"(d[3]),"=r"(d[4]),"=r"(d[5]),"=r"(d[6]),"=r"(d[7]),
              "=r"(d[8]),"=r"(d[9]),"=r"(d[10]),"=r"(d[11]),"=r"(d[12]),"=r"(d[13]),"=r"(d[14]),"=r"(d[15]),
              "=r"(d[16]),"=r"(d[17]),"=r"(d[18]),"=r"(d[19]),"=r"(d[20]),"=r"(d[21]),"=r"(d[22]),"=r"(d[23]),
              "=r"(d[24]),"=r"(d[25]),"=r"(d[26]),"=r"(d[27]),"=r"(d[28]),"=r"(d[29]),"=r"(d[30]),"=r"(d[31])
            : "r"(taddr));
        asm volatile(
            "tcgen05.ld.sync.aligned.32x32b.x32.b32 "
            "{%0,%1,%2,%3,%4,%5,%6,%7,%8,%9,%10,%11,%12,%13,%14,%15,"
            "%16,%17,%18,%19,%20,%21,%22,%23,%24,%25,%26,%27,%28,%29,%30,%31}, [%32];"
            : "=r"(d[32]),"=r"(d[33]),"=r"(d[34]),"=r"(d[35]),"=r"(d[36]),"=r"(d[37]),"=r"(d[38]),"=r"(d[39]),
              "=r"(d[40]),"=r"(d[41]),"=r"(d[42]),"=r"(d[43]),"=r"(d[44]),"=r"(d[45]),"=r"(d[46]),"=r"(d[47]),
              "=r"(d[48]),"=r"(d[49]),"=r"(d[50]),"=r"(d[51]),"=r"(d[52]),"=r"(d[53]),"=r"(d[54]),"=r"(d[55]),
              "=r"(d[56]),"=r"(d[57]),"=r"(d[58]),"=r"(d[59]),"=r"(d[60]),"=r"(d[61]),"=r"(d[62]),"=r"(d[63])
            : "r"(taddr + 32));
        asm volatile("tcgen05.wait::ld.sync.aligned;" ::: "memory");

        const int gr = block_row + sub * 32 + lane;
        if (gr < N_NODES) {
            uint2* sp = (uint2*)(g_support_h + (size_t)gr * OUT_F + half * 64);
            #pragma unroll
            for (int q = 0; q < 16; q++) {
                __half2 h0 = __floats2half2_rn(__uint_as_float(d[q * 4 + 0]),
                                               __uint_as_float(d[q * 4 + 1]));
                __half2 h1 = __floats2half2_rn(__uint_as_float(d[q * 4 + 2]),
                                               __uint_as_float(d[q * 4 + 3]));
                sp[q] = make_uint2(h2_bits(h0), h2_bits(h1));
            }
        }
    }

    __syncthreads();
    if (tid == 0) {
        asm volatile("mbarrier.inval.shared.b64 [%0];" :: "r"(sbase + SM_MBAR) : "memory");
    }
    if (wid == 0) {
        asm volatile("tcgen05.dealloc.cta_group::1.sync.aligned.b32 %0, %1;"
                     :: "r"(tmem), "r"(128u));
    }

#else
    // ---------------- FFMA fallback (family compute_103 pass) ----------------
    const int BK = 16;
    float* As = (float*)smem;
    float* Bs = As + BK * 128;

    const int tx = tid & 15;
    const int ty = tid >> 4;
    const int a_row = tid >> 1;
    const int a_col = (tid & 1) * 8;
    const int b_row = tid >> 4;
    const int b_col = (tid & 15) * 8;

    float acc[8][8];
    #pragma unroll
    for (int i = 0; i < 8; i++)
        #pragma unroll
        for (int j = 0; j < 8; j++)
            acc[i][j] = 0.0f;

    const int g_arow = block_row + a_row;
    const bool a_valid = (g_arow < N_NODES);

    for (int kt = 0; kt < IN_F; kt += BK) {
        {
            float4 v0, v1;
            if (a_valid) {
                const float* xp = x + (size_t)g_arow * IN_F + kt + a_col;
                v0 = *(const float4*)(xp);
                v1 = *(const float4*)(xp + 4);
            } else {
                v0 = make_float4(0.f, 0.f, 0.f, 0.f);
                v1 = v0;
            }
            As[(a_col + 0) * 128 + a_row] = v0.x;
            As[(a_col + 1) * 128 + a_row] = v0.y;
            As[(a_col + 2) * 128 + a_row] = v0.z;
            As[(a_col + 3) * 128 + a_row] = v0.w;
            As[(a_col + 4) * 128 + a_row] = v1.x;
            As[(a_col + 5) * 128 + a_row] = v1.y;
            As[(a_col + 6) * 128 + a_row] = v1.z;
            As[(a_col + 7) * 128 + a_row] = v1.w;
        }
        {
            const float* wp = w + (size_t)(kt + b_row) * OUT_F + b_col;
            float4 v0 = *(const float4*)(wp);
            float4 v1 = *(const float4*)(wp + 4);
            *(float4*)(&Bs[b_row * 128 + b_col])     = v0;
            *(float4*)(&Bs[b_row * 128 + b_col + 4]) = v1;
        }
        __syncthreads();

        #pragma unroll
        for (int k = 0; k < BK; k++) {
            float a[8], b[8];
            float4 av0 = *(const float4*)(&As[k * 128 + ty * 8]);
            float4 av1 = *(const float4*)(&As[k * 128 + ty * 8 + 4]);
            float4 bv0 = *(const float4*)(&Bs[k * 128 + tx * 8]);
            float4 bv1 = *(const float4*)(&Bs[k * 128 + tx * 8 + 4]);
            a[0]=av0.x; a[1]=av0.y; a[2]=av0.z; a[3]=av0.w;
            a[4]=av1.x; a[5]=av1.y; a[6]=av1.z; a[7]=av1.w;
            b[0]=bv0.x; b[1]=bv0.y; b[2]=bv0.z; b[3]=bv0.w;
            b[4]=bv1.x; b[5]=bv1.y; b[6]=bv1.z; b[7]=bv1.w;
            #pragma unroll
            for (int i = 0; i < 8; i++)
                #pragma unroll
                for (int j = 0; j < 8; j++)
                    acc[i][j] = fmaf(a[i], b[j], acc[i][j]);
        }
        __syncthreads();
    }

    #pragma unroll
    for (int i = 0; i < 8; i++) {
        const int gr = block_row + ty * 8 + i;
        if (gr < N_NODES) {
            uint2* sp = (uint2*)(g_support_h + (size_t)gr * OUT_F + tx * 8);
            __half2 h0 = __floats2half2_rn(acc[i][0], acc[i][1]);
            __half2 h1 = __floats2half2_rn(acc[i][2], acc[i][3]);
            __half2 h2 = __floats2half2_rn(acc[i][4], acc[i][5]);
            __half2 h3 = __floats2half2_rn(acc[i][6], acc[i][7]);
            sp[0] = make_uint2(h2_bits(h0), h2_bits(h1));
            sp[1] = make_uint2(h2_bits(h2), h2_bits(h3));
        }
    }
#endif
}

// ---------------------------------------------------------------------------
// CSR build
// ---------------------------------------------------------------------------
__global__ void gcn_zero_counts_kernel()
{
    int i = blockIdx.x * blockDim.x + threadIdx.x;
    if (i < N_NODES) g_counts[i] = 0;
}

__global__ void gcn_histogram_kernel(const int* __restrict__ edge_rows)
{
    int e = blockIdx.x * blockDim.x + threadIdx.x;
    if (e < N_EDGES) atomicAdd(&g_counts[edge_rows[e]], 1);
}

__global__ __launch_bounds__(1024) void gcn_scan_reduce_kernel()
{
    __shared__ int sdata[32];
    const int i = blockIdx.x * SCAN_CHUNK + threadIdx.x;
    int v = (i < N_NODES) ? g_counts[i] : 0;
    #pragma unroll
    for (int off = 16; off > 0; off >>= 1)
        v += __shfl_down_sync(0xffffffffu, v, off);
    if ((threadIdx.x & 31) == 0) sdata[threadIdx.x >> 5] = v;
    __syncthreads();
    if (threadIdx.x < 32) {
        int w = sdata[threadIdx.x];
        #pragma unroll
        for (int off = 16; off > 0; off >>= 1)
            w += __shfl_down_sync(0xffffffffu, w, off);
        if (threadIdx.x == 0) g_partials[blockIdx.x] = w;
    }
}

__global__ void gcn_scan_partials_kernel()
{
    __shared__ int s[64];
    int v = (threadIdx.x < NUM_CHUNKS) ? g_partials[threadIdx.x] : 0;
    s[threadIdx.x] = v;
    __syncthreads();
    #pragma unroll
    for (int off = 1; off < 64; off <<= 1) {
        int t = (threadIdx.x >= off) ? s[threadIdx.x - off] : 0;
        __syncthreads();
        s[threadIdx.x] += t;
        __syncthreads();
    }
    if (threadIdx.x < NUM_CHUNKS) g_chunk_base[threadIdx.x] = s[threadIdx.x] - v;
    if (threadIdx.x == 63) g_offsets[N_NODES] = s[63];
}

__global__ __launch_bounds__(1024) void gcn_scan_final_kernel()
{
    __shared__ int warp_sums[32];
    const int i = blockIdx.x * SCAN_CHUNK + threadIdx.x;
    const int lane = threadIdx.x & 31;
    const int warp = threadIdx.x >> 5;

    int v = (i < N_NODES) ? g_counts[i] : 0;
    int incl = v;
    #pragma unroll
    for (int off = 1; off < 32; off <<= 1) {
        int t = __shfl_up_sync(0xffffffffu, incl, off);
        if (lane >= off) incl += t;
    }
    if (lane == 31) warp_sums[warp] = incl;
    __syncthreads();
    if (warp == 0) {
        int w = warp_sums[lane];
        int wi = w;
        #pragma unroll
        for (int off = 1; off < 32; off <<= 1) {
            int t = __shfl_up_sync(0xffffffffu, wi, off);
            if (lane >= off) wi += t;
        }
        warp_sums[lane] = wi - w;
    }
    __syncthreads();

    if (i < N_NODES) {
        int o = g_chunk_base[blockIdx.x] + warp_sums[warp] + (incl - v);
        g_offsets[i] = o;
        g_cursor[i]  = o;
    }
}

__global__ void gcn_permute_kernel(const int*   __restrict__ edge_rows,
                                   const int*   __restrict__ edge_cols,
                                   const float* __restrict__ edge_vals)
{
    int e = blockIdx.x * blockDim.x + threadIdx.x;
    if (e < N_EDGES) {
        int r = edge_rows[e];
        int pos = atomicAdd(&g_cursor[r], 1);
        g_sorted[pos] = make_int2(edge_cols[e], __float_as_int(edge_vals[e]));
    }
}

// ---------------------------------------------------------------------------
// Aggregate: one warp per node; fp16 gathers (uint2 = 4 halves per lane),
// fp32 accumulation. 4-way unrolled for MLP.
// ---------------------------------------------------------------------------
__device__ __forceinline__ void agg_fma(float4& acc, float v, uint2 m)
{
    __half2 ha, hb;
    memcpy(&ha, &m.x, 4);
    memcpy(&hb, &m.y, 4);
    const float2 fa = __half22float2(ha);
    const float2 fb = __half22float2(hb);
    acc.x = fmaf(v, fa.x, acc.x);
    acc.y = fmaf(v, fa.y, acc.y);
    acc.z = fmaf(v, fb.x, acc.z);
    acc.w = fmaf(v, fb.y, acc.w);
}

__global__ __launch_bounds__(256) void gcn_aggregate_kernel(
    float* __restrict__ out,
    const float* __restrict__ bias)
{
    const int warp_id = (blockIdx.x * blockDim.x + threadIdx.x) >> 5;
    const int lane    = threadIdx.x & 31;
    if (warp_id >= N_NODES) return;

    const int start = g_offsets[warp_id];
    const int end   = g_offsets[warp_id + 1];

    float4 acc = make_float4(0.f, 0.f, 0.f, 0.f);
    const uint2* sup = (const uint2*)g_support_h;   // 32 uint2 per node row

    for (int base = start; base < end; base += 32) {
        const int n = min(32, end - base);
        int2 ev = make_int2(0, 0);
        if (lane < n)
            ev = __ldg(&g_sorted[base + lane]);
        const int   c = ev.x;
        const float v = __int_as_float(ev.y);

        int j = 0;
        for (; j + 4 <= n; j += 4) {
            const int   c0 = __shfl_sync(0xffffffffu, c, j + 0);
            const int   c1 = __shfl_sync(0xffffffffu, c, j + 1);
            const int   c2 = __shfl_sync(0xffffffffu, c, j + 2);
            const int   c3 = __shfl_sync(0xffffffffu, c, j + 3);
            const float v0 = __shfl_sync(0xffffffffu, v, j + 0);
            const float v1 = __shfl_sync(0xffffffffu, v, j + 1);
            const float v2 = __shfl_sync(0xffffffffu, v, j + 2);
            const float v3 = __shfl_sync(0xffffffffu, v, j + 3);
            const uint2 m0 = __ldg(sup + (size_t)c0 * 32 + lane);
            const uint2 m1 = __ldg(sup + (size_t)c1 * 32 + lane);
            const uint2 m2 = __ldg(sup + (size_t)c2 * 32 + lane);
            const uint2 m3 = __ldg(sup + (size_t)c3 * 32 + lane);
            agg_fma(acc, v0, m0);
            agg_fma(acc, v1, m1);
            agg_fma(acc, v2, m2);
            agg_fma(acc, v3, m3);
        }
        for (; j < n; j++) {
            const int   cj = __shfl_sync(0xffffffffu, c, j);
            const float vj = __shfl_sync(0xffffffffu, v, j);
            const uint2 m = __ldg(sup + (size_t)cj * 32 + lane);
            agg_fma(acc, vj, m);
        }
    }

    const float4 b = __ldg(((const float4*)bias) + lane);
    acc.x += b.x; acc.y += b.y; acc.z += b.z; acc.w += b.w;
    ((float4*)out)[(size_t)warp_id * 32 + lane] = acc;
}

// ---------------------------------------------------------------------------
// kernel_launch: GEMM on main stream; CSR build forked to side stream;
// join before aggregate. (R12 proven fork/join.)
// Inputs (metadata order): x, edge_rows, edge_cols, edge_vals, weight, bias
// ---------------------------------------------------------------------------
extern "C" void kernel_launch(void* const* d_in, const int* in_sizes, int n_in,
                              void* d_out, int out_size)
{
    const float* x         = (const float*)d_in[0];
    const int*   edge_rows = (const int*)  d_in[1];
    const int*   edge_cols = (const int*)  d_in[2];
    const float* edge_vals = (const float*)d_in[3];
    const float* weight    = (const float*)d_in[4];
    const float* bias      = (const float*)d_in[5];
    float*       out       = (float*)d_out;

    static cudaStream_t s_side = nullptr;
    static cudaEvent_t  ev_fork = nullptr;
    static cudaEvent_t  ev_join = nullptr;
    if (s_side == nullptr) {
        cudaStreamCreateWithFlags(&s_side, cudaStreamNonBlocking);
        cudaEventCreateWithFlags(&ev_fork, cudaEventDisableTiming);
        cudaEventCreateWithFlags(&ev_join, cudaEventDisableTiming);
        cudaFuncSetAttribute(gcn_gemm_tc_kernel,
                             cudaFuncAttributeMaxDynamicSharedMemorySize, SM_TOTAL);
    }

    // Fork
    cudaEventRecord(ev_fork, 0);
    cudaStreamWaitEvent(s_side, ev_fork, 0);

    // Branch A (main): GEMM
    gcn_gemm_tc_kernel<<<(N_NODES + 127) / 128, 256, SM_TOTAL>>>(x, weight);

    // Branch B (side): CSR build
    gcn_zero_counts_kernel<<<(N_NODES + 255) / 256, 256, 0, s_side>>>();
    gcn_histogram_kernel<<<(N_EDGES + 255) / 256, 256, 0, s_side>>>(edge_rows);
    gcn_scan_reduce_kernel<<<NUM_CHUNKS, 1024, 0, s_side>>>();
    gcn_scan_partials_kernel<<<1, 64, 0, s_side>>>();
    gcn_scan_final_kernel<<<NUM_CHUNKS, 1024, 0, s_side>>>();
    gcn_permute_kernel<<<(N_EDGES + 255) / 256, 256, 0, s_side>>>(
        edge_rows, edge_cols, edge_vals);
    cudaEventRecord(ev_join, s_side);

    // Join + aggregate
    cudaStreamWaitEvent(0, ev_join, 0);
    {
        const int warps_per_block = 256 / 32;
        const int blocks = (N_NODES + warps_per_block - 1) / warps_per_block;
        gcn_aggregate_kernel<<<blocks, 256>>>(out, bias);
    }
}

// round 15
// speedup vs baseline: 2.7959x; 1.0572x over previous
#include <cuda_runtime.h>
#include <cuda_fp16.h>
#include <cstdint>
#include <cstring>

#define N_NODES 50000
#define N_EDGES 600000
#define IN_F    256
#define OUT_F   128

#define SCAN_CHUNK   1024
#define NUM_CHUNKS   ((N_NODES + SCAN_CHUNK - 1) / SCAN_CHUNK)   // 49

// Scratch (alloc-free rule: __device__ globals)
__device__ __half g_support_h[(size_t)N_NODES * OUT_F];   // 12.8 MB fp16
__device__ int   g_counts[N_NODES];
__device__ int   g_offsets[N_NODES + 1];
__device__ int   g_cursor[N_NODES];
__device__ volatile int g_scan_partial[NUM_CHUNKS];
__device__ int   g_scan_flag[NUM_CHUNKS];
__device__ int2  g_sorted[N_EDGES];                    // {col, val_bits}

#if defined(__CUDA_ARCH__) && (__CUDA_ARCH__ == 1030) && \
    (defined(__CUDA_ARCH_FEAT_SM103_ALL) || defined(__CUDA_ARCH_SPECIFIC__))
#define GCN_HAS_TCGEN05 1
#else
#define GCN_HAS_TCGEN05 0
#endif

// ===========================================================================
// GEMM: support = x @ W, tcgen05 kind::f16 (fp16 in, fp32 acc), single-pass.
// fp16 rn rounding (2^-11) == tf32 rounding -> same error as R13/R14 GEMM.
// K_CHUNK=64 (4 chunks), fp16 tiles 16 KB -> 33 KB SMEM, 3 CTAs/SM wave.
// ===========================================================================

#define K_CHUNK     64
#define NUM_KCHUNK  (IN_F / K_CHUNK)       // 4
#define TILE_BYTES  (128 * K_CHUNK * 2)    // 16384 (fp16 tile)

#define SM_TMEM_PTR 0
#define SM_MBAR     8
#define SM_A        1024
#define SM_B        (SM_A + TILE_BYTES)
#define SM_TOTAL    (SM_B + TILE_BYTES)    // 33792 (~33 KB)

// idesc kind::f16, FP16 inputs (atype=btype=0), F32 acc, M=128, N=128
#define F16_IDESC   0x8200010u

#define DESC_BASE   0x4000404000010000ull
#define MAKE_DESC(a) (DESC_BASE | (uint64_t)(((a) >> 4) & 0x3FFF))

__device__ __forceinline__ uint32_t smem_u32(const void* p) {
    uint32_t a;
    asm("{ .reg .u64 t; cvta.to.shared.u64 t, %1; cvt.u32.u64 %0, t; }"
        : "=r"(a) : "l"(p));
    return a;
}

__device__ __forceinline__ uint32_t h2_bits(__half2 h) {
    uint32_t u;
    memcpy(&u, &h, 4);
    return u;
}

#if GCN_HAS_TCGEN05
__device__ __forceinline__ uint32_t elect_one() {
    uint32_t p;
    asm volatile("{ .reg .pred p; elect.sync _|p, 0xFFFFFFFF; selp.b32 %0,1,0,p; }"
                 : "=r"(p));
    return p;
}

__device__ __forceinline__ void mma_f16_ss(uint32_t d_tmem, uint64_t a_desc,
                                           uint64_t b_desc, uint32_t idesc,
                                           uint32_t enable_d) {
    asm volatile(
        "{\n\t.reg .pred p;\n\tsetp.ne.u32 p, %4, 0;\n\t"
        "tcgen05.mma.cta_group::1.kind::f16 [%0], %1, %2, %3, {%5,%5,%5,%5}, p;\n\t}"
        :: "r"(d_tmem), "l"(a_desc), "l"(b_desc), "r"(idesc),
           "r"(enable_d), "r"(0u)
        : "memory");
}

__device__ __forceinline__ void mbar_wait(uint32_t addr, uint32_t parity) {
    uint32_t done;
    asm volatile(
        "{\n\t.reg .pred p;\n\t"
        "mbarrier.try_wait.parity.acquire.cta.shared::cta.b64 p, [%1], %2;\n\t"
        "selp.b32 %0, 1, 0, p;\n\t}"
        : "=r"(done) : "r"(addr), "r"(parity) : "memory");
    while (!done) {
        asm volatile(
            "{\n\t.reg .pred p;\n\t"
            "mbarrier.try_wait.parity.acquire.cta.shared::cta.b64 p, [%1], %2, 0x989680;\n\t"
            "selp.b32 %0, 1, 0, p;\n\t}"
            : "=r"(done) : "r"(addr), "r"(parity) : "memory");
    }
}

__device__ __forceinline__ uint32_t swz(uint32_t b) {
    return b ^ ((b >> 3) & 0x70);
}

// SW128 atom byte offset for fp16 element (row, col) in a 128 x 64 fp16 tile:
// row = 64 fp16 = 128 B = one SW128 atom row; 16 atom-rows. (R8-proven.)
__device__ __forceinline__ uint32_t tile_off_h(int row, int col) {
    uint32_t byte = (uint32_t)((row >> 3) * 1024 + (row & 7) * 128 + col * 2);
    return swz(byte);
}
#endif  // GCN_HAS_TCGEN05

__global__ __launch_bounds__(256) void gcn_gemm_tc_kernel(
    const float* __restrict__ x,
    const float* __restrict__ w)
{
    extern __shared__ char smem[];
    const int tid  = threadIdx.x;
    const int block_row = blockIdx.x * 128;

#if GCN_HAS_TCGEN05
    const uint32_t sbase = smem_u32(smem);
    const int wid  = tid >> 5;
    const int lane = tid & 31;

    if (wid == 0) {
        asm volatile("tcgen05.alloc.cta_group::1.sync.aligned.shared::cta.b32 [%0], %1;"
                     :: "r"(sbase + SM_TMEM_PTR), "r"(128u) : "memory");
        asm volatile("tcgen05.relinquish_alloc_permit.cta_group::1.sync.aligned;");
    }
    if (tid == 0) {
        asm volatile("mbarrier.init.shared.b64 [%0], %1;"
                     :: "r"(sbase + SM_MBAR), "r"(1u) : "memory");
    }
    __syncthreads();

    uint32_t tmem;
    asm volatile("ld.shared.b32 %0, [%1];" : "=r"(tmem) : "r"(sbase + SM_TMEM_PTR));

    const int a_row = tid >> 4;          // 0..15
    const int a_c4  = (tid & 15) * 4;    // 0..60
    const int b_n   = tid & 127;
    const int b_kg0 = tid >> 7;          // 0 or 1

    for (int kc = 0; kc < NUM_KCHUNK; kc++) {
        const int kb = kc * K_CHUNK;

        // 1) issue global loads into registers
        float4 a_pre[8];
        float4 b_pre[8];
        #pragma unroll
        for (int p = 0; p < 8; p++) {
            const int row = a_row + p * 16;
            const int gr  = block_row + row;
            a_pre[p] = make_float4(0.f, 0.f, 0.f, 0.f);
            if (gr < N_NODES)
                a_pre[p] = *(const float4*)(x + (size_t)gr * IN_F + kb + a_c4);
        }
        #pragma unroll
        for (int p = 0; p < 8; p++) {
            const int kg = b_kg0 + p * 2;            // 0..15
            const float* wp = w + (size_t)(kb + kg * 4) * OUT_F + b_n;
            b_pre[p].x = __ldg(wp);
            b_pre[p].y = __ldg(wp + OUT_F);
            b_pre[p].z = __ldg(wp + 2 * OUT_F);
            b_pre[p].w = __ldg(wp + 3 * OUT_F);
        }

        // 2) wait for previous chunk's MMAs before overwriting SMEM
        if (kc >= 1)
            mbar_wait(sbase + SM_MBAR, (uint32_t)((kc - 1) & 1));

        // 3) convert to fp16 + store (8B per tile store, conflict-free)
        #pragma unroll
        for (int p = 0; p < 8; p++) {
            const int row = a_row + p * 16;
            const float4 v = a_pre[p];
            const uint32_t o = tile_off_h(row, a_c4);
            *(uint2*)(smem + SM_A + o) = make_uint2(
                h2_bits(__floats2half2_rn(v.x, v.y)),
                h2_bits(__floats2half2_rn(v.z, v.w)));
        }
        #pragma unroll
        for (int p = 0; p < 8; p++) {
            const int kg = b_kg0 + p * 2;
            const float4 v = b_pre[p];
            const uint32_t o = tile_off_h(b_n, kg * 4);
            *(uint2*)(smem + SM_B + o) = make_uint2(
                h2_bits(__floats2half2_rn(v.x, v.y)),
                h2_bits(__floats2half2_rn(v.z, v.w)));
        }
        asm volatile("fence.proxy.async.shared::cta;" ::: "memory");
        __syncthreads();

        // 4) issue MMAs (4 k-steps of K=16); commit
        if (wid == 0 && elect_one()) {
            const uint64_t ad = MAKE_DESC(sbase + SM_A);
            const uint64_t bd = MAKE_DESC(sbase + SM_B);
            #pragma unroll
            for (int s = 0; s < K_CHUNK / 16; s++) {
                const uint64_t off = (uint64_t)(s * 2);   // 32B per step
                const uint32_t first = (kc == 0 && s == 0) ? 0u : 1u;
                mma_f16_ss(tmem, ad + off, bd + off, F16_IDESC, first);
            }
            asm volatile(
                "tcgen05.commit.cta_group::1.mbarrier::arrive::one.shared::cluster.b64 [%0];"
                :: "r"(sbase + SM_MBAR) : "memory");
        }
    }

    // Final wait: 4th commit -> parity 1.
    mbar_wait(sbase + SM_MBAR, 1u);
    asm volatile("tcgen05.fence::after_thread_sync;" ::: "memory");

    // epilogue: 8 warps read D from TMEM, convert fp32 -> fp16, store
    {
        const int sub  = wid & 3;
        const int half = wid >> 2;
        uint32_t d[64];
        const uint32_t taddr = tmem + half * 64;
        asm volatile(
            "tcgen05.ld.sync.aligned.32x32b.x32.b32 "
            "{%0,%1,%2,%3,%4,%5,%6,%7,%8,%9,%10,%11,%12,%13,%14,%15,"
            "%16,%17,%18,%19,%20,%21,%22,%23,%24,%25,%26,%27,%28,%29,%30,%31}, [%32];"
            : "=r"(d[0]),"=r"(d[1]),"=r"(d[2]),"=r"(d[3]),"=r"(d[4]),"=r"(d[5]),"=r"(d[6]),"=r"(d[7]),
              "=r"(d[8]),"=r"(d[9]),"=r"(d[10]),"=r"(d[11]),"=r"(d[12]),"=r"(d[13]),"=r"(d[14]),"=r"(d[15]),
              "=r"(d[16]),"=r"(d[17]),"=r"(d[18]),"=r"(d[19]),"=r"(d[20]),"=r"(d[21]),"=r"(d[22]),"=r"(d[23]),
              "=r"(d[24]),"=r"(d[25]),"=r"(d[26]),"=r"(d[27]),"=r"(d[28]),"=r"(d[29]),"=r"(d[30]),"=r"(d[31])
            : "r"(taddr));
        asm volatile(
            "tcgen05.ld.sync.aligned.32x32b.x32.b32 "
            "{%0,%1,%2,%3,%4,%5,%6,%7,%8,%9,%10,%11,%12,%13,%14,%15,"
            "%16,%17,%18,%19,%20,%21,%22,%23,%24,%25,%26,%27,%28,%29,%30,%31}, [%32];"
            : "=r"(d[32]),"=r"(d[33]),"=r"(d[34]),"=r"(d[35]),"=r"(d[36]),"=r"(d[37]),"=r"(d[38]),"=r"(d[39]),
              "=r"(d[40]),"=r"(d[41]),"=r"(d[42]),"=r"(d[43]),"=r"(d[44]),"=r"(d[45]),"=r"(d[46]),"=r"(d[47]),
              "=r"(d[48]),"=r"(d[49]),"=r"(d[50]),"=r"(d[51]),"=r"(d[52]),"=r"(d[53]),"=r"(d[54]),"=r"(d[55]),
              "=r"(d[56]),"=r"(d[57]),"=r"(d[58]),"=r"(d[59]),"=r"(d[60]),"=r"(d[61]),"=r"(d[62]),"=r"(d[63])
            : "r"(taddr + 32));
        asm volatile("tcgen05.wait::ld.sync.aligned;" ::: "memory");

        const int gr = block_row + sub * 32 + lane;
        if (gr < N_NODES) {
            uint2* sp = (uint2*)(g_support_h + (size_t)gr * OUT_F + half * 64);
            #pragma unroll
            for (int q = 0; q < 16; q++) {
                __half2 h0 = __floats2half2_rn(__uint_as_float(d[q * 4 + 0]),
                                               __uint_as_float(d[q * 4 + 1]));
                __half2 h1 = __floats2half2_rn(__uint_as_float(d[q * 4 + 2]),
                                               __uint_as_float(d[q * 4 + 3]));
                sp[q] = make_uint2(h2_bits(h0), h2_bits(h1));
            }
        }
    }

    __syncthreads();
    if (tid == 0) {
        asm volatile("mbarrier.inval.shared.b64 [%0];" :: "r"(sbase + SM_MBAR) : "memory");
    }
    if (wid == 0) {
        asm volatile("tcgen05.dealloc.cta_group::1.sync.aligned.b32 %0, %1;"
                     :: "r"(tmem), "r"(128u));
    }

#else
    // ---------------- FFMA fallback (family compute_103 pass) ----------------
    const int BK = 16;
    float* As = (float*)smem;
    float* Bs = As + BK * 128;

    const int tx = tid & 15;
    const int ty = tid >> 4;
    const int a_row = tid >> 1;
    const int a_col = (tid & 1) * 8;
    const int b_row = tid >> 4;
    const int b_col = (tid & 15) * 8;

    float acc[8][8];
    #pragma unroll
    for (int i = 0; i < 8; i++)
        #pragma unroll
        for (int j = 0; j < 8; j++)
            acc[i][j] = 0.0f;

    const int g_arow = block_row + a_row;
    const bool a_valid = (g_arow < N_NODES);

    for (int kt = 0; kt < IN_F; kt += BK) {
        {
            float4 v0, v1;
            if (a_valid) {
                const float* xp = x + (size_t)g_arow * IN_F + kt + a_col;
                v0 = *(const float4*)(xp);
                v1 = *(const float4*)(xp + 4);
            } else {
                v0 = make_float4(0.f, 0.f, 0.f, 0.f);
                v1 = v0;
            }
            As[(a_col + 0) * 128 + a_row] = v0.x;
            As[(a_col + 1) * 128 + a_row] = v0.y;
            As[(a_col + 2) * 128 + a_row] = v0.z;
            As[(a_col + 3) * 128 + a_row] = v0.w;
            As[(a_col + 4) * 128 + a_row] = v1.x;
            As[(a_col + 5) * 128 + a_row] = v1.y;
            As[(a_col + 6) * 128 + a_row] = v1.z;
            As[(a_col + 7) * 128 + a_row] = v1.w;
        }
        {
            const float* wp = w + (size_t)(kt + b_row) * OUT_F + b_col;
            float4 v0 = *(const float4*)(wp);
            float4 v1 = *(const float4*)(wp + 4);
            *(float4*)(&Bs[b_row * 128 + b_col])     = v0;
            *(float4*)(&Bs[b_row * 128 + b_col + 4]) = v1;
        }
        __syncthreads();

        #pragma unroll
        for (int k = 0; k < BK; k++) {
            float a[8], b[8];
            float4 av0 = *(const float4*)(&As[k * 128 + ty * 8]);
            float4 av1 = *(const float4*)(&As[k * 128 + ty * 8 + 4]);
            float4 bv0 = *(const float4*)(&Bs[k * 128 + tx * 8]);
            float4 bv1 = *(const float4*)(&Bs[k * 128 + tx * 8 + 4]);
            a[0]=av0.x; a[1]=av0.y; a[2]=av0.z; a[3]=av0.w;
            a[4]=av1.x; a[5]=av1.y; a[6]=av1.z; a[7]=av1.w;
            b[0]=bv0.x; b[1]=bv0.y; b[2]=bv0.z; b[3]=bv0.w;
            b[4]=bv1.x; b[5]=bv1.y; b[6]=bv1.z; b[7]=bv1.w;
            #pragma unroll
            for (int i = 0; i < 8; i++)
                #pragma unroll
                for (int j = 0; j < 8; j++)
                    acc[i][j] = fmaf(a[i], b[j], acc[i][j]);
        }
        __syncthreads();
    }

    #pragma unroll
    for (int i = 0; i < 8; i++) {
        const int gr = block_row + ty * 8 + i;
        if (gr < N_NODES) {
            uint2* sp = (uint2*)(g_support_h + (size_t)gr * OUT_F + tx * 8);
            __half2 h0 = __floats2half2_rn(acc[i][0], acc[i][1]);
            __half2 h1 = __floats2half2_rn(acc[i][2], acc[i][3]);
            __half2 h2 = __floats2half2_rn(acc[i][4], acc[i][5]);
            __half2 h3 = __floats2half2_rn(acc[i][6], acc[i][7]);
            sp[0] = make_uint2(h2_bits(h0), h2_bits(h1));
            sp[1] = make_uint2(h2_bits(h2), h2_bits(h3));
        }
    }
#endif
}

// ---------------------------------------------------------------------------
// CSR build
// ---------------------------------------------------------------------------
__global__ void gcn_zero_counts_kernel()
{
    int i = blockIdx.x * blockDim.x + threadIdx.x;
    if (i < N_NODES) g_counts[i] = 0;
    if (i < NUM_CHUNKS) g_scan_flag[i] = 0;
}

__global__ void gcn_histogram_kernel(const int* __restrict__ edge_rows)
{
    int e = blockIdx.x * blockDim.x + threadIdx.x;
    if (e < N_EDGES) atomicAdd(&g_counts[edge_rows[e]], 1);
}

// Single-pass decoupled-lookback exclusive scan. grid = NUM_CHUNKS (49),
// all blocks co-resident (49 << 148 SMs) so spinning cannot deadlock.
__global__ __launch_bounds__(1024) void gcn_scan_kernel()
{
    __shared__ int warp_sums[32];
    __shared__ int s_total;
    __shared__ int s_base;

    const int bid  = blockIdx.x;
    const int i    = bid * SCAN_CHUNK + threadIdx.x;
    const int lane = threadIdx.x & 31;
    const int warp = threadIdx.x >> 5;

    int v = (i < N_NODES) ? g_counts[i] : 0;

    // warp inclusive scan
    int incl = v;
    #pragma unroll
    for (int off = 1; off < 32; off <<= 1) {
        int t = __shfl_up_sync(0xffffffffu, incl, off);
        if (lane >= off) incl += t;
    }
    if (lane == 31) warp_sums[warp] = incl;
    __syncthreads();
    if (warp == 0) {
        int w = warp_sums[lane];
        int wi = w;
        #pragma unroll
        for (int off = 1; off < 32; off <<= 1) {
            int t = __shfl_up_sync(0xffffffffu, wi, off);
            if (lane >= off) wi += t;
        }
        if (lane == 31) s_total = wi;      // block total
        warp_sums[lane] = wi - w;          // exclusive warp bases
    }
    __syncthreads();

    // publish this block's total (release: fence then atomic flag)
    if (threadIdx.x == 0) {
        g_scan_partial[bid] = s_total;
        __threadfence();
        atomicExch(&g_scan_flag[bid], 1);
    }

    // lookback: sum all predecessors' totals
    if (warp == 0) {
        int base = 0;
        for (int b = lane; b < bid; b += 32) {
            while (atomicAdd(&g_scan_flag[b], 0) == 0) {}
            base += g_scan_partial[b];
        }
        #pragma unroll
        for (int off = 16; off > 0; off >>= 1)
            base += __shfl_down_sync(0xffffffffu, base, off);
        if (lane == 0) s_base = base;
    }
    __syncthreads();

    if (i < N_NODES) {
        int o = s_base + warp_sums[warp] + (incl - v);
        g_offsets[i] = o;
        g_cursor[i]  = o;
    }
    if (bid == NUM_CHUNKS - 1 && threadIdx.x == 0)
        g_offsets[N_NODES] = s_base + s_total;
}

__global__ void gcn_permute_kernel(const int*   __restrict__ edge_rows,
                                   const int*   __restrict__ edge_cols,
                                   const float* __restrict__ edge_vals)
{
    int e = blockIdx.x * blockDim.x + threadIdx.x;
    if (e < N_EDGES) {
        int r = edge_rows[e];
        int pos = atomicAdd(&g_cursor[r], 1);
        g_sorted[pos] = make_int2(edge_cols[e], __float_as_int(edge_vals[e]));
    }
}

// ---------------------------------------------------------------------------
// Aggregate: one warp per node; fp16 gathers (uint2 = 4 halves per lane),
// fp32 accumulation. 4-way unrolled for MLP.
// ---------------------------------------------------------------------------
__device__ __forceinline__ void agg_fma(float4& acc, float v, uint2 m)
{
    __half2 ha, hb;
    memcpy(&ha, &m.x, 4);
    memcpy(&hb, &m.y, 4);
    const float2 fa = __half22float2(ha);
    const float2 fb = __half22float2(hb);
    acc.x = fmaf(v, fa.x, acc.x);
    acc.y = fmaf(v, fa.y, acc.y);
    acc.z = fmaf(v, fb.x, acc.z);
    acc.w = fmaf(v, fb.y, acc.w);
}

__global__ __launch_bounds__(256) void gcn_aggregate_kernel(
    float* __restrict__ out,
    const float* __restrict__ bias)
{
    const int warp_id = (blockIdx.x * blockDim.x + threadIdx.x) >> 5;
    const int lane    = threadIdx.x & 31;
    if (warp_id >= N_NODES) return;

    const int start = g_offsets[warp_id];
    const int end   = g_offsets[warp_id + 1];

    float4 acc = make_float4(0.f, 0.f, 0.f, 0.f);
    const uint2* sup = (const uint2*)g_support_h;   // 32 uint2 per node row

    for (int base = start; base < end; base += 32) {
        const int n = min(32, end - base);
        int2 ev = make_int2(0, 0);
        if (lane < n)
            ev = __ldg(&g_sorted[base + lane]);
        const int   c = ev.x;
        const float v = __int_as_float(ev.y);

        int j = 0;
        for (; j + 4 <= n; j += 4) {
            const int   c0 = __shfl_sync(0xffffffffu, c, j + 0);
            const int   c1 = __shfl_sync(0xffffffffu, c, j + 1);
            const int   c2 = __shfl_sync(0xffffffffu, c, j + 2);
            const int   c3 = __shfl_sync(0xffffffffu, c, j + 3);
            const float v0 = __shfl_sync(0xffffffffu, v, j + 0);
            const float v1 = __shfl_sync(0xffffffffu, v, j + 1);
            const float v2 = __shfl_sync(0xffffffffu, v, j + 2);
            const float v3 = __shfl_sync(0xffffffffu, v, j + 3);
            const uint2 m0 = __ldg(sup + (size_t)c0 * 32 + lane);
            const uint2 m1 = __ldg(sup + (size_t)c1 * 32 + lane);
            const uint2 m2 = __ldg(sup + (size_t)c2 * 32 + lane);
            const uint2 m3 = __ldg(sup + (size_t)c3 * 32 + lane);
            agg_fma(acc, v0, m0);
            agg_fma(acc, v1, m1);
            agg_fma(acc, v2, m2);
            agg_fma(acc, v3, m3);
        }
        for (; j < n; j++) {
            const int   cj = __shfl_sync(0xffffffffu, c, j);
            const float vj = __shfl_sync(0xffffffffu, v, j);
            const uint2 m = __ldg(sup + (size_t)cj * 32 + lane);
            agg_fma(acc, vj, m);
        }
    }

    const float4 b = __ldg(((const float4*)bias) + lane);
    acc.x += b.x; acc.y += b.y; acc.z += b.z; acc.w += b.w;
    ((float4*)out)[(size_t)warp_id * 32 + lane] = acc;
}

// ---------------------------------------------------------------------------
// kernel_launch: GEMM on main stream; CSR build forked to side stream;
// join before aggregate. (R12 proven fork/join.)
// Inputs (metadata order): x, edge_rows, edge_cols, edge_vals, weight, bias
// ---------------------------------------------------------------------------
extern "C" void kernel_launch(void* const* d_in, const int* in_sizes, int n_in,
                              void* d_out, int out_size)
{
    const float* x         = (const float*)d_in[0];
    const int*   edge_rows = (const int*)  d_in[1];
    const int*   edge_cols = (const int*)  d_in[2];
    const float* edge_vals = (const float*)d_in[3];
    const float* weight    = (const float*)d_in[4];
    const float* bias      = (const float*)d_in[5];
    float*       out       = (float*)d_out;

    static cudaStream_t s_side = nullptr;
    static cudaEvent_t  ev_fork = nullptr;
    static cudaEvent_t  ev_join = nullptr;
    if (s_side == nullptr) {
        cudaStreamCreateWithFlags(&s_side, cudaStreamNonBlocking);
        cudaEventCreateWithFlags(&ev_fork, cudaEventDisableTiming);
        cudaEventCreateWithFlags(&ev_join, cudaEventDisableTiming);
        cudaFuncSetAttribute(gcn_gemm_tc_kernel,
                             cudaFuncAttributeMaxDynamicSharedMemorySize, SM_TOTAL);
    }

    // Fork
    cudaEventRecord(ev_fork, 0);
    cudaStreamWaitEvent(s_side, ev_fork, 0);

    // Branch A (main): GEMM
    gcn_gemm_tc_kernel<<<(N_NODES + 127) / 128, 256, SM_TOTAL>>>(x, weight);

    // Branch B (side): CSR build (4 launches: zero, histogram, scan, permute)
    gcn_zero_counts_kernel<<<(N_NODES + 255) / 256, 256, 0, s_side>>>();
    gcn_histogram_kernel<<<(N_EDGES + 255) / 256, 256, 0, s_side>>>(edge_rows);
    gcn_scan_kernel<<<NUM_CHUNKS, 1024, 0, s_side>>>();
    gcn_permute_kernel<<<(N_EDGES + 255) / 256, 256, 0, s_side>>>(
        edge_rows, edge_cols, edge_vals);
    cudaEventRecord(ev_join, s_side);

    // Join + aggregate
    cudaStreamWaitEvent(0, ev_join, 0);
    {
        const int warps_per_block = 256 / 32;
        const int blocks = (N_NODES + warps_per_block - 1) / warps_per_block;
        gcn_aggregate_kernel<<<blocks, 256>>>(out, bias);
    }
}